// round 7
// baseline (speedup 1.0000x reference)
#include <cuda_runtime.h>
#include <cuda_bf16.h>
#include <math.h>

#define Bc 4
#define Tc 1024
#define Mc 256
#define Cc 512
#define Hc 8
#define HDc 64
#define C3c 1536
#define BHc 32

// ---------------- scratch ----------------
__device__ float g_qkv_x[Bc * Tc * C3c];
__device__ float g_qkv_y[Bc * Mc * C3c];
__device__ float g_catt1[BHc * Tc];
__device__ float g_catt2[BHc * Mc];
__device__ float g_catt[(long)BHc * Tc * Mc];
__device__ float g_x2y[(long)BHc * Tc * Mc];
__device__ float g_y2x[(long)BHc * Tc * Mc];
__device__ float g_big[(long)BHc * Tc * Tc];    // chain scores
__device__ float g_big2[(long)BHc * Tc * Tc];   // satt scores
__device__ float g_cval[Bc * Tc * Cc];
__device__ float g_sval[Bc * Tc * Cc];
__device__ float g_gs[Bc * Tc * Cc];
__device__ float g_z[Bc * Tc * Cc];

// ---------------- helpers ----------------
__device__ __forceinline__ unsigned f2tf(float f) {
    unsigned u;
    asm("cvt.rna.tf32.f32 %0, %1;" : "=r"(u) : "f"(f));
    return u;
}
__device__ __forceinline__ void mma8(float* d, const unsigned* a, const unsigned* b) {
    asm volatile(
        "mma.sync.aligned.m16n8k8.row.col.f32.tf32.tf32.f32 "
        "{%0,%1,%2,%3},{%4,%5,%6,%7},{%8,%9},{%0,%1,%2,%3};"
        : "+f"(d[0]), "+f"(d[1]), "+f"(d[2]), "+f"(d[3])
        : "r"(a[0]), "r"(a[1]), "r"(a[2]), "r"(a[3]), "r"(b[0]), "r"(b[1]));
}
__device__ __forceinline__ void cpa16(unsigned dst, const void* src) {
    asm volatile("cp.async.cg.shared.global [%0], [%1], 16;" :: "r"(dst), "l"(src));
}
__device__ __forceinline__ void cpcommit() { asm volatile("cp.async.commit_group;"); }
__device__ __forceinline__ void ldsm4(unsigned& r0, unsigned& r1, unsigned& r2, unsigned& r3,
                                      unsigned addr) {
    asm volatile("ldmatrix.sync.aligned.m8n8.x4.shared.b16 {%0,%1,%2,%3},[%4];"
                 : "=r"(r0), "=r"(r1), "=r"(r2), "=r"(r3) : "r"(addr));
}

#define NT_STAGE (128 * 36)
#define NT_SMEM (4 * NT_STAGE * 4)
#define NN_ASTG (128 * 36)
#define NN_BSTG (32 * 68)
#define NN_SMEM ((2 * NN_ASTG + 2 * NN_BSTG) * 4)

extern __shared__ unsigned smem_u[];

// ================= NT GEMM: C = alpha * A(I,K) @ B(J,K)^T (+rb +cb) =================
__global__ void __launch_bounds__(256, 2)
mma_nt(const float* __restrict__ A, long Abs, long Ahs, int ldA,
       const float* __restrict__ Bp, long Bbs, long Bhs, int ldB,
       const float* __restrict__ scaleA,
       const float* __restrict__ rbias, const float* __restrict__ cbias,
       float* __restrict__ Cp, int I, int J, int K, float alpha, int causal) {
    const int bh = blockIdx.z, b = bh >> 3, h = bh & 7;
    const int j0 = blockIdx.x * 128, i0 = blockIdx.y * 128;
    if (causal && j0 > i0) return;
    unsigned* As = smem_u;
    unsigned* Bs = smem_u + 2 * NT_STAGE;
    const unsigned sA0 = (unsigned)__cvta_generic_to_shared(As);
    const unsigned sB0 = (unsigned)__cvta_generic_to_shared(Bs);
    const float* Ab = A + (long)b * Abs + (long)h * Ahs + (long)i0 * ldA;
    const float* Bb = Bp + (long)b * Bbs + (long)h * Bhs + (long)j0 * ldB;

    const int tid = threadIdx.x, wid = tid >> 5, lane = tid & 31;
    const int g = lane >> 2, t = lane & 3;
    const int wm = (wid & 1) * 64, wn = (wid >> 1) * 32;
    const int lrow = lane & 15, lblk = lane >> 4;
    const int ldrow = tid >> 3, ldc4 = (tid & 7) * 4;

    float sreg[16];
    const bool hasS = (scaleA != nullptr);
    if (hasS) {
        const float* sA = scaleA + h * HDc;
        #pragma unroll
        for (int j = 0; j < 8; j++) {
            sreg[2 * j] = sA[8 * j + t];
            sreg[2 * j + 1] = sA[8 * j + t + 4];
        }
    }

    const int niter = K / 32;
    float acc[4][4][4] = {};

    {
        #pragma unroll
        for (int w = 0; w < 4; w++) {
            int r = ldrow + w * 32;
            cpa16(sA0 + (r * 36 + ldc4) * 4, Ab + (long)r * ldA + ldc4);
            cpa16(sB0 + (r * 36 + ldc4) * 4, Bb + (long)r * ldB + ldc4);
        }
        cpcommit();
    }

    for (int it = 0; it < niter; it++) {
        if (it + 1 < niter) {
            const int k0 = (it + 1) * 32, buf = (it + 1) & 1;
            #pragma unroll
            for (int w = 0; w < 4; w++) {
                int r = ldrow + w * 32;
                cpa16(sA0 + (buf * NT_STAGE + r * 36 + ldc4) * 4,
                      Ab + (long)r * ldA + k0 + ldc4);
                cpa16(sB0 + (buf * NT_STAGE + r * 36 + ldc4) * 4,
                      Bb + (long)r * ldB + k0 + ldc4);
            }
            cpcommit();
            asm volatile("cp.async.wait_group 1;");
        } else {
            asm volatile("cp.async.wait_group 0;");
        }
        __syncthreads();

        const int buf = it & 1;
        const unsigned aBase = sA0 + buf * NT_STAGE * 4;
        const unsigned bBase = sB0 + buf * NT_STAGE * 4;
        #pragma unroll
        for (int kk = 0; kk < 4; kk++) {
            const int kb = kk * 8 + 4 * lblk;
            unsigned a[4][4], bb[4][2];
            #pragma unroll
            for (int mf = 0; mf < 4; mf++)
                ldsm4(a[mf][0], a[mf][1], a[mf][2], a[mf][3],
                      aBase + ((wm + mf * 16 + lrow) * 36 + kb) * 4);
            #pragma unroll
            for (int p = 0; p < 2; p++) {
                unsigned r0, r1, r2, r3;
                ldsm4(r0, r1, r2, r3, bBase + ((wn + p * 16 + lrow) * 36 + kb) * 4);
                bb[2 * p][0] = f2tf(__uint_as_float(r0));
                bb[2 * p][1] = f2tf(__uint_as_float(r2));
                bb[2 * p + 1][0] = f2tf(__uint_as_float(r1));
                bb[2 * p + 1][1] = f2tf(__uint_as_float(r3));
            }
            if (hasS) {
                const int j = it * 4 + kk;
                const float slo = sreg[2 * j], shi = sreg[2 * j + 1];
                #pragma unroll
                for (int mf = 0; mf < 4; mf++) {
                    a[mf][0] = f2tf(__uint_as_float(a[mf][0]) * slo);
                    a[mf][1] = f2tf(__uint_as_float(a[mf][1]) * slo);
                    a[mf][2] = f2tf(__uint_as_float(a[mf][2]) * shi);
                    a[mf][3] = f2tf(__uint_as_float(a[mf][3]) * shi);
                }
            } else {
                #pragma unroll
                for (int mf = 0; mf < 4; mf++)
                    #pragma unroll
                    for (int q = 0; q < 4; q++)
                        a[mf][q] = f2tf(__uint_as_float(a[mf][q]));
            }
            #pragma unroll
            for (int mf = 0; mf < 4; mf++)
                #pragma unroll
                for (int nf = 0; nf < 4; nf++) mma8(acc[mf][nf], a[mf], bb[nf]);
        }
        __syncthreads();
    }

    float* Cb = Cp + (long)bh * I * J;
    const float* rb = rbias ? rbias + (long)bh * I : nullptr;
    const float* cb = cbias ? cbias + (long)bh * J : nullptr;
    #pragma unroll
    for (int mf = 0; mf < 4; mf++)
        #pragma unroll
        for (int nf = 0; nf < 4; nf++) {
            int r0 = i0 + wm + mf * 16 + g;
            int c0 = j0 + wn + nf * 8 + 2 * t;
            #pragma unroll
            for (int ep = 0; ep < 2; ep++) {
                int rr = r0 + ep * 8;
                float v0 = acc[mf][nf][2 * ep] * alpha;
                float v1 = acc[mf][nf][2 * ep + 1] * alpha;
                if (rb) { v0 += rb[rr]; v1 += rb[rr]; }
                if (cb) { v0 += cb[c0]; v1 += cb[c0 + 1]; }
                *(float2*)&Cb[(long)rr * J + c0] = make_float2(v0, v1);
            }
        }
}

// ================= NN GEMM with fused epilogues =================
// epilogue: v = acc (+bias[col]) (+=C) (+addV); if gate buffers given:
//   v = sigmoid(gGs)*gA2 + sigmoid(v)*gB2
__global__ void __launch_bounds__(256, 2)
mma_nn(const float* __restrict__ A, long Abs, long Ahs, int ldA,
       const float* __restrict__ Bp, long Bbs, long Bhs, int ldB,
       const float* __restrict__ bias,
       float* __restrict__ Cp, long Cbs, long Chs, int ldC,
       int K, int accumulate, int trailK,
       const float* __restrict__ addV,
       const float* __restrict__ gGs, const float* __restrict__ gA2,
       const float* __restrict__ gB2) {
    const int bh = blockIdx.z, b = bh >> 3, h = bh & 7;
    const int col0 = blockIdx.x * 64, i0 = blockIdx.y * 128;
    unsigned* As = smem_u;
    unsigned* Bs = smem_u + 2 * NN_ASTG;
    const unsigned sA0 = (unsigned)__cvta_generic_to_shared(As);
    const unsigned sB0 = (unsigned)__cvta_generic_to_shared(Bs);
    const float* Ab = A + (long)b * Abs + (long)h * Ahs + (long)i0 * ldA;
    const float* Bb = Bp + (long)b * Bbs + (long)h * Bhs + col0;

    const int tid = threadIdx.x, wid = tid >> 5, lane = tid & 31;
    const int g = lane >> 2, t = lane & 3;
    const int wm = (wid & 1) * 64, wn = (wid >> 1) * 16;
    const int lrow = lane & 15, lblk = lane >> 4;
    const int ldrow = tid >> 3, ldc4 = (tid & 7) * 4;

    const int Keff = trailK ? min(K, i0 + 128) : K;
    const int niter = Keff / 32;
    float acc[4][2][4] = {};

    {
        #pragma unroll
        for (int w = 0; w < 4; w++) {
            int r = ldrow + w * 32;
            cpa16(sA0 + (r * 36 + ldc4) * 4, Ab + (long)r * ldA + ldc4);
        }
        #pragma unroll
        for (int w = 0; w < 2; w++) {
            int li = tid + w * 256;
            int r = li >> 4, c4 = (li & 15) * 4;
            cpa16(sB0 + (r * 68 + c4) * 4, Bb + (long)r * ldB + c4);
        }
        cpcommit();
    }

    for (int it = 0; it < niter; it++) {
        if (it + 1 < niter) {
            const int k0 = (it + 1) * 32, buf = (it + 1) & 1;
            #pragma unroll
            for (int w = 0; w < 4; w++) {
                int r = ldrow + w * 32;
                cpa16(sA0 + (buf * NN_ASTG + r * 36 + ldc4) * 4,
                      Ab + (long)r * ldA + k0 + ldc4);
            }
            #pragma unroll
            for (int w = 0; w < 2; w++) {
                int li = tid + w * 256;
                int r = li >> 4, c4 = (li & 15) * 4;
                cpa16(sB0 + (buf * NN_BSTG + r * 68 + c4) * 4,
                      Bb + (long)(k0 + r) * ldB + c4);
            }
            cpcommit();
            asm volatile("cp.async.wait_group 1;");
        } else {
            asm volatile("cp.async.wait_group 0;");
        }
        __syncthreads();

        const int buf = it & 1;
        const unsigned aBase = sA0 + buf * NN_ASTG * 4;
        const unsigned* Bbuf = Bs + buf * NN_BSTG;
        #pragma unroll
        for (int kk = 0; kk < 4; kk++) {
            const int kb8 = kk * 8;
            unsigned a[4][4], bb[2][2];
            #pragma unroll
            for (int mf = 0; mf < 4; mf++) {
                ldsm4(a[mf][0], a[mf][1], a[mf][2], a[mf][3],
                      aBase + ((wm + mf * 16 + lrow) * 36 + kb8 + 4 * lblk) * 4);
                #pragma unroll
                for (int q = 0; q < 4; q++)
                    a[mf][q] = f2tf(__uint_as_float(a[mf][q]));
            }
            #pragma unroll
            for (int nf = 0; nf < 2; nf++) {
                bb[nf][0] = f2tf(__uint_as_float(Bbuf[(kb8 + t) * 68 + wn + nf * 8 + g]));
                bb[nf][1] = f2tf(__uint_as_float(Bbuf[(kb8 + t + 4) * 68 + wn + nf * 8 + g]));
            }
            #pragma unroll
            for (int mf = 0; mf < 4; mf++)
                #pragma unroll
                for (int nf = 0; nf < 2; nf++) mma8(acc[mf][nf], a[mf], bb[nf]);
        }
        __syncthreads();
    }

    const long baseoff = (long)b * Cbs + (long)h * Chs + (long)i0 * ldC + col0;
    float* Cb = Cp + baseoff;
    const float* Xb = addV ? addV + baseoff : nullptr;
    const float* Gs = gGs ? gGs + baseoff : nullptr;
    const float* A2 = gA2 ? gA2 + baseoff : nullptr;
    const float* B2 = gB2 ? gB2 + baseoff : nullptr;
    #pragma unroll
    for (int mf = 0; mf < 4; mf++)
        #pragma unroll
        for (int nf = 0; nf < 2; nf++) {
            int r0 = wm + mf * 16 + g;
            int c0 = wn + nf * 8 + 2 * t;
            #pragma unroll
            for (int e = 0; e < 4; e++) {
                int rr = r0 + (e >> 1) * 8;
                int cc = c0 + (e & 1);
                float v = acc[mf][nf][e];
                if (bias) v += bias[col0 + cc];
                long off = (long)rr * ldC + cc;
                if (accumulate) v += Cb[off];
                if (Xb) v += Xb[off];
                if (Gs) {
                    float sg = 1.f / (1.f + expf(-Gs[off]));
                    float cg = 1.f / (1.f + expf(-v));
                    v = sg * A2[off] + cg * B2[off];
                }
                Cb[off] = v;
            }
        }
}

// -------- catt1/catt2 dot products --------
__global__ void dotw(const float* __restrict__ qkv, const float* __restrict__ w,
                     int rows, float* __restrict__ out) {
    int gw = (blockIdx.x * blockDim.x + threadIdx.x) >> 5;
    int lane = threadIdx.x & 31;
    if (gw >= BHc * rows) return;
    int bh = gw / rows, r = gw % rows;
    int b = bh >> 3, h = bh & 7;
    const float* p = qkv + (long)(b * rows + r) * C3c + h * HDc;
    float s = p[lane] * w[h * HDc + lane] + p[lane + 32] * w[h * HDc + lane + 32];
    #pragma unroll
    for (int o = 16; o; o >>= 1) s += __shfl_xor_sync(0xffffffffu, s, o);
    if (lane == 0) out[gw] = s;
}

// -------- row softmax over M=256 --------
__global__ void softmax_row256(const float* __restrict__ in, float* __restrict__ out) {
    long row = blockIdx.x;
    int tid = threadIdx.x;
    __shared__ float sh[8];
    float v = in[row * 256 + tid];
    float m = v;
    #pragma unroll
    for (int o = 16; o; o >>= 1) m = fmaxf(m, __shfl_xor_sync(0xffffffffu, m, o));
    if ((tid & 31) == 0) sh[tid >> 5] = m;
    __syncthreads();
    float bm = sh[0];
    #pragma unroll
    for (int i = 1; i < 8; i++) bm = fmaxf(bm, sh[i]);
    __syncthreads();
    float e = expf(v - bm);
    float s = e;
    #pragma unroll
    for (int o = 16; o; o >>= 1) s += __shfl_xor_sync(0xffffffffu, s, o);
    if ((tid & 31) == 0) sh[tid >> 5] = s;
    __syncthreads();
    float bs = 0.f;
    #pragma unroll
    for (int i = 0; i < 8; i++) bs += sh[i];
    out[row * 256 + tid] = e / bs;
}

// -------- column softmax over T=1024 --------
__global__ void softmax_col(const float* __restrict__ in, float* __restrict__ out) {
    int bh = blockIdx.y;
    int mx = threadIdx.x & 63;
    int ty = threadIdx.x >> 6;
    int m = blockIdx.x * 64 + mx;
    const float* base = in + (long)bh * Tc * Mc + m;
    __shared__ float red[256];
    __shared__ float cstat[64];
    float acc = -3.4e38f;
    for (int t = ty; t < Tc; t += 4) acc = fmaxf(acc, base[(long)t * Mc]);
    red[threadIdx.x] = acc;
    __syncthreads();
    if (ty == 0)
        cstat[mx] = fmaxf(fmaxf(red[mx], red[64 + mx]), fmaxf(red[128 + mx], red[192 + mx]));
    __syncthreads();
    float cm = cstat[mx];
    __syncthreads();
    float s = 0.f;
    for (int t = ty; t < Tc; t += 4) s += expf(base[(long)t * Mc] - cm);
    red[threadIdx.x] = s;
    __syncthreads();
    if (ty == 0) cstat[mx] = red[mx] + red[64 + mx] + red[128 + mx] + red[192 + mx];
    __syncthreads();
    float inv = 1.f / cstat[mx];
    float* ob = out + (long)bh * Tc * Mc + m;
    for (int t = ty; t < Tc; t += 4) ob[(long)t * Mc] = expf(base[(long)t * Mc] - cm) * inv;
}

// -------- causal row softmax, trimmed to diagonal block, in-place --------
__global__ void softmax_causal(float* __restrict__ buf) {
    long row = blockIdx.x;
    int t = (int)(row & 1023);
    const int len = ((t >> 7) + 1) << 7;
    float* p = buf + row * 1024;
    int tid = threadIdx.x;
    __shared__ float sh[8];
    float v[4];
    float m = -3.4e38f;
    const int nchunk = (len + 255) >> 8;
    #pragma unroll 4
    for (int j = 0; j < nchunk; j++) {
        int s = tid + j * 256;
        float val = (s < len && s <= t) ? p[s] : -3.4e38f;
        v[j] = val;
        m = fmaxf(m, val);
    }
    #pragma unroll
    for (int o = 16; o; o >>= 1) m = fmaxf(m, __shfl_xor_sync(0xffffffffu, m, o));
    if ((tid & 31) == 0) sh[tid >> 5] = m;
    __syncthreads();
    float bm = sh[0];
    #pragma unroll
    for (int i = 1; i < 8; i++) bm = fmaxf(bm, sh[i]);
    __syncthreads();
    float sum = 0.f;
    #pragma unroll 4
    for (int j = 0; j < nchunk; j++) {
        int s = tid + j * 256;
        float e = (s < len && s <= t) ? expf(v[j] - bm) : 0.f;
        v[j] = e;
        sum += e;
    }
    #pragma unroll
    for (int o = 16; o; o >>= 1) sum += __shfl_xor_sync(0xffffffffu, sum, o);
    if ((tid & 31) == 0) sh[tid >> 5] = sum;
    __syncthreads();
    float bs = 0.f;
    #pragma unroll
    for (int i = 0; i < 8; i++) bs += sh[i];
    float inv = 1.f / bs;
    #pragma unroll 4
    for (int j = 0; j < nchunk; j++) {
        int s = tid + j * 256;
        if (s < len) p[s] = v[j] * inv;
    }
}

extern "C" void kernel_launch(void* const* d_in, const int* in_sizes, int n_in,
                              void* d_out, int out_size) {
    const float* x      = (const float*)d_in[0];
    const float* y      = (const float*)d_in[1];
    const float* Wqkv_x = (const float*)d_in[3];
    const float* bqkv_x = (const float*)d_in[4];
    const float* Wqkv_y = (const float*)d_in[5];
    const float* bqkv_y = (const float*)d_in[6];
    const float* w4x    = (const float*)d_in[7];
    const float* w4y    = (const float*)d_in[8];
    const float* w4xy   = (const float*)d_in[9];
    const float* Wgs    = (const float*)d_in[10];
    const float* bgs    = (const float*)d_in[11];
    const float* Wgc    = (const float*)d_in[12];
    const float* bgc    = (const float*)d_in[13];
    const float* Wp     = (const float*)d_in[14];
    const float* bp     = (const float*)d_in[15];
    float* out = (float*)d_out;

    cudaFuncSetAttribute(mma_nt, cudaFuncAttributeMaxDynamicSharedMemorySize, NT_SMEM);
    cudaFuncSetAttribute(mma_nn, cudaFuncAttributeMaxDynamicSharedMemorySize, NN_SMEM);

    float *p_qkv_x, *p_qkv_y, *p_catt1, *p_catt2, *p_catt, *p_x2y, *p_y2x,
          *p_big, *p_big2, *p_cval, *p_sval, *p_gs, *p_z;
    cudaGetSymbolAddress((void**)&p_qkv_x, g_qkv_x);
    cudaGetSymbolAddress((void**)&p_qkv_y, g_qkv_y);
    cudaGetSymbolAddress((void**)&p_catt1, g_catt1);
    cudaGetSymbolAddress((void**)&p_catt2, g_catt2);
    cudaGetSymbolAddress((void**)&p_catt, g_catt);
    cudaGetSymbolAddress((void**)&p_x2y, g_x2y);
    cudaGetSymbolAddress((void**)&p_y2x, g_y2x);
    cudaGetSymbolAddress((void**)&p_big, g_big);
    cudaGetSymbolAddress((void**)&p_big2, g_big2);
    cudaGetSymbolAddress((void**)&p_cval, g_cval);
    cudaGetSymbolAddress((void**)&p_sval, g_sval);
    cudaGetSymbolAddress((void**)&p_gs, g_gs);
    cudaGetSymbolAddress((void**)&p_z, g_z);

    const float scale = 0.125f;
    const float invSqrtM = 0.0625f;

    // 1. QKV x
    mma_nn<<<dim3(C3c / 64, (Bc * Tc) / 128, 1), 256, NN_SMEM>>>(
        x, 0, 0, Cc, Wqkv_x, 0, 0, C3c, bqkv_x,
        p_qkv_x, 0, 0, C3c, Cc, 0, 0, nullptr, nullptr, nullptr, nullptr);
    // 2. QKV y
    mma_nn<<<dim3(C3c / 64, (Bc * Mc) / 128, 1), 256, NN_SMEM>>>(
        y, 0, 0, Cc, Wqkv_y, 0, 0, C3c, bqkv_y,
        p_qkv_y, 0, 0, C3c, Cc, 0, 0, nullptr, nullptr, nullptr, nullptr);
    // 3. dotw x
    dotw<<<(BHc * Tc) / 8, 256>>>(p_qkv_x, w4x, Tc, p_catt1);
    // 4. satt NT (profiling slot) — independent, own buffer
    mma_nt<<<dim3(Tc / 128, Tc / 128, BHc), 256, NT_SMEM>>>(
        p_qkv_x, (long)Tc * C3c, 64, C3c,
        p_qkv_x + Cc, (long)Tc * C3c, 64, C3c,
        nullptr, nullptr, nullptr,
        p_big2, Tc, Tc, HDc, scale, 1);
    // 5. dotw y
    dotw<<<(BHc * Mc) / 8, 256>>>(p_qkv_y, w4y, Mc, p_catt2);
    // 6. satt softmax
    softmax_causal<<<BHc * Tc, 256>>>(p_big2);
    // 7. sval = satt @ v_x
    mma_nn<<<dim3(1, Tc / 128, BHc), 256, NN_SMEM>>>(
        p_big2, 8L * Tc * Tc, (long)Tc * Tc, Tc,
        p_qkv_x + 2 * Cc, (long)Tc * C3c, 64, C3c, nullptr,
        p_sval, (long)Tc * Cc, 64, Cc, Tc, 0, 1, nullptr, nullptr, nullptr, nullptr);
    // 8. gs = sval @ Wgs + bgs (pre-sigmoid)
    mma_nn<<<dim3(Cc / 64, (Bc * Tc) / 128, 1), 256, NN_SMEM>>>(
        p_sval, 0, 0, Cc, Wgs, 0, 0, Cc, bgs,
        p_gs, 0, 0, Cc, Cc, 0, 0, nullptr, nullptr, nullptr, nullptr);

    // 9. catt = scale*(q_x*w4xy)@k_y^T + catt1 + catt2
    mma_nt<<<dim3(Mc / 128, Tc / 128, BHc), 256, NT_SMEM>>>(
        p_qkv_x, (long)Tc * C3c, 64, C3c,
        p_qkv_y + Cc, (long)Mc * C3c, 64, C3c,
        w4xy, p_catt1, p_catt2,
        p_catt, Tc, Mc, HDc, scale, 0);
    // 10-11. softmaxes
    softmax_row256<<<BHc * Tc, 256>>>(p_catt, p_x2y);
    softmax_col<<<dim3(Mc / 64, BHc), 256>>>(p_catt, p_y2x);
    // 12. cval = x2y @ v_y
    mma_nn<<<dim3(1, Tc / 128, BHc), 256, NN_SMEM>>>(
        p_x2y, 8L * Tc * Mc, (long)Tc * Mc, Mc,
        p_qkv_y + 2 * Cc, (long)Mc * C3c, 64, C3c, nullptr,
        p_cval, (long)Tc * Cc, 64, Cc, Mc, 0, 0, nullptr, nullptr, nullptr, nullptr);
    // 13. chain scores
    mma_nt<<<dim3(Tc / 128, Tc / 128, BHc), 256, NT_SMEM>>>(
        p_x2y, 8L * Tc * Mc, (long)Tc * Mc, Mc,
        p_y2x, 8L * Tc * Mc, (long)Tc * Mc, Mc,
        nullptr, nullptr, nullptr,
        p_big, Tc, Tc, Mc, invSqrtM, 1);
    // 14. chain softmax
    softmax_causal<<<BHc * Tc, 256>>>(p_big);
    // 15. cval += chain @ v_x + x  (fused residual)
    mma_nn<<<dim3(1, Tc / 128, BHc), 256, NN_SMEM>>>(
        p_big, 8L * Tc * Tc, (long)Tc * Tc, Tc,
        p_qkv_x + 2 * Cc, (long)Tc * C3c, 64, C3c, nullptr,
        p_cval, (long)Tc * Cc, 64, Cc, Tc, 1, 1, x, nullptr, nullptr, nullptr);

    // 16. z = sigmoid(gs)*cval + sigmoid(cval@Wgc+bgc)*sval  (fused gate+combine)
    mma_nn<<<dim3(Cc / 64, (Bc * Tc) / 128, 1), 256, NN_SMEM>>>(
        p_cval, 0, 0, Cc, Wgc, 0, 0, Cc, bgc,
        p_z, 0, 0, Cc, Cc, 0, 0, nullptr, p_gs, p_cval, p_sval);

    // 17. out = z @ Wp + bp
    mma_nn<<<dim3(Cc / 64, (Bc * Tc) / 128, 1), 256, NN_SMEM>>>(
        p_z, 0, 0, Cc, Wp, 0, 0, Cc, bp,
        out, 0, 0, Cc, Cc, 0, 0, nullptr, nullptr, nullptr, nullptr);
}

// round 8
// speedup vs baseline: 1.0313x; 1.0313x over previous
#include <cuda_runtime.h>
#include <cuda_bf16.h>
#include <math.h>

#define Bc 4
#define Tc 1024
#define Mc 256
#define Cc 512
#define Hc 8
#define HDc 64
#define C3c 1536
#define BHc 32

// ---------------- scratch ----------------
__device__ float g_qkv_x[Bc * Tc * C3c];
__device__ float g_qkv_y[Bc * Mc * C3c];
__device__ float g_catt1[BHc * Tc];
__device__ float g_catt2[BHc * Mc];
__device__ float g_catt[(long)BHc * Tc * Mc];
__device__ float g_x2y[(long)BHc * Tc * Mc];
__device__ float g_y2x[(long)BHc * Tc * Mc];
__device__ float g_big[(long)BHc * Tc * Tc];    // chain scores
__device__ float g_big2[(long)BHc * Tc * Tc];   // satt scores
__device__ float g_cval[Bc * Tc * Cc];
__device__ float g_sval[Bc * Tc * Cc];
__device__ float g_gs[Bc * Tc * Cc];
__device__ float g_z[Bc * Tc * Cc];

// ---------------- helpers ----------------
__device__ __forceinline__ float rnd(float f) {
    unsigned u;
    asm("cvt.rna.tf32.f32 %0, %1;" : "=r"(u) : "f"(f));
    return __uint_as_float(u);
}
__device__ __forceinline__ unsigned f2tf(float f) {
    unsigned u;
    asm("cvt.rna.tf32.f32 %0, %1;" : "=r"(u) : "f"(f));
    return u;
}
__device__ __forceinline__ void mma8(float* d, const unsigned* a, const unsigned* b) {
    asm volatile(
        "mma.sync.aligned.m16n8k8.row.col.f32.tf32.tf32.f32 "
        "{%0,%1,%2,%3},{%4,%5,%6,%7},{%8,%9},{%0,%1,%2,%3};"
        : "+f"(d[0]), "+f"(d[1]), "+f"(d[2]), "+f"(d[3])
        : "r"(a[0]), "r"(a[1]), "r"(a[2]), "r"(a[3]), "r"(b[0]), "r"(b[1]));
}
__device__ __forceinline__ void cpa16(unsigned dst, const void* src) {
    asm volatile("cp.async.cg.shared.global [%0], [%1], 16;" :: "r"(dst), "l"(src));
}
__device__ __forceinline__ void cpcommit() { asm volatile("cp.async.commit_group;"); }
__device__ __forceinline__ void ldsm4(unsigned& r0, unsigned& r1, unsigned& r2, unsigned& r3,
                                      unsigned addr) {
    asm volatile("ldmatrix.sync.aligned.m8n8.x4.shared.b16 {%0,%1,%2,%3},[%4];"
                 : "=r"(r0), "=r"(r1), "=r"(r2), "=r"(r3) : "r"(addr));
}

#define NT_STAGE (128 * 36)
#define NT_SMEM (4 * NT_STAGE * 4)
#define NN_ASTG (128 * 36)
#define NN_BSTG (32 * 68)
#define NN_SMEM ((2 * NN_ASTG + 2 * NN_BSTG) * 4)

extern __shared__ unsigned smem_u[];

// ================= NT GEMM: C = alpha * A(I,K) @ B(J,K)^T (+rb +cb) =================
// cvtIn=0 requires tf32-prerounded inputs (raw-bit feed is then exact).
__global__ void __launch_bounds__(256, 2)
mma_nt(const float* __restrict__ A, long Abs, long Ahs, int ldA,
       const float* __restrict__ Bp, long Bbs, long Bhs, int ldB,
       const float* __restrict__ scaleA,
       const float* __restrict__ rbias, const float* __restrict__ cbias,
       float* __restrict__ Cp, int I, int J, int K, float alpha, int causal,
       int cvtIn) {
    const int bh = blockIdx.z, b = bh >> 3, h = bh & 7;
    const int j0 = blockIdx.x * 128, i0 = blockIdx.y * 128;
    if (causal && j0 > i0) return;
    unsigned* As = smem_u;
    unsigned* Bs = smem_u + 2 * NT_STAGE;
    const unsigned sA0 = (unsigned)__cvta_generic_to_shared(As);
    const unsigned sB0 = (unsigned)__cvta_generic_to_shared(Bs);
    const float* Ab = A + (long)b * Abs + (long)h * Ahs + (long)i0 * ldA;
    const float* Bb = Bp + (long)b * Bbs + (long)h * Bhs + (long)j0 * ldB;

    const int tid = threadIdx.x, wid = tid >> 5, lane = tid & 31;
    const int g = lane >> 2, t = lane & 3;
    const int wm = (wid & 1) * 64, wn = (wid >> 1) * 32;
    const int lrow = lane & 15, lblk = lane >> 4;
    const int ldrow = tid >> 3, ldc4 = (tid & 7) * 4;

    float sreg[16];
    const bool hasS = (scaleA != nullptr);
    if (hasS) {
        const float* sA = scaleA + h * HDc;
        #pragma unroll
        for (int j = 0; j < 8; j++) {
            sreg[2 * j] = sA[8 * j + t];
            sreg[2 * j + 1] = sA[8 * j + t + 4];
        }
    }

    const int niter = K / 32;
    float acc[4][4][4] = {};

    {
        #pragma unroll
        for (int w = 0; w < 4; w++) {
            int r = ldrow + w * 32;
            cpa16(sA0 + (r * 36 + ldc4) * 4, Ab + (long)r * ldA + ldc4);
            cpa16(sB0 + (r * 36 + ldc4) * 4, Bb + (long)r * ldB + ldc4);
        }
        cpcommit();
    }

    for (int it = 0; it < niter; it++) {
        if (it + 1 < niter) {
            const int k0 = (it + 1) * 32, buf = (it + 1) & 1;
            #pragma unroll
            for (int w = 0; w < 4; w++) {
                int r = ldrow + w * 32;
                cpa16(sA0 + (buf * NT_STAGE + r * 36 + ldc4) * 4,
                      Ab + (long)r * ldA + k0 + ldc4);
                cpa16(sB0 + (buf * NT_STAGE + r * 36 + ldc4) * 4,
                      Bb + (long)r * ldB + k0 + ldc4);
            }
            cpcommit();
            asm volatile("cp.async.wait_group 1;");
        } else {
            asm volatile("cp.async.wait_group 0;");
        }
        __syncthreads();

        const int buf = it & 1;
        const unsigned aBase = sA0 + buf * NT_STAGE * 4;
        const unsigned bBase = sB0 + buf * NT_STAGE * 4;
        #pragma unroll
        for (int kk = 0; kk < 4; kk++) {
            const int kb = kk * 8 + 4 * lblk;
            unsigned a[4][4], bb[4][2];
            #pragma unroll
            for (int mf = 0; mf < 4; mf++)
                ldsm4(a[mf][0], a[mf][1], a[mf][2], a[mf][3],
                      aBase + ((wm + mf * 16 + lrow) * 36 + kb) * 4);
            #pragma unroll
            for (int p = 0; p < 2; p++) {
                unsigned r0, r1, r2, r3;
                ldsm4(r0, r1, r2, r3, bBase + ((wn + p * 16 + lrow) * 36 + kb) * 4);
                bb[2 * p][0] = r0;
                bb[2 * p][1] = r2;
                bb[2 * p + 1][0] = r1;
                bb[2 * p + 1][1] = r3;
            }
            if (cvtIn) {
                #pragma unroll
                for (int nf = 0; nf < 4; nf++) {
                    bb[nf][0] = f2tf(__uint_as_float(bb[nf][0]));
                    bb[nf][1] = f2tf(__uint_as_float(bb[nf][1]));
                }
            }
            if (hasS) {
                const int j = it * 4 + kk;
                const float slo = sreg[2 * j], shi = sreg[2 * j + 1];
                #pragma unroll
                for (int mf = 0; mf < 4; mf++) {
                    a[mf][0] = f2tf(__uint_as_float(a[mf][0]) * slo);
                    a[mf][1] = f2tf(__uint_as_float(a[mf][1]) * slo);
                    a[mf][2] = f2tf(__uint_as_float(a[mf][2]) * shi);
                    a[mf][3] = f2tf(__uint_as_float(a[mf][3]) * shi);
                }
            } else if (cvtIn) {
                #pragma unroll
                for (int mf = 0; mf < 4; mf++)
                    #pragma unroll
                    for (int q = 0; q < 4; q++)
                        a[mf][q] = f2tf(__uint_as_float(a[mf][q]));
            }
            #pragma unroll
            for (int mf = 0; mf < 4; mf++)
                #pragma unroll
                for (int nf = 0; nf < 4; nf++) mma8(acc[mf][nf], a[mf], bb[nf]);
        }
        __syncthreads();
    }

    float* Cb = Cp + (long)bh * I * J;
    const float* rb = rbias ? rbias + (long)bh * I : nullptr;
    const float* cb = cbias ? cbias + (long)bh * J : nullptr;
    #pragma unroll
    for (int mf = 0; mf < 4; mf++)
        #pragma unroll
        for (int nf = 0; nf < 4; nf++) {
            int r0 = i0 + wm + mf * 16 + g;
            int c0 = j0 + wn + nf * 8 + 2 * t;
            #pragma unroll
            for (int ep = 0; ep < 2; ep++) {
                int rr = r0 + ep * 8;
                float v0 = acc[mf][nf][2 * ep] * alpha;
                float v1 = acc[mf][nf][2 * ep + 1] * alpha;
                if (rb) { v0 += rb[rr]; v1 += rb[rr]; }
                if (cb) { v0 += cb[c0]; v1 += cb[c0 + 1]; }
                *(float2*)&Cb[(long)rr * J + c0] = make_float2(v0, v1);
            }
        }
}

// ================= NN GEMM with fused epilogues =================
__global__ void __launch_bounds__(256, 2)
mma_nn(const float* __restrict__ A, long Abs, long Ahs, int ldA,
       const float* __restrict__ Bp, long Bbs, long Bhs, int ldB,
       const float* __restrict__ bias,
       float* __restrict__ Cp, long Cbs, long Chs, int ldC,
       int K, int accumulate, int trailK, int cvtIn, int roundOut,
       const float* __restrict__ addV,
       const float* __restrict__ gGs, const float* __restrict__ gA2,
       const float* __restrict__ gB2) {
    const int bh = blockIdx.z, b = bh >> 3, h = bh & 7;
    const int col0 = blockIdx.x * 64, i0 = blockIdx.y * 128;
    unsigned* As = smem_u;
    unsigned* Bs = smem_u + 2 * NN_ASTG;
    const unsigned sA0 = (unsigned)__cvta_generic_to_shared(As);
    const unsigned sB0 = (unsigned)__cvta_generic_to_shared(Bs);
    const float* Ab = A + (long)b * Abs + (long)h * Ahs + (long)i0 * ldA;
    const float* Bb = Bp + (long)b * Bbs + (long)h * Bhs + col0;

    const int tid = threadIdx.x, wid = tid >> 5, lane = tid & 31;
    const int g = lane >> 2, t = lane & 3;
    const int wm = (wid & 1) * 64, wn = (wid >> 1) * 16;
    const int lrow = lane & 15, lblk = lane >> 4;
    const int ldrow = tid >> 3, ldc4 = (tid & 7) * 4;

    const int Keff = trailK ? min(K, i0 + 128) : K;
    const int niter = Keff / 32;
    float acc[4][2][4] = {};

    {
        #pragma unroll
        for (int w = 0; w < 4; w++) {
            int r = ldrow + w * 32;
            cpa16(sA0 + (r * 36 + ldc4) * 4, Ab + (long)r * ldA + ldc4);
        }
        #pragma unroll
        for (int w = 0; w < 2; w++) {
            int li = tid + w * 256;
            int r = li >> 4, c4 = (li & 15) * 4;
            cpa16(sB0 + (r * 68 + c4) * 4, Bb + (long)r * ldB + c4);
        }
        cpcommit();
    }

    for (int it = 0; it < niter; it++) {
        if (it + 1 < niter) {
            const int k0 = (it + 1) * 32, buf = (it + 1) & 1;
            #pragma unroll
            for (int w = 0; w < 4; w++) {
                int r = ldrow + w * 32;
                cpa16(sA0 + (buf * NN_ASTG + r * 36 + ldc4) * 4,
                      Ab + (long)r * ldA + k0 + ldc4);
            }
            #pragma unroll
            for (int w = 0; w < 2; w++) {
                int li = tid + w * 256;
                int r = li >> 4, c4 = (li & 15) * 4;
                cpa16(sB0 + (buf * NN_BSTG + r * 68 + c4) * 4,
                      Bb + (long)(k0 + r) * ldB + c4);
            }
            cpcommit();
            asm volatile("cp.async.wait_group 1;");
        } else {
            asm volatile("cp.async.wait_group 0;");
        }
        __syncthreads();

        const int buf = it & 1;
        const unsigned aBase = sA0 + buf * NN_ASTG * 4;
        const unsigned* Bbuf = Bs + buf * NN_BSTG;
        #pragma unroll
        for (int kk = 0; kk < 4; kk++) {
            const int kb8 = kk * 8;
            unsigned a[4][4], bb[2][2];
            #pragma unroll
            for (int mf = 0; mf < 4; mf++) {
                ldsm4(a[mf][0], a[mf][1], a[mf][2], a[mf][3],
                      aBase + ((wm + mf * 16 + lrow) * 36 + kb8 + 4 * lblk) * 4);
                if (cvtIn) {
                    #pragma unroll
                    for (int q = 0; q < 4; q++)
                        a[mf][q] = f2tf(__uint_as_float(a[mf][q]));
                }
            }
            #pragma unroll
            for (int nf = 0; nf < 2; nf++) {
                bb[nf][0] = Bbuf[(kb8 + t) * 68 + wn + nf * 8 + g];
                bb[nf][1] = Bbuf[(kb8 + t + 4) * 68 + wn + nf * 8 + g];
                if (cvtIn) {
                    bb[nf][0] = f2tf(__uint_as_float(bb[nf][0]));
                    bb[nf][1] = f2tf(__uint_as_float(bb[nf][1]));
                }
            }
            #pragma unroll
            for (int mf = 0; mf < 4; mf++)
                #pragma unroll
                for (int nf = 0; nf < 2; nf++) mma8(acc[mf][nf], a[mf], bb[nf]);
        }
        __syncthreads();
    }

    const long baseoff = (long)b * Cbs + (long)h * Chs + (long)i0 * ldC + col0;
    float* Cb = Cp + baseoff;
    const float* Xb = addV ? addV + baseoff : nullptr;
    const float* Gs = gGs ? gGs + baseoff : nullptr;
    const float* A2 = gA2 ? gA2 + baseoff : nullptr;
    const float* B2 = gB2 ? gB2 + baseoff : nullptr;
    #pragma unroll
    for (int mf = 0; mf < 4; mf++)
        #pragma unroll
        for (int nf = 0; nf < 2; nf++) {
            int r0 = wm + mf * 16 + g;
            int c0 = wn + nf * 8 + 2 * t;
            #pragma unroll
            for (int e = 0; e < 4; e++) {
                int rr = r0 + (e >> 1) * 8;
                int cc = c0 + (e & 1);
                float v = acc[mf][nf][e];
                if (bias) v += bias[col0 + cc];
                long off = (long)rr * ldC + cc;
                if (accumulate) v += Cb[off];
                if (Xb) v += Xb[off];
                if (Gs) {
                    float sg = 1.f / (1.f + expf(-Gs[off]));
                    float cg = 1.f / (1.f + expf(-v));
                    v = sg * A2[off] + cg * B2[off];
                }
                if (roundOut) v = rnd(v);
                Cb[off] = v;
            }
        }
}

// -------- catt1/catt2 dot products --------
__global__ void dotw(const float* __restrict__ qkv, const float* __restrict__ w,
                     int rows, float* __restrict__ out) {
    int gw = (blockIdx.x * blockDim.x + threadIdx.x) >> 5;
    int lane = threadIdx.x & 31;
    if (gw >= BHc * rows) return;
    int bh = gw / rows, r = gw % rows;
    int b = bh >> 3, h = bh & 7;
    const float* p = qkv + (long)(b * rows + r) * C3c + h * HDc;
    float s = p[lane] * w[h * HDc + lane] + p[lane + 32] * w[h * HDc + lane + 32];
    #pragma unroll
    for (int o = 16; o; o >>= 1) s += __shfl_xor_sync(0xffffffffu, s, o);
    if (lane == 0) out[gw] = s;
}

// -------- row softmax over M=256 (tf32-rounded output) --------
__global__ void softmax_row256(const float* __restrict__ in, float* __restrict__ out) {
    long row = blockIdx.x;
    int tid = threadIdx.x;
    __shared__ float sh[8];
    float v = in[row * 256 + tid];
    float m = v;
    #pragma unroll
    for (int o = 16; o; o >>= 1) m = fmaxf(m, __shfl_xor_sync(0xffffffffu, m, o));
    if ((tid & 31) == 0) sh[tid >> 5] = m;
    __syncthreads();
    float bm = sh[0];
    #pragma unroll
    for (int i = 1; i < 8; i++) bm = fmaxf(bm, sh[i]);
    __syncthreads();
    float e = expf(v - bm);
    float s = e;
    #pragma unroll
    for (int o = 16; o; o >>= 1) s += __shfl_xor_sync(0xffffffffu, s, o);
    if ((tid & 31) == 0) sh[tid >> 5] = s;
    __syncthreads();
    float bs = 0.f;
    #pragma unroll
    for (int i = 0; i < 8; i++) bs += sh[i];
    out[row * 256 + tid] = rnd(e / bs);
}

// -------- column softmax over T=1024 (tf32-rounded output) --------
__global__ void softmax_col(const float* __restrict__ in, float* __restrict__ out) {
    int bh = blockIdx.y;
    int mx = threadIdx.x & 63;
    int ty = threadIdx.x >> 6;
    int m = blockIdx.x * 64 + mx;
    const float* base = in + (long)bh * Tc * Mc + m;
    __shared__ float red[256];
    __shared__ float cstat[64];
    float acc = -3.4e38f;
    for (int t = ty; t < Tc; t += 4) acc = fmaxf(acc, base[(long)t * Mc]);
    red[threadIdx.x] = acc;
    __syncthreads();
    if (ty == 0)
        cstat[mx] = fmaxf(fmaxf(red[mx], red[64 + mx]), fmaxf(red[128 + mx], red[192 + mx]));
    __syncthreads();
    float cm = cstat[mx];
    __syncthreads();
    float s = 0.f;
    for (int t = ty; t < Tc; t += 4) s += expf(base[(long)t * Mc] - cm);
    red[threadIdx.x] = s;
    __syncthreads();
    if (ty == 0) cstat[mx] = red[mx] + red[64 + mx] + red[128 + mx] + red[192 + mx];
    __syncthreads();
    float inv = 1.f / cstat[mx];
    float* ob = out + (long)bh * Tc * Mc + m;
    for (int t = ty; t < Tc; t += 4) ob[(long)t * Mc] = rnd(expf(base[(long)t * Mc] - cm) * inv);
}

// -------- causal row softmax, trimmed, STATIC unroll (no local spills) --------
__global__ void softmax_causal(float* __restrict__ buf) {
    long row = blockIdx.x;
    int t = (int)(row & 1023);
    const int len = ((t >> 7) + 1) << 7;   // multiple of 128
    float* p = buf + row * 1024;
    int tid = threadIdx.x;
    __shared__ float sh[8];
    float v[4];
    float m = -3.4e38f;
    #pragma unroll
    for (int j = 0; j < 4; j++) {
        int s = tid + j * 256;
        float val = -3.4e38f;
        if (j * 256 < len) {                 // uniform per block
            if (s <= t) val = p[s];
        }
        v[j] = val;
        m = fmaxf(m, val);
    }
    #pragma unroll
    for (int o = 16; o; o >>= 1) m = fmaxf(m, __shfl_xor_sync(0xffffffffu, m, o));
    if ((tid & 31) == 0) sh[tid >> 5] = m;
    __syncthreads();
    float bm = sh[0];
    #pragma unroll
    for (int i = 1; i < 8; i++) bm = fmaxf(bm, sh[i]);
    __syncthreads();
    float sum = 0.f;
    #pragma unroll
    for (int j = 0; j < 4; j++) {
        int s = tid + j * 256;
        float e = 0.f;
        if (j * 256 < len) {
            if (s <= t) e = expf(v[j] - bm);
        }
        v[j] = e;
        sum += e;
    }
    #pragma unroll
    for (int o = 16; o; o >>= 1) sum += __shfl_xor_sync(0xffffffffu, sum, o);
    if ((tid & 31) == 0) sh[tid >> 5] = sum;
    __syncthreads();
    float bs = 0.f;
    #pragma unroll
    for (int i = 0; i < 8; i++) bs += sh[i];
    float inv = 1.f / bs;
    #pragma unroll
    for (int j = 0; j < 4; j++) {
        int s = tid + j * 256;
        if (j * 256 < len) {
            if (s < len) p[s] = rnd(v[j] * inv);
        }
    }
}

extern "C" void kernel_launch(void* const* d_in, const int* in_sizes, int n_in,
                              void* d_out, int out_size) {
    const float* x      = (const float*)d_in[0];
    const float* y      = (const float*)d_in[1];
    const float* Wqkv_x = (const float*)d_in[3];
    const float* bqkv_x = (const float*)d_in[4];
    const float* Wqkv_y = (const float*)d_in[5];
    const float* bqkv_y = (const float*)d_in[6];
    const float* w4x    = (const float*)d_in[7];
    const float* w4y    = (const float*)d_in[8];
    const float* w4xy   = (const float*)d_in[9];
    const float* Wgs    = (const float*)d_in[10];
    const float* bgs    = (const float*)d_in[11];
    const float* Wgc    = (const float*)d_in[12];
    const float* bgc    = (const float*)d_in[13];
    const float* Wp     = (const float*)d_in[14];
    const float* bp     = (const float*)d_in[15];
    float* out = (float*)d_out;

    cudaFuncSetAttribute(mma_nt, cudaFuncAttributeMaxDynamicSharedMemorySize, NT_SMEM);
    cudaFuncSetAttribute(mma_nn, cudaFuncAttributeMaxDynamicSharedMemorySize, NN_SMEM);

    float *p_qkv_x, *p_qkv_y, *p_catt1, *p_catt2, *p_catt, *p_x2y, *p_y2x,
          *p_big, *p_big2, *p_cval, *p_sval, *p_gs, *p_z;
    cudaGetSymbolAddress((void**)&p_qkv_x, g_qkv_x);
    cudaGetSymbolAddress((void**)&p_qkv_y, g_qkv_y);
    cudaGetSymbolAddress((void**)&p_catt1, g_catt1);
    cudaGetSymbolAddress((void**)&p_catt2, g_catt2);
    cudaGetSymbolAddress((void**)&p_catt, g_catt);
    cudaGetSymbolAddress((void**)&p_x2y, g_x2y);
    cudaGetSymbolAddress((void**)&p_y2x, g_y2x);
    cudaGetSymbolAddress((void**)&p_big, g_big);
    cudaGetSymbolAddress((void**)&p_big2, g_big2);
    cudaGetSymbolAddress((void**)&p_cval, g_cval);
    cudaGetSymbolAddress((void**)&p_sval, g_sval);
    cudaGetSymbolAddress((void**)&p_gs, g_gs);
    cudaGetSymbolAddress((void**)&p_z, g_z);

    const float scale = 0.125f;
    const float invSqrtM = 0.0625f;

    // 1-2. QKV projections (cvtIn, tf32-rounded outputs)
    mma_nn<<<dim3(C3c / 64, (Bc * Tc) / 128, 1), 256, NN_SMEM>>>(
        x, 0, 0, Cc, Wqkv_x, 0, 0, C3c, bqkv_x,
        p_qkv_x, 0, 0, C3c, Cc, 0, 0, 1, 1, nullptr, nullptr, nullptr, nullptr);
    mma_nn<<<dim3(C3c / 64, (Bc * Mc) / 128, 1), 256, NN_SMEM>>>(
        y, 0, 0, Cc, Wqkv_y, 0, 0, C3c, bqkv_y,
        p_qkv_y, 0, 0, C3c, Cc, 0, 0, 1, 1, nullptr, nullptr, nullptr, nullptr);
    // 3. dotw
    dotw<<<(BHc * Tc) / 8, 256>>>(p_qkv_x, w4x, Tc, p_catt1);
    // 4. satt NT (profiling slot) — prerounded inputs, cvtIn=0
    mma_nt<<<dim3(Tc / 128, Tc / 128, BHc), 256, NT_SMEM>>>(
        p_qkv_x, (long)Tc * C3c, 64, C3c,
        p_qkv_x + Cc, (long)Tc * C3c, 64, C3c,
        nullptr, nullptr, nullptr,
        p_big2, Tc, Tc, HDc, scale, 1, 0);
    // 5. dotw y
    dotw<<<(BHc * Mc) / 8, 256>>>(p_qkv_y, w4y, Mc, p_catt2);
    // 6. satt softmax (rounded output)
    softmax_causal<<<BHc * Tc, 256>>>(p_big2);
    // 7. sval = satt @ v_x (prerounded, cvtIn=0)
    mma_nn<<<dim3(1, Tc / 128, BHc), 256, NN_SMEM>>>(
        p_big2, 8L * Tc * Tc, (long)Tc * Tc, Tc,
        p_qkv_x + 2 * Cc, (long)Tc * C3c, 64, C3c, nullptr,
        p_sval, (long)Tc * Cc, 64, Cc, Tc, 0, 1, 0, 0, nullptr, nullptr, nullptr, nullptr);
    // 8. gs = sval @ Wgs + bgs (raw inputs -> cvtIn=1)
    mma_nn<<<dim3(Cc / 64, (Bc * Tc) / 128, 1), 256, NN_SMEM>>>(
        p_sval, 0, 0, Cc, Wgs, 0, 0, Cc, bgs,
        p_gs, 0, 0, Cc, Cc, 0, 0, 1, 0, nullptr, nullptr, nullptr, nullptr);

    // 9. catt (A scaled by w4xy -> cvt after scale; B prerounded, cvtIn=0)
    mma_nt<<<dim3(Mc / 128, Tc / 128, BHc), 256, NT_SMEM>>>(
        p_qkv_x, (long)Tc * C3c, 64, C3c,
        p_qkv_y + Cc, (long)Mc * C3c, 64, C3c,
        w4xy, p_catt1, p_catt2,
        p_catt, Tc, Mc, HDc, scale, 0, 0);
    // 10-11. softmaxes (rounded outputs)
    softmax_row256<<<BHc * Tc, 256>>>(p_catt, p_x2y);
    softmax_col<<<dim3(Mc / 64, BHc), 256>>>(p_catt, p_y2x);
    // 12. cval = x2y @ v_y (prerounded, cvtIn=0)
    mma_nn<<<dim3(1, Tc / 128, BHc), 256, NN_SMEM>>>(
        p_x2y, 8L * Tc * Mc, (long)Tc * Mc, Mc,
        p_qkv_y + 2 * Cc, (long)Mc * C3c, 64, C3c, nullptr,
        p_cval, (long)Tc * Cc, 64, Cc, Mc, 0, 0, 0, 0, nullptr, nullptr, nullptr, nullptr);
    // 13. chain scores (prerounded, cvtIn=0)
    mma_nt<<<dim3(Tc / 128, Tc / 128, BHc), 256, NT_SMEM>>>(
        p_x2y, 8L * Tc * Mc, (long)Tc * Mc, Mc,
        p_y2x, 8L * Tc * Mc, (long)Tc * Mc, Mc,
        nullptr, nullptr, nullptr,
        p_big, Tc, Tc, Mc, invSqrtM, 1, 0);
    // 14. chain softmax
    softmax_causal<<<BHc * Tc, 256>>>(p_big);
    // 15. cval += chain @ v_x + x (fused residual; prerounded, cvtIn=0)
    mma_nn<<<dim3(1, Tc / 128, BHc), 256, NN_SMEM>>>(
        p_big, 8L * Tc * Tc, (long)Tc * Tc, Tc,
        p_qkv_x + 2 * Cc, (long)Tc * C3c, 64, C3c, nullptr,
        p_cval, (long)Tc * Cc, 64, Cc, Tc, 1, 1, 0, 0, x, nullptr, nullptr, nullptr);

    // 16. z = sigmoid(gs)*cval + sigmoid(cval@Wgc+bgc)*sval (cvtIn=1)
    mma_nn<<<dim3(Cc / 64, (Bc * Tc) / 128, 1), 256, NN_SMEM>>>(
        p_cval, 0, 0, Cc, Wgc, 0, 0, Cc, bgc,
        p_z, 0, 0, Cc, Cc, 0, 0, 1, 0, nullptr, p_gs, p_cval, p_sval);

    // 17. out = z @ Wp + bp (cvtIn=1)
    mma_nn<<<dim3(Cc / 64, (Bc * Tc) / 128, 1), 256, NN_SMEM>>>(
        p_z, 0, 0, Cc, Wp, 0, 0, Cc, bp,
        out, 0, 0, Cc, Cc, 0, 0, 1, 0, nullptr, nullptr, nullptr, nullptr);
}

// round 9
// speedup vs baseline: 1.0457x; 1.0139x over previous
#include <cuda_runtime.h>
#include <cuda_bf16.h>
#include <math.h>

#define Bc 4
#define Tc 1024
#define Mc 256
#define Cc 512
#define Hc 8
#define HDc 64
#define C3c 1536
#define BHc 32

// ---------------- scratch ----------------
__device__ float g_qkv_x[Bc * Tc * C3c];
__device__ float g_qkv_y[Bc * Mc * C3c];
__device__ float g_catt1[BHc * Tc];
__device__ float g_catt2[BHc * Mc];
__device__ float g_catt[(long)BHc * Tc * Mc];
__device__ float g_x2y[(long)BHc * Tc * Mc];
__device__ float g_y2x[(long)BHc * Tc * Mc];
__device__ float g_big[(long)BHc * Tc * Tc];    // chain scores
__device__ float g_big2[(long)BHc * Tc * Tc];   // satt scores
__device__ float g_cval[Bc * Tc * Cc];
__device__ float g_sval[Bc * Tc * Cc];
__device__ float g_gs[Bc * Tc * Cc];
__device__ float g_z[Bc * Tc * Cc];

// ---------------- helpers ----------------
__device__ __forceinline__ float rnd(float f) {
    unsigned u;
    asm("cvt.rna.tf32.f32 %0, %1;" : "=r"(u) : "f"(f));
    return __uint_as_float(u);
}
__device__ __forceinline__ unsigned f2tf(float f) {
    unsigned u;
    asm("cvt.rna.tf32.f32 %0, %1;" : "=r"(u) : "f"(f));
    return u;
}
__device__ __forceinline__ void mma8(float* d, const unsigned* a, const unsigned* b) {
    asm volatile(
        "mma.sync.aligned.m16n8k8.row.col.f32.tf32.tf32.f32 "
        "{%0,%1,%2,%3},{%4,%5,%6,%7},{%8,%9},{%0,%1,%2,%3};"
        : "+f"(d[0]), "+f"(d[1]), "+f"(d[2]), "+f"(d[3])
        : "r"(a[0]), "r"(a[1]), "r"(a[2]), "r"(a[3]), "r"(b[0]), "r"(b[1]));
}
__device__ __forceinline__ void cpa16(unsigned dst, const void* src) {
    asm volatile("cp.async.cg.shared.global [%0], [%1], 16;" :: "r"(dst), "l"(src));
}
__device__ __forceinline__ void cpcommit() { asm volatile("cp.async.commit_group;"); }
__device__ __forceinline__ void ldsm4(unsigned& r0, unsigned& r1, unsigned& r2, unsigned& r3,
                                      unsigned addr) {
    asm volatile("ldmatrix.sync.aligned.m8n8.x4.shared.b16 {%0,%1,%2,%3},[%4];"
                 : "=r"(r0), "=r"(r1), "=r"(r2), "=r"(r3) : "r"(addr));
}

// 3-stage pipelines
#define NT_STG (128 * 36)                       // words per array per stage
#define NT_SMEM (6 * NT_STG * 4)                // 3 stages x (A+B) = 110592 B
#define NN_ASTG (128 * 36)
#define NN_BSTG (32 * 68)
#define NN_SMEM ((3 * NN_ASTG + 3 * NN_BSTG) * 4)  // 81408 B

extern __shared__ unsigned smem_u[];

// ================= NT GEMM: C = alpha * A(I,K) @ B(J,K)^T (+rb +cb) =================
// cvtIn=0 requires tf32-prerounded inputs. 3-stage cp.async, 1 sync/iter.
__global__ void __launch_bounds__(256, 2)
mma_nt(const float* __restrict__ A, long Abs, long Ahs, int ldA,
       const float* __restrict__ Bp, long Bbs, long Bhs, int ldB,
       const float* __restrict__ scaleA,
       const float* __restrict__ rbias, const float* __restrict__ cbias,
       float* __restrict__ Cp, int I, int J, int K, float alpha, int causal,
       int cvtIn) {
    const int bh = blockIdx.z, b = bh >> 3, h = bh & 7;
    const int j0 = blockIdx.x * 128;
    const int i0 = causal ? (I - 128 - blockIdx.y * 128) : blockIdx.y * 128;
    if (causal && j0 > i0) return;
    unsigned* As = smem_u;                  // [3][128][36]
    unsigned* Bs = smem_u + 3 * NT_STG;     // [3][128][36]
    const unsigned sA0 = (unsigned)__cvta_generic_to_shared(As);
    const unsigned sB0 = (unsigned)__cvta_generic_to_shared(Bs);
    const float* Ab = A + (long)b * Abs + (long)h * Ahs + (long)i0 * ldA;
    const float* Bb = Bp + (long)b * Bbs + (long)h * Bhs + (long)j0 * ldB;

    const int tid = threadIdx.x, wid = tid >> 5, lane = tid & 31;
    const int g = lane >> 2, t = lane & 3;
    const int wm = (wid & 1) * 64, wn = (wid >> 1) * 32;
    const int lrow = lane & 15, lblk = lane >> 4;
    const int ldrow = tid >> 3, ldc4 = (tid & 7) * 4;

    float sreg[16];
    const bool hasS = (scaleA != nullptr);
    if (hasS) {
        const float* sA = scaleA + h * HDc;
        #pragma unroll
        for (int j = 0; j < 8; j++) {
            sreg[2 * j] = sA[8 * j + t];
            sreg[2 * j + 1] = sA[8 * j + t + 4];
        }
    }

    const int niter = K / 32;
    float acc[4][4][4] = {};

    // prologue: stages 0,1
    #pragma unroll
    for (int s = 0; s < 2; s++) {
        if (s < niter) {
            const int k0 = s * 32;
            #pragma unroll
            for (int w = 0; w < 4; w++) {
                int r = ldrow + w * 32;
                cpa16(sA0 + (s * NT_STG + r * 36 + ldc4) * 4, Ab + (long)r * ldA + k0 + ldc4);
                cpa16(sB0 + (s * NT_STG + r * 36 + ldc4) * 4, Bb + (long)r * ldB + k0 + ldc4);
            }
            cpcommit();
        }
    }

    int slot = 0, pslot = 2 >= 3 ? 2 - 3 : 2;   // compute slot, prefetch slot (=2)
    pslot = 2;
    for (int it = 0; it < niter; it++) {
        if (it < niter - 1) asm volatile("cp.async.wait_group 1;");
        else                asm volatile("cp.async.wait_group 0;");
        __syncthreads();

        const unsigned aBase = sA0 + slot * NT_STG * 4;
        const unsigned bBase = sB0 + slot * NT_STG * 4;
        #pragma unroll
        for (int kk = 0; kk < 4; kk++) {
            const int kb = kk * 8 + 4 * lblk;
            unsigned a[4][4], bb[4][2];
            #pragma unroll
            for (int mf = 0; mf < 4; mf++)
                ldsm4(a[mf][0], a[mf][1], a[mf][2], a[mf][3],
                      aBase + ((wm + mf * 16 + lrow) * 36 + kb) * 4);
            #pragma unroll
            for (int p = 0; p < 2; p++) {
                unsigned r0, r1, r2, r3;
                ldsm4(r0, r1, r2, r3, bBase + ((wn + p * 16 + lrow) * 36 + kb) * 4);
                bb[2 * p][0] = r0;
                bb[2 * p][1] = r2;
                bb[2 * p + 1][0] = r1;
                bb[2 * p + 1][1] = r3;
            }
            if (cvtIn) {
                #pragma unroll
                for (int nf = 0; nf < 4; nf++) {
                    bb[nf][0] = f2tf(__uint_as_float(bb[nf][0]));
                    bb[nf][1] = f2tf(__uint_as_float(bb[nf][1]));
                }
            }
            if (hasS) {
                const int j = it * 4 + kk;
                const float slo = sreg[2 * j], shi = sreg[2 * j + 1];
                #pragma unroll
                for (int mf = 0; mf < 4; mf++) {
                    a[mf][0] = f2tf(__uint_as_float(a[mf][0]) * slo);
                    a[mf][1] = f2tf(__uint_as_float(a[mf][1]) * slo);
                    a[mf][2] = f2tf(__uint_as_float(a[mf][2]) * shi);
                    a[mf][3] = f2tf(__uint_as_float(a[mf][3]) * shi);
                }
            } else if (cvtIn) {
                #pragma unroll
                for (int mf = 0; mf < 4; mf++)
                    #pragma unroll
                    for (int q = 0; q < 4; q++)
                        a[mf][q] = f2tf(__uint_as_float(a[mf][q]));
            }
            #pragma unroll
            for (int mf = 0; mf < 4; mf++)
                #pragma unroll
                for (int nf = 0; nf < 4; nf++) mma8(acc[mf][nf], a[mf], bb[nf]);
        }

        if (it + 2 < niter) {
            const int k0 = (it + 2) * 32;
            #pragma unroll
            for (int w = 0; w < 4; w++) {
                int r = ldrow + w * 32;
                cpa16(sA0 + (pslot * NT_STG + r * 36 + ldc4) * 4,
                      Ab + (long)r * ldA + k0 + ldc4);
                cpa16(sB0 + (pslot * NT_STG + r * 36 + ldc4) * 4,
                      Bb + (long)r * ldB + k0 + ldc4);
            }
            cpcommit();
        }
        slot = (slot == 2) ? 0 : slot + 1;
        pslot = (pslot == 2) ? 0 : pslot + 1;
    }

    float* Cb = Cp + (long)bh * I * J;
    const float* rb = rbias ? rbias + (long)bh * I : nullptr;
    const float* cb = cbias ? cbias + (long)bh * J : nullptr;
    #pragma unroll
    for (int mf = 0; mf < 4; mf++)
        #pragma unroll
        for (int nf = 0; nf < 4; nf++) {
            int r0 = i0 + wm + mf * 16 + g;
            int c0 = j0 + wn + nf * 8 + 2 * t;
            #pragma unroll
            for (int ep = 0; ep < 2; ep++) {
                int rr = r0 + ep * 8;
                float v0 = acc[mf][nf][2 * ep] * alpha;
                float v1 = acc[mf][nf][2 * ep + 1] * alpha;
                if (rb) { v0 += rb[rr]; v1 += rb[rr]; }
                if (cb) { v0 += cb[c0]; v1 += cb[c0 + 1]; }
                *(float2*)&Cb[(long)rr * J + c0] = make_float2(v0, v1);
            }
        }
}

// ================= NN GEMM with fused epilogues (3-stage) =================
__global__ void __launch_bounds__(256, 2)
mma_nn(const float* __restrict__ A, long Abs, long Ahs, int ldA,
       const float* __restrict__ Bp, long Bbs, long Bhs, int ldB,
       const float* __restrict__ bias,
       float* __restrict__ Cp, long Cbs, long Chs, int ldC,
       int K, int accumulate, int trailK, int cvtIn, int roundOut,
       const float* __restrict__ addV,
       const float* __restrict__ gGs, const float* __restrict__ gA2,
       const float* __restrict__ gB2) {
    const int bh = blockIdx.z, b = bh >> 3, h = bh & 7;
    const int col0 = blockIdx.x * 64;
    const int i0 = trailK ? ((gridDim.y - 1 - blockIdx.y) * 128) : blockIdx.y * 128;
    unsigned* As = smem_u;                    // [3][128][36]
    unsigned* Bs = smem_u + 3 * NN_ASTG;      // [3][32][68]
    const unsigned sA0 = (unsigned)__cvta_generic_to_shared(As);
    const unsigned sB0 = (unsigned)__cvta_generic_to_shared(Bs);
    const float* Ab = A + (long)b * Abs + (long)h * Ahs + (long)i0 * ldA;
    const float* Bb = Bp + (long)b * Bbs + (long)h * Bhs + col0;

    const int tid = threadIdx.x, wid = tid >> 5, lane = tid & 31;
    const int g = lane >> 2, t = lane & 3;
    const int wm = (wid & 1) * 64, wn = (wid >> 1) * 16;
    const int lrow = lane & 15, lblk = lane >> 4;
    const int ldrow = tid >> 3, ldc4 = (tid & 7) * 4;

    const int Keff = trailK ? min(K, i0 + 128) : K;
    const int niter = Keff / 32;
    float acc[4][2][4] = {};

    #pragma unroll
    for (int s = 0; s < 2; s++) {
        if (s < niter) {
            const int k0 = s * 32;
            #pragma unroll
            for (int w = 0; w < 4; w++) {
                int r = ldrow + w * 32;
                cpa16(sA0 + (s * NN_ASTG + r * 36 + ldc4) * 4, Ab + (long)r * ldA + k0 + ldc4);
            }
            #pragma unroll
            for (int w = 0; w < 2; w++) {
                int li = tid + w * 256;
                int r = li >> 4, c4 = (li & 15) * 4;
                cpa16(sB0 + (s * NN_BSTG + r * 68 + c4) * 4, Bb + (long)(k0 + r) * ldB + c4);
            }
            cpcommit();
        }
    }

    int slot = 0, pslot = 2;
    for (int it = 0; it < niter; it++) {
        if (it < niter - 1) asm volatile("cp.async.wait_group 1;");
        else                asm volatile("cp.async.wait_group 0;");
        __syncthreads();

        const unsigned aBase = sA0 + slot * NN_ASTG * 4;
        const unsigned* Bbuf = Bs + slot * NN_BSTG;
        #pragma unroll
        for (int kk = 0; kk < 4; kk++) {
            const int kb8 = kk * 8;
            unsigned a[4][4], bb[2][2];
            #pragma unroll
            for (int mf = 0; mf < 4; mf++) {
                ldsm4(a[mf][0], a[mf][1], a[mf][2], a[mf][3],
                      aBase + ((wm + mf * 16 + lrow) * 36 + kb8 + 4 * lblk) * 4);
                if (cvtIn) {
                    #pragma unroll
                    for (int q = 0; q < 4; q++)
                        a[mf][q] = f2tf(__uint_as_float(a[mf][q]));
                }
            }
            #pragma unroll
            for (int nf = 0; nf < 2; nf++) {
                bb[nf][0] = Bbuf[(kb8 + t) * 68 + wn + nf * 8 + g];
                bb[nf][1] = Bbuf[(kb8 + t + 4) * 68 + wn + nf * 8 + g];
                if (cvtIn) {
                    bb[nf][0] = f2tf(__uint_as_float(bb[nf][0]));
                    bb[nf][1] = f2tf(__uint_as_float(bb[nf][1]));
                }
            }
            #pragma unroll
            for (int mf = 0; mf < 4; mf++)
                #pragma unroll
                for (int nf = 0; nf < 2; nf++) mma8(acc[mf][nf], a[mf], bb[nf]);
        }

        if (it + 2 < niter) {
            const int k0 = (it + 2) * 32;
            #pragma unroll
            for (int w = 0; w < 4; w++) {
                int r = ldrow + w * 32;
                cpa16(sA0 + (pslot * NN_ASTG + r * 36 + ldc4) * 4,
                      Ab + (long)r * ldA + k0 + ldc4);
            }
            #pragma unroll
            for (int w = 0; w < 2; w++) {
                int li = tid + w * 256;
                int r = li >> 4, c4 = (li & 15) * 4;
                cpa16(sB0 + (pslot * NN_BSTG + r * 68 + c4) * 4,
                      Bb + (long)(k0 + r) * ldB + c4);
            }
            cpcommit();
        }
        slot = (slot == 2) ? 0 : slot + 1;
        pslot = (pslot == 2) ? 0 : pslot + 1;
    }

    const long baseoff = (long)b * Cbs + (long)h * Chs + (long)i0 * ldC + col0;
    float* Cb = Cp + baseoff;
    const float* Xb = addV ? addV + baseoff : nullptr;
    const float* Gs = gGs ? gGs + baseoff : nullptr;
    const float* A2 = gA2 ? gA2 + baseoff : nullptr;
    const float* B2 = gB2 ? gB2 + baseoff : nullptr;
    #pragma unroll
    for (int mf = 0; mf < 4; mf++)
        #pragma unroll
        for (int nf = 0; nf < 2; nf++) {
            int r0 = wm + mf * 16 + g;
            int c0 = wn + nf * 8 + 2 * t;
            #pragma unroll
            for (int e = 0; e < 4; e++) {
                int rr = r0 + (e >> 1) * 8;
                int cc = c0 + (e & 1);
                float v = acc[mf][nf][e];
                if (bias) v += bias[col0 + cc];
                long off = (long)rr * ldC + cc;
                if (accumulate) v += Cb[off];
                if (Xb) v += Xb[off];
                if (Gs) {
                    float sg = 1.f / (1.f + expf(-Gs[off]));
                    float cg = 1.f / (1.f + expf(-v));
                    v = sg * A2[off] + cg * B2[off];
                }
                if (roundOut) v = rnd(v);
                Cb[off] = v;
            }
        }
}

// -------- catt1/catt2 dot products --------
__global__ void dotw(const float* __restrict__ qkv, const float* __restrict__ w,
                     int rows, float* __restrict__ out) {
    int gw = (blockIdx.x * blockDim.x + threadIdx.x) >> 5;
    int lane = threadIdx.x & 31;
    if (gw >= BHc * rows) return;
    int bh = gw / rows, r = gw % rows;
    int b = bh >> 3, h = bh & 7;
    const float* p = qkv + (long)(b * rows + r) * C3c + h * HDc;
    float s = p[lane] * w[h * HDc + lane] + p[lane + 32] * w[h * HDc + lane + 32];
    #pragma unroll
    for (int o = 16; o; o >>= 1) s += __shfl_xor_sync(0xffffffffu, s, o);
    if (lane == 0) out[gw] = s;
}

// -------- row softmax over M=256 (tf32-rounded output) --------
__global__ void softmax_row256(const float* __restrict__ in, float* __restrict__ out) {
    long row = blockIdx.x;
    int tid = threadIdx.x;
    __shared__ float sh[8];
    float v = in[row * 256 + tid];
    float m = v;
    #pragma unroll
    for (int o = 16; o; o >>= 1) m = fmaxf(m, __shfl_xor_sync(0xffffffffu, m, o));
    if ((tid & 31) == 0) sh[tid >> 5] = m;
    __syncthreads();
    float bm = sh[0];
    #pragma unroll
    for (int i = 1; i < 8; i++) bm = fmaxf(bm, sh[i]);
    __syncthreads();
    float e = expf(v - bm);
    float s = e;
    #pragma unroll
    for (int o = 16; o; o >>= 1) s += __shfl_xor_sync(0xffffffffu, s, o);
    if ((tid & 31) == 0) sh[tid >> 5] = s;
    __syncthreads();
    float bs = 0.f;
    #pragma unroll
    for (int i = 0; i < 8; i++) bs += sh[i];
    out[row * 256 + tid] = rnd(e / bs);
}

// -------- column softmax over T=1024 (tf32-rounded output) --------
__global__ void softmax_col(const float* __restrict__ in, float* __restrict__ out) {
    int bh = blockIdx.y;
    int mx = threadIdx.x & 63;
    int ty = threadIdx.x >> 6;
    int m = blockIdx.x * 64 + mx;
    const float* base = in + (long)bh * Tc * Mc + m;
    __shared__ float red[256];
    __shared__ float cstat[64];
    float acc = -3.4e38f;
    for (int t = ty; t < Tc; t += 4) acc = fmaxf(acc, base[(long)t * Mc]);
    red[threadIdx.x] = acc;
    __syncthreads();
    if (ty == 0)
        cstat[mx] = fmaxf(fmaxf(red[mx], red[64 + mx]), fmaxf(red[128 + mx], red[192 + mx]));
    __syncthreads();
    float cm = cstat[mx];
    __syncthreads();
    float s = 0.f;
    for (int t = ty; t < Tc; t += 4) s += expf(base[(long)t * Mc] - cm);
    red[threadIdx.x] = s;
    __syncthreads();
    if (ty == 0) cstat[mx] = red[mx] + red[64 + mx] + red[128 + mx] + red[192 + mx];
    __syncthreads();
    float inv = 1.f / cstat[mx];
    float* ob = out + (long)bh * Tc * Mc + m;
    for (int t = ty; t < Tc; t += 4) ob[(long)t * Mc] = rnd(expf(base[(long)t * Mc] - cm) * inv);
}

// -------- causal row softmax, trimmed, static unroll --------
__global__ void softmax_causal(float* __restrict__ buf) {
    long row = blockIdx.x;
    int t = (int)(row & 1023);
    const int len = ((t >> 7) + 1) << 7;
    float* p = buf + row * 1024;
    int tid = threadIdx.x;
    __shared__ float sh[8];
    float v[4];
    float m = -3.4e38f;
    #pragma unroll
    for (int j = 0; j < 4; j++) {
        int s = tid + j * 256;
        float val = -3.4e38f;
        if (j * 256 < len) {
            if (s <= t) val = p[s];
        }
        v[j] = val;
        m = fmaxf(m, val);
    }
    #pragma unroll
    for (int o = 16; o; o >>= 1) m = fmaxf(m, __shfl_xor_sync(0xffffffffu, m, o));
    if ((tid & 31) == 0) sh[tid >> 5] = m;
    __syncthreads();
    float bm = sh[0];
    #pragma unroll
    for (int i = 1; i < 8; i++) bm = fmaxf(bm, sh[i]);
    __syncthreads();
    float sum = 0.f;
    #pragma unroll
    for (int j = 0; j < 4; j++) {
        int s = tid + j * 256;
        float e = 0.f;
        if (j * 256 < len) {
            if (s <= t) e = expf(v[j] - bm);
        }
        v[j] = e;
        sum += e;
    }
    #pragma unroll
    for (int o = 16; o; o >>= 1) sum += __shfl_xor_sync(0xffffffffu, sum, o);
    if ((tid & 31) == 0) sh[tid >> 5] = sum;
    __syncthreads();
    float bs = 0.f;
    #pragma unroll
    for (int i = 0; i < 8; i++) bs += sh[i];
    float inv = 1.f / bs;
    #pragma unroll
    for (int j = 0; j < 4; j++) {
        int s = tid + j * 256;
        if (j * 256 < len) {
            if (s < len) p[s] = rnd(v[j] * inv);
        }
    }
}

extern "C" void kernel_launch(void* const* d_in, const int* in_sizes, int n_in,
                              void* d_out, int out_size) {
    const float* x      = (const float*)d_in[0];
    const float* y      = (const float*)d_in[1];
    const float* Wqkv_x = (const float*)d_in[3];
    const float* bqkv_x = (const float*)d_in[4];
    const float* Wqkv_y = (const float*)d_in[5];
    const float* bqkv_y = (const float*)d_in[6];
    const float* w4x    = (const float*)d_in[7];
    const float* w4y    = (const float*)d_in[8];
    const float* w4xy   = (const float*)d_in[9];
    const float* Wgs    = (const float*)d_in[10];
    const float* bgs    = (const float*)d_in[11];
    const float* Wgc    = (const float*)d_in[12];
    const float* bgc    = (const float*)d_in[13];
    const float* Wp     = (const float*)d_in[14];
    const float* bp     = (const float*)d_in[15];
    float* out = (float*)d_out;

    cudaFuncSetAttribute(mma_nt, cudaFuncAttributeMaxDynamicSharedMemorySize, NT_SMEM);
    cudaFuncSetAttribute(mma_nn, cudaFuncAttributeMaxDynamicSharedMemorySize, NN_SMEM);

    float *p_qkv_x, *p_qkv_y, *p_catt1, *p_catt2, *p_catt, *p_x2y, *p_y2x,
          *p_big, *p_big2, *p_cval, *p_sval, *p_gs, *p_z;
    cudaGetSymbolAddress((void**)&p_qkv_x, g_qkv_x);
    cudaGetSymbolAddress((void**)&p_qkv_y, g_qkv_y);
    cudaGetSymbolAddress((void**)&p_catt1, g_catt1);
    cudaGetSymbolAddress((void**)&p_catt2, g_catt2);
    cudaGetSymbolAddress((void**)&p_catt, g_catt);
    cudaGetSymbolAddress((void**)&p_x2y, g_x2y);
    cudaGetSymbolAddress((void**)&p_y2x, g_y2x);
    cudaGetSymbolAddress((void**)&p_big, g_big);
    cudaGetSymbolAddress((void**)&p_big2, g_big2);
    cudaGetSymbolAddress((void**)&p_cval, g_cval);
    cudaGetSymbolAddress((void**)&p_sval, g_sval);
    cudaGetSymbolAddress((void**)&p_gs, g_gs);
    cudaGetSymbolAddress((void**)&p_z, g_z);

    const float scale = 0.125f;
    const float invSqrtM = 0.0625f;

    // 1-2. QKV projections (cvtIn, tf32-rounded outputs)
    mma_nn<<<dim3(C3c / 64, (Bc * Tc) / 128, 1), 256, NN_SMEM>>>(
        x, 0, 0, Cc, Wqkv_x, 0, 0, C3c, bqkv_x,
        p_qkv_x, 0, 0, C3c, Cc, 0, 0, 1, 1, nullptr, nullptr, nullptr, nullptr);
    mma_nn<<<dim3(C3c / 64, (Bc * Mc) / 128, 1), 256, NN_SMEM>>>(
        y, 0, 0, Cc, Wqkv_y, 0, 0, C3c, bqkv_y,
        p_qkv_y, 0, 0, C3c, Cc, 0, 0, 1, 1, nullptr, nullptr, nullptr, nullptr);
    // 3. dotw x
    dotw<<<(BHc * Tc) / 8, 256>>>(p_qkv_x, w4x, Tc, p_catt1);
    // 4. satt NT (profiling slot)
    mma_nt<<<dim3(Tc / 128, Tc / 128, BHc), 256, NT_SMEM>>>(
        p_qkv_x, (long)Tc * C3c, 64, C3c,
        p_qkv_x + Cc, (long)Tc * C3c, 64, C3c,
        nullptr, nullptr, nullptr,
        p_big2, Tc, Tc, HDc, scale, 1, 0);
    // 5. dotw y
    dotw<<<(BHc * Mc) / 8, 256>>>(p_qkv_y, w4y, Mc, p_catt2);
    // 6. satt softmax
    softmax_causal<<<BHc * Tc, 256>>>(p_big2);
    // 7. sval = satt @ v_x
    mma_nn<<<dim3(1, Tc / 128, BHc), 256, NN_SMEM>>>(
        p_big2, 8L * Tc * Tc, (long)Tc * Tc, Tc,
        p_qkv_x + 2 * Cc, (long)Tc * C3c, 64, C3c, nullptr,
        p_sval, (long)Tc * Cc, 64, Cc, Tc, 0, 1, 0, 0, nullptr, nullptr, nullptr, nullptr);
    // 8. gs = sval @ Wgs + bgs
    mma_nn<<<dim3(Cc / 64, (Bc * Tc) / 128, 1), 256, NN_SMEM>>>(
        p_sval, 0, 0, Cc, Wgs, 0, 0, Cc, bgs,
        p_gs, 0, 0, Cc, Cc, 0, 0, 1, 0, nullptr, nullptr, nullptr, nullptr);

    // 9. catt
    mma_nt<<<dim3(Mc / 128, Tc / 128, BHc), 256, NT_SMEM>>>(
        p_qkv_x, (long)Tc * C3c, 64, C3c,
        p_qkv_y + Cc, (long)Mc * C3c, 64, C3c,
        w4xy, p_catt1, p_catt2,
        p_catt, Tc, Mc, HDc, scale, 0, 0);
    // 10-11. softmaxes
    softmax_row256<<<BHc * Tc, 256>>>(p_catt, p_x2y);
    softmax_col<<<dim3(Mc / 64, BHc), 256>>>(p_catt, p_y2x);
    // 12. cval = x2y @ v_y
    mma_nn<<<dim3(1, Tc / 128, BHc), 256, NN_SMEM>>>(
        p_x2y, 8L * Tc * Mc, (long)Tc * Mc, Mc,
        p_qkv_y + 2 * Cc, (long)Mc * C3c, 64, C3c, nullptr,
        p_cval, (long)Tc * Cc, 64, Cc, Mc, 0, 0, 0, 0, nullptr, nullptr, nullptr, nullptr);
    // 13. chain scores
    mma_nt<<<dim3(Tc / 128, Tc / 128, BHc), 256, NT_SMEM>>>(
        p_x2y, 8L * Tc * Mc, (long)Tc * Mc, Mc,
        p_y2x, 8L * Tc * Mc, (long)Tc * Mc, Mc,
        nullptr, nullptr, nullptr,
        p_big, Tc, Tc, Mc, invSqrtM, 1, 0);
    // 14. chain softmax
    softmax_causal<<<BHc * Tc, 256>>>(p_big);
    // 15. cval += chain @ v_x + x
    mma_nn<<<dim3(1, Tc / 128, BHc), 256, NN_SMEM>>>(
        p_big, 8L * Tc * Tc, (long)Tc * Tc, Tc,
        p_qkv_x + 2 * Cc, (long)Tc * C3c, 64, C3c, nullptr,
        p_cval, (long)Tc * Cc, 64, Cc, Tc, 1, 1, 0, 0, x, nullptr, nullptr, nullptr);

    // 16. z = sigmoid(gs)*cval + sigmoid(cval@Wgc+bgc)*sval
    mma_nn<<<dim3(Cc / 64, (Bc * Tc) / 128, 1), 256, NN_SMEM>>>(
        p_cval, 0, 0, Cc, Wgc, 0, 0, Cc, bgc,
        p_z, 0, 0, Cc, Cc, 0, 0, 1, 0, nullptr, p_gs, p_cval, p_sval);

    // 17. out = z @ Wp + bp
    mma_nn<<<dim3(Cc / 64, (Bc * Tc) / 128, 1), 256, NN_SMEM>>>(
        p_z, 0, 0, Cc, Wp, 0, 0, Cc, bp,
        out, 0, 0, Cc, Cc, 0, 0, 1, 0, nullptr, nullptr, nullptr, nullptr);
}

// round 10
// speedup vs baseline: 1.0941x; 1.0463x over previous
#include <cuda_runtime.h>
#include <cuda_bf16.h>
#include <math.h>

#define Bc 4
#define Tc 1024
#define Mc 256
#define Cc 512
#define Hc 8
#define HDc 64
#define C3c 1536
#define BHc 32

// ---------------- scratch ----------------
__device__ float g_qkv_x[Bc * Tc * C3c];
__device__ float g_qkv_y[Bc * Mc * C3c];
__device__ float g_catt1[BHc * Tc];
__device__ float g_catt2[BHc * Mc];
__device__ float g_catt[(long)BHc * Tc * Mc];
__device__ float g_x2y[(long)BHc * Tc * Mc];
__device__ __nv_bfloat16 g_x2yh[(long)BHc * Tc * Mc];
__device__ __nv_bfloat16 g_y2xh[(long)BHc * Tc * Mc];
__device__ float g_big[(long)BHc * Tc * Tc];    // chain scores
__device__ float g_big2[(long)BHc * Tc * Tc];   // satt scores
__device__ float g_cval[Bc * Tc * Cc];
__device__ float g_sval[Bc * Tc * Cc];
__device__ float g_gs[Bc * Tc * Cc];
__device__ float g_z[Bc * Tc * Cc];

// ---------------- helpers ----------------
__device__ __forceinline__ float rnd(float f) {
    unsigned u;
    asm("cvt.rna.tf32.f32 %0, %1;" : "=r"(u) : "f"(f));
    return __uint_as_float(u);
}
__device__ __forceinline__ unsigned f2tf(float f) {
    unsigned u;
    asm("cvt.rna.tf32.f32 %0, %1;" : "=r"(u) : "f"(f));
    return u;
}
__device__ __forceinline__ void mma8(float* d, const unsigned* a, const unsigned* b) {
    asm volatile(
        "mma.sync.aligned.m16n8k8.row.col.f32.tf32.tf32.f32 "
        "{%0,%1,%2,%3},{%4,%5,%6,%7},{%8,%9},{%0,%1,%2,%3};"
        : "+f"(d[0]), "+f"(d[1]), "+f"(d[2]), "+f"(d[3])
        : "r"(a[0]), "r"(a[1]), "r"(a[2]), "r"(a[3]), "r"(b[0]), "r"(b[1]));
}
__device__ __forceinline__ void mma16bf(float* d, const unsigned* a, const unsigned* b) {
    asm volatile(
        "mma.sync.aligned.m16n8k16.row.col.f32.bf16.bf16.f32 "
        "{%0,%1,%2,%3},{%4,%5,%6,%7},{%8,%9},{%0,%1,%2,%3};"
        : "+f"(d[0]), "+f"(d[1]), "+f"(d[2]), "+f"(d[3])
        : "r"(a[0]), "r"(a[1]), "r"(a[2]), "r"(a[3]), "r"(b[0]), "r"(b[1]));
}
__device__ __forceinline__ void cpa16(unsigned dst, const void* src) {
    asm volatile("cp.async.cg.shared.global [%0], [%1], 16;" :: "r"(dst), "l"(src));
}
__device__ __forceinline__ void cpcommit() { asm volatile("cp.async.commit_group;"); }
__device__ __forceinline__ void ldsm4(unsigned& r0, unsigned& r1, unsigned& r2, unsigned& r3,
                                      unsigned addr) {
    asm volatile("ldmatrix.sync.aligned.m8n8.x4.shared.b16 {%0,%1,%2,%3},[%4];"
                 : "=r"(r0), "=r"(r1), "=r"(r2), "=r"(r3) : "r"(addr));
}

// 3-stage pipelines
#define NT_STG (128 * 36)
#define NT_SMEM (6 * NT_STG * 4)                   // 110592 B
#define NN_ASTG (128 * 36)
#define NN_BSTG (32 * 68)
#define NN_SMEM ((3 * NN_ASTG + 3 * NN_BSTG) * 4)  // 81408 B
#define BF_STG (128 * 72)                          // halfs per array per stage
#define BF_SMEM (6 * BF_STG * 2)                   // 110592 B

extern __shared__ unsigned smem_u[];

// ================= NT GEMM (tf32): C = alpha*A@B^T (+rb +cb) =================
__global__ void __launch_bounds__(256, 2)
mma_nt(const float* __restrict__ A, long Abs, long Ahs, int ldA,
       const float* __restrict__ Bp, long Bbs, long Bhs, int ldB,
       const float* __restrict__ scaleA,
       const float* __restrict__ rbias, const float* __restrict__ cbias,
       float* __restrict__ Cp, int I, int J, int K, float alpha, int causal,
       int cvtIn) {
    const int bh = blockIdx.z, b = bh >> 3, h = bh & 7;
    const int j0 = blockIdx.x * 128;
    const int i0 = causal ? (I - 128 - blockIdx.y * 128) : blockIdx.y * 128;
    if (causal && j0 > i0) return;
    unsigned* As = smem_u;
    unsigned* Bs = smem_u + 3 * NT_STG;
    const unsigned sA0 = (unsigned)__cvta_generic_to_shared(As);
    const unsigned sB0 = (unsigned)__cvta_generic_to_shared(Bs);
    const float* Ab = A + (long)b * Abs + (long)h * Ahs + (long)i0 * ldA;
    const float* Bb = Bp + (long)b * Bbs + (long)h * Bhs + (long)j0 * ldB;

    const int tid = threadIdx.x, wid = tid >> 5, lane = tid & 31;
    const int g = lane >> 2, t = lane & 3;
    const int wm = (wid & 1) * 64, wn = (wid >> 1) * 32;
    const int lrow = lane & 15, lblk = lane >> 4;
    const int ldrow = tid >> 3, ldc4 = (tid & 7) * 4;

    float sreg[16];
    const bool hasS = (scaleA != nullptr);
    if (hasS) {
        const float* sA = scaleA + h * HDc;
        #pragma unroll
        for (int j = 0; j < 8; j++) {
            sreg[2 * j] = sA[8 * j + t];
            sreg[2 * j + 1] = sA[8 * j + t + 4];
        }
    }

    const int niter = K / 32;
    float acc[4][4][4] = {};

    #pragma unroll
    for (int s = 0; s < 2; s++) {
        if (s < niter) {
            const int k0 = s * 32;
            #pragma unroll
            for (int w = 0; w < 4; w++) {
                int r = ldrow + w * 32;
                cpa16(sA0 + (s * NT_STG + r * 36 + ldc4) * 4, Ab + (long)r * ldA + k0 + ldc4);
                cpa16(sB0 + (s * NT_STG + r * 36 + ldc4) * 4, Bb + (long)r * ldB + k0 + ldc4);
            }
            cpcommit();
        }
    }

    int slot = 0, pslot = 2;
    for (int it = 0; it < niter; it++) {
        if (it < niter - 1) asm volatile("cp.async.wait_group 1;");
        else                asm volatile("cp.async.wait_group 0;");
        __syncthreads();

        const unsigned aBase = sA0 + slot * NT_STG * 4;
        const unsigned bBase = sB0 + slot * NT_STG * 4;
        #pragma unroll
        for (int kk = 0; kk < 4; kk++) {
            const int kb = kk * 8 + 4 * lblk;
            unsigned a[4][4], bb[4][2];
            #pragma unroll
            for (int mf = 0; mf < 4; mf++)
                ldsm4(a[mf][0], a[mf][1], a[mf][2], a[mf][3],
                      aBase + ((wm + mf * 16 + lrow) * 36 + kb) * 4);
            #pragma unroll
            for (int p = 0; p < 2; p++) {
                unsigned r0, r1, r2, r3;
                ldsm4(r0, r1, r2, r3, bBase + ((wn + p * 16 + lrow) * 36 + kb) * 4);
                bb[2 * p][0] = r0;
                bb[2 * p][1] = r2;
                bb[2 * p + 1][0] = r1;
                bb[2 * p + 1][1] = r3;
            }
            if (cvtIn) {
                #pragma unroll
                for (int nf = 0; nf < 4; nf++) {
                    bb[nf][0] = f2tf(__uint_as_float(bb[nf][0]));
                    bb[nf][1] = f2tf(__uint_as_float(bb[nf][1]));
                }
            }
            if (hasS) {
                const int j = it * 4 + kk;
                const float slo = sreg[2 * j], shi = sreg[2 * j + 1];
                #pragma unroll
                for (int mf = 0; mf < 4; mf++) {
                    a[mf][0] = f2tf(__uint_as_float(a[mf][0]) * slo);
                    a[mf][1] = f2tf(__uint_as_float(a[mf][1]) * slo);
                    a[mf][2] = f2tf(__uint_as_float(a[mf][2]) * shi);
                    a[mf][3] = f2tf(__uint_as_float(a[mf][3]) * shi);
                }
            } else if (cvtIn) {
                #pragma unroll
                for (int mf = 0; mf < 4; mf++)
                    #pragma unroll
                    for (int q = 0; q < 4; q++)
                        a[mf][q] = f2tf(__uint_as_float(a[mf][q]));
            }
            #pragma unroll
            for (int mf = 0; mf < 4; mf++)
                #pragma unroll
                for (int nf = 0; nf < 4; nf++) mma8(acc[mf][nf], a[mf], bb[nf]);
        }

        if (it + 2 < niter) {
            const int k0 = (it + 2) * 32;
            #pragma unroll
            for (int w = 0; w < 4; w++) {
                int r = ldrow + w * 32;
                cpa16(sA0 + (pslot * NT_STG + r * 36 + ldc4) * 4,
                      Ab + (long)r * ldA + k0 + ldc4);
                cpa16(sB0 + (pslot * NT_STG + r * 36 + ldc4) * 4,
                      Bb + (long)r * ldB + k0 + ldc4);
            }
            cpcommit();
        }
        slot = (slot == 2) ? 0 : slot + 1;
        pslot = (pslot == 2) ? 0 : pslot + 1;
    }

    float* Cb = Cp + (long)bh * I * J;
    const float* rb = rbias ? rbias + (long)bh * I : nullptr;
    const float* cb = cbias ? cbias + (long)bh * J : nullptr;
    #pragma unroll
    for (int mf = 0; mf < 4; mf++)
        #pragma unroll
        for (int nf = 0; nf < 4; nf++) {
            int r0 = i0 + wm + mf * 16 + g;
            int c0 = j0 + wn + nf * 8 + 2 * t;
            #pragma unroll
            for (int ep = 0; ep < 2; ep++) {
                int rr = r0 + ep * 8;
                float v0 = acc[mf][nf][2 * ep] * alpha;
                float v1 = acc[mf][nf][2 * ep + 1] * alpha;
                if (rb) { v0 += rb[rr]; v1 += rb[rr]; }
                if (cb) { v0 += cb[c0]; v1 += cb[c0 + 1]; }
                *(float2*)&Cb[(long)rr * J + c0] = make_float2(v0, v1);
            }
        }
}

// ================= NT GEMM (bf16): chain scores =================
// C[bh] = alpha * A(I,K)bf16 @ B(J,K)bf16^T, causal tile skip.
__global__ void __launch_bounds__(256, 2)
mma_nt_bf(const __nv_bfloat16* __restrict__ A, long Ahs, int ldA,
          const __nv_bfloat16* __restrict__ Bp, long Bhs, int ldB,
          float* __restrict__ Cp, int I, int J, int K, float alpha, int causal) {
    const int bh = blockIdx.z;
    const int j0 = blockIdx.x * 128;
    const int i0 = causal ? (I - 128 - blockIdx.y * 128) : blockIdx.y * 128;
    if (causal && j0 > i0) return;
    const unsigned sA0 = (unsigned)__cvta_generic_to_shared(smem_u);
    const unsigned sB0 = sA0 + 3 * BF_STG * 2;
    const __nv_bfloat16* Ab = A + (long)bh * Ahs + (long)i0 * ldA;
    const __nv_bfloat16* Bb = Bp + (long)bh * Bhs + (long)j0 * ldB;

    const int tid = threadIdx.x, wid = tid >> 5, lane = tid & 31;
    const int g = lane >> 2, t = lane & 3;
    const int wm = (wid & 1) * 64, wn = (wid >> 1) * 32;
    const int lrow = lane & 15, lblk = lane >> 4;
    const int ldrow = tid >> 3, hc8 = (tid & 7) * 8;   // halfs

    const int niter = K / 64;          // 64 halfs (128 B) per stage-chunk
    float acc[4][4][4] = {};

    #pragma unroll
    for (int s = 0; s < 2; s++) {
        if (s < niter) {
            const int k0 = s * 64;
            #pragma unroll
            for (int w = 0; w < 4; w++) {
                int r = ldrow + w * 32;
                cpa16(sA0 + (s * BF_STG + r * 72 + hc8) * 2, Ab + (long)r * ldA + k0 + hc8);
                cpa16(sB0 + (s * BF_STG + r * 72 + hc8) * 2, Bb + (long)r * ldB + k0 + hc8);
            }
            cpcommit();
        }
    }

    int slot = 0, pslot = 2;
    for (int it = 0; it < niter; it++) {
        if (it < niter - 1) asm volatile("cp.async.wait_group 1;");
        else                asm volatile("cp.async.wait_group 0;");
        __syncthreads();

        const unsigned aBase = sA0 + slot * BF_STG * 2;
        const unsigned bBase = sB0 + slot * BF_STG * 2;
        #pragma unroll
        for (int kk = 0; kk < 4; kk++) {
            const int kb = kk * 16 + 8 * lblk;   // halfs
            unsigned a[4][4], bb[4][2];
            #pragma unroll
            for (int mf = 0; mf < 4; mf++)
                ldsm4(a[mf][0], a[mf][1], a[mf][2], a[mf][3],
                      aBase + ((wm + mf * 16 + lrow) * 72 + kb) * 2);
            #pragma unroll
            for (int p = 0; p < 2; p++) {
                unsigned r0, r1, r2, r3;
                ldsm4(r0, r1, r2, r3, bBase + ((wn + p * 16 + lrow) * 72 + kb) * 2);
                bb[2 * p][0] = r0;
                bb[2 * p][1] = r2;
                bb[2 * p + 1][0] = r1;
                bb[2 * p + 1][1] = r3;
            }
            #pragma unroll
            for (int mf = 0; mf < 4; mf++)
                #pragma unroll
                for (int nf = 0; nf < 4; nf++) mma16bf(acc[mf][nf], a[mf], bb[nf]);
        }

        if (it + 2 < niter) {
            const int k0 = (it + 2) * 64;
            #pragma unroll
            for (int w = 0; w < 4; w++) {
                int r = ldrow + w * 32;
                cpa16(sA0 + (pslot * BF_STG + r * 72 + hc8) * 2,
                      Ab + (long)r * ldA + k0 + hc8);
                cpa16(sB0 + (pslot * BF_STG + r * 72 + hc8) * 2,
                      Bb + (long)r * ldB + k0 + hc8);
            }
            cpcommit();
        }
        slot = (slot == 2) ? 0 : slot + 1;
        pslot = (pslot == 2) ? 0 : pslot + 1;
    }

    float* Cb = Cp + (long)bh * I * J;
    #pragma unroll
    for (int mf = 0; mf < 4; mf++)
        #pragma unroll
        for (int nf = 0; nf < 4; nf++) {
            int r0 = i0 + wm + mf * 16 + g;
            int c0 = j0 + wn + nf * 8 + 2 * t;
            #pragma unroll
            for (int ep = 0; ep < 2; ep++) {
                int rr = r0 + ep * 8;
                *(float2*)&Cb[(long)rr * J + c0] =
                    make_float2(acc[mf][nf][2 * ep] * alpha,
                                acc[mf][nf][2 * ep + 1] * alpha);
            }
        }
}

// ================= NN GEMM with fused epilogues (3-stage) =================
__global__ void __launch_bounds__(256, 2)
mma_nn(const float* __restrict__ A, long Abs, long Ahs, int ldA,
       const float* __restrict__ Bp, long Bbs, long Bhs, int ldB,
       const float* __restrict__ bias,
       float* __restrict__ Cp, long Cbs, long Chs, int ldC,
       int K, int accumulate, int trailK, int cvtIn, int roundOut,
       const float* __restrict__ addV,
       const float* __restrict__ gGs, const float* __restrict__ gA2,
       const float* __restrict__ gB2) {
    const int bh = blockIdx.z, b = bh >> 3, h = bh & 7;
    const int col0 = blockIdx.x * 64;
    const int i0 = trailK ? ((gridDim.y - 1 - blockIdx.y) * 128) : blockIdx.y * 128;
    unsigned* As = smem_u;
    unsigned* Bs = smem_u + 3 * NN_ASTG;
    const unsigned sA0 = (unsigned)__cvta_generic_to_shared(As);
    const unsigned sB0 = (unsigned)__cvta_generic_to_shared(Bs);
    const float* Ab = A + (long)b * Abs + (long)h * Ahs + (long)i0 * ldA;
    const float* Bb = Bp + (long)b * Bbs + (long)h * Bhs + col0;

    const int tid = threadIdx.x, wid = tid >> 5, lane = tid & 31;
    const int g = lane >> 2, t = lane & 3;
    const int wm = (wid & 1) * 64, wn = (wid >> 1) * 16;
    const int lrow = lane & 15, lblk = lane >> 4;
    const int ldrow = tid >> 3, ldc4 = (tid & 7) * 4;

    const int Keff = trailK ? min(K, i0 + 128) : K;
    const int niter = Keff / 32;
    float acc[4][2][4] = {};

    #pragma unroll
    for (int s = 0; s < 2; s++) {
        if (s < niter) {
            const int k0 = s * 32;
            #pragma unroll
            for (int w = 0; w < 4; w++) {
                int r = ldrow + w * 32;
                cpa16(sA0 + (s * NN_ASTG + r * 36 + ldc4) * 4, Ab + (long)r * ldA + k0 + ldc4);
            }
            #pragma unroll
            for (int w = 0; w < 2; w++) {
                int li = tid + w * 256;
                int r = li >> 4, c4 = (li & 15) * 4;
                cpa16(sB0 + (s * NN_BSTG + r * 68 + c4) * 4, Bb + (long)(k0 + r) * ldB + c4);
            }
            cpcommit();
        }
    }

    int slot = 0, pslot = 2;
    for (int it = 0; it < niter; it++) {
        if (it < niter - 1) asm volatile("cp.async.wait_group 1;");
        else                asm volatile("cp.async.wait_group 0;");
        __syncthreads();

        const unsigned aBase = sA0 + slot * NN_ASTG * 4;
        const unsigned* Bbuf = Bs + slot * NN_BSTG;
        #pragma unroll
        for (int kk = 0; kk < 4; kk++) {
            const int kb8 = kk * 8;
            unsigned a[4][4], bb[2][2];
            #pragma unroll
            for (int mf = 0; mf < 4; mf++) {
                ldsm4(a[mf][0], a[mf][1], a[mf][2], a[mf][3],
                      aBase + ((wm + mf * 16 + lrow) * 36 + kb8 + 4 * lblk) * 4);
                if (cvtIn) {
                    #pragma unroll
                    for (int q = 0; q < 4; q++)
                        a[mf][q] = f2tf(__uint_as_float(a[mf][q]));
                }
            }
            #pragma unroll
            for (int nf = 0; nf < 2; nf++) {
                bb[nf][0] = Bbuf[(kb8 + t) * 68 + wn + nf * 8 + g];
                bb[nf][1] = Bbuf[(kb8 + t + 4) * 68 + wn + nf * 8 + g];
                if (cvtIn) {
                    bb[nf][0] = f2tf(__uint_as_float(bb[nf][0]));
                    bb[nf][1] = f2tf(__uint_as_float(bb[nf][1]));
                }
            }
            #pragma unroll
            for (int mf = 0; mf < 4; mf++)
                #pragma unroll
                for (int nf = 0; nf < 2; nf++) mma8(acc[mf][nf], a[mf], bb[nf]);
        }

        if (it + 2 < niter) {
            const int k0 = (it + 2) * 32;
            #pragma unroll
            for (int w = 0; w < 4; w++) {
                int r = ldrow + w * 32;
                cpa16(sA0 + (pslot * NN_ASTG + r * 36 + ldc4) * 4,
                      Ab + (long)r * ldA + k0 + ldc4);
            }
            #pragma unroll
            for (int w = 0; w < 2; w++) {
                int li = tid + w * 256;
                int r = li >> 4, c4 = (li & 15) * 4;
                cpa16(sB0 + (pslot * NN_BSTG + r * 68 + c4) * 4,
                      Bb + (long)(k0 + r) * ldB + c4);
            }
            cpcommit();
        }
        slot = (slot == 2) ? 0 : slot + 1;
        pslot = (pslot == 2) ? 0 : pslot + 1;
    }

    const long baseoff = (long)b * Cbs + (long)h * Chs + (long)i0 * ldC + col0;
    float* Cb = Cp + baseoff;
    const float* Xb = addV ? addV + baseoff : nullptr;
    const float* Gs = gGs ? gGs + baseoff : nullptr;
    const float* A2 = gA2 ? gA2 + baseoff : nullptr;
    const float* B2 = gB2 ? gB2 + baseoff : nullptr;
    #pragma unroll
    for (int mf = 0; mf < 4; mf++)
        #pragma unroll
        for (int nf = 0; nf < 2; nf++) {
            int r0 = wm + mf * 16 + g;
            int c0 = wn + nf * 8 + 2 * t;
            #pragma unroll
            for (int e = 0; e < 4; e++) {
                int rr = r0 + (e >> 1) * 8;
                int cc = c0 + (e & 1);
                float v = acc[mf][nf][e];
                if (bias) v += bias[col0 + cc];
                long off = (long)rr * ldC + cc;
                if (accumulate) v += Cb[off];
                if (Xb) v += Xb[off];
                if (Gs) {
                    float sg = 1.f / (1.f + expf(-Gs[off]));
                    float cg = 1.f / (1.f + expf(-v));
                    v = sg * A2[off] + cg * B2[off];
                }
                if (roundOut) v = rnd(v);
                Cb[off] = v;
            }
        }
}

// -------- catt1/catt2 dot products --------
__global__ void dotw(const float* __restrict__ qkv, const float* __restrict__ w,
                     int rows, float* __restrict__ out) {
    int gw = (blockIdx.x * blockDim.x + threadIdx.x) >> 5;
    int lane = threadIdx.x & 31;
    if (gw >= BHc * rows) return;
    int bh = gw / rows, r = gw % rows;
    int b = bh >> 3, h = bh & 7;
    const float* p = qkv + (long)(b * rows + r) * C3c + h * HDc;
    float s = p[lane] * w[h * HDc + lane] + p[lane + 32] * w[h * HDc + lane + 32];
    #pragma unroll
    for (int o = 16; o; o >>= 1) s += __shfl_xor_sync(0xffffffffu, s, o);
    if (lane == 0) out[gw] = s;
}

// -------- row softmax over M=256: f32(tf32-rounded) + bf16 outputs --------
__global__ void softmax_row256(const float* __restrict__ in, float* __restrict__ out,
                               __nv_bfloat16* __restrict__ outh) {
    long row = blockIdx.x;
    int tid = threadIdx.x;
    __shared__ float sh[8];
    float v = in[row * 256 + tid];
    float m = v;
    #pragma unroll
    for (int o = 16; o; o >>= 1) m = fmaxf(m, __shfl_xor_sync(0xffffffffu, m, o));
    if ((tid & 31) == 0) sh[tid >> 5] = m;
    __syncthreads();
    float bm = sh[0];
    #pragma unroll
    for (int i = 1; i < 8; i++) bm = fmaxf(bm, sh[i]);
    __syncthreads();
    float e = expf(v - bm);
    float s = e;
    #pragma unroll
    for (int o = 16; o; o >>= 1) s += __shfl_xor_sync(0xffffffffu, s, o);
    if ((tid & 31) == 0) sh[tid >> 5] = s;
    __syncthreads();
    float bs = 0.f;
    #pragma unroll
    for (int i = 0; i < 8; i++) bs += sh[i];
    float p = e / bs;
    out[row * 256 + tid] = rnd(p);
    outh[row * 256 + tid] = __float2bfloat16(p);
}

// -------- column softmax over T=1024: bf16 output only --------
__global__ void softmax_col(const float* __restrict__ in, __nv_bfloat16* __restrict__ out) {
    int bh = blockIdx.y;
    int mx = threadIdx.x & 63;
    int ty = threadIdx.x >> 6;
    int m = blockIdx.x * 64 + mx;
    const float* base = in + (long)bh * Tc * Mc + m;
    __shared__ float red[256];
    __shared__ float cstat[64];
    float acc = -3.4e38f;
    for (int t = ty; t < Tc; t += 4) acc = fmaxf(acc, base[(long)t * Mc]);
    red[threadIdx.x] = acc;
    __syncthreads();
    if (ty == 0)
        cstat[mx] = fmaxf(fmaxf(red[mx], red[64 + mx]), fmaxf(red[128 + mx], red[192 + mx]));
    __syncthreads();
    float cm = cstat[mx];
    __syncthreads();
    float s = 0.f;
    for (int t = ty; t < Tc; t += 4) s += expf(base[(long)t * Mc] - cm);
    red[threadIdx.x] = s;
    __syncthreads();
    if (ty == 0) cstat[mx] = red[mx] + red[64 + mx] + red[128 + mx] + red[192 + mx];
    __syncthreads();
    float inv = 1.f / cstat[mx];
    __nv_bfloat16* ob = out + (long)bh * Tc * Mc + m;
    for (int t = ty; t < Tc; t += 4)
        ob[(long)t * Mc] = __float2bfloat16(expf(base[(long)t * Mc] - cm) * inv);
}

// -------- causal row softmax, trimmed, static unroll --------
__global__ void softmax_causal(float* __restrict__ buf) {
    long row = blockIdx.x;
    int t = (int)(row & 1023);
    const int len = ((t >> 7) + 1) << 7;
    float* p = buf + row * 1024;
    int tid = threadIdx.x;
    __shared__ float sh[8];
    float v[4];
    float m = -3.4e38f;
    #pragma unroll
    for (int j = 0; j < 4; j++) {
        int s = tid + j * 256;
        float val = -3.4e38f;
        if (j * 256 < len) {
            if (s <= t) val = p[s];
        }
        v[j] = val;
        m = fmaxf(m, val);
    }
    #pragma unroll
    for (int o = 16; o; o >>= 1) m = fmaxf(m, __shfl_xor_sync(0xffffffffu, m, o));
    if ((tid & 31) == 0) sh[tid >> 5] = m;
    __syncthreads();
    float bm = sh[0];
    #pragma unroll
    for (int i = 1; i < 8; i++) bm = fmaxf(bm, sh[i]);
    __syncthreads();
    float sum = 0.f;
    #pragma unroll
    for (int j = 0; j < 4; j++) {
        int s = tid + j * 256;
        float e = 0.f;
        if (j * 256 < len) {
            if (s <= t) e = expf(v[j] - bm);
        }
        v[j] = e;
        sum += e;
    }
    #pragma unroll
    for (int o = 16; o; o >>= 1) sum += __shfl_xor_sync(0xffffffffu, sum, o);
    if ((tid & 31) == 0) sh[tid >> 5] = sum;
    __syncthreads();
    float bs = 0.f;
    #pragma unroll
    for (int i = 0; i < 8; i++) bs += sh[i];
    float inv = 1.f / bs;
    #pragma unroll
    for (int j = 0; j < 4; j++) {
        int s = tid + j * 256;
        if (j * 256 < len) {
            if (s < len) p[s] = rnd(v[j] * inv);
        }
    }
}

extern "C" void kernel_launch(void* const* d_in, const int* in_sizes, int n_in,
                              void* d_out, int out_size) {
    const float* x      = (const float*)d_in[0];
    const float* y      = (const float*)d_in[1];
    const float* Wqkv_x = (const float*)d_in[3];
    const float* bqkv_x = (const float*)d_in[4];
    const float* Wqkv_y = (const float*)d_in[5];
    const float* bqkv_y = (const float*)d_in[6];
    const float* w4x    = (const float*)d_in[7];
    const float* w4y    = (const float*)d_in[8];
    const float* w4xy   = (const float*)d_in[9];
    const float* Wgs    = (const float*)d_in[10];
    const float* bgs    = (const float*)d_in[11];
    const float* Wgc    = (const float*)d_in[12];
    const float* bgc    = (const float*)d_in[13];
    const float* Wp     = (const float*)d_in[14];
    const float* bp     = (const float*)d_in[15];
    float* out = (float*)d_out;

    cudaFuncSetAttribute(mma_nt, cudaFuncAttributeMaxDynamicSharedMemorySize, NT_SMEM);
    cudaFuncSetAttribute(mma_nt_bf, cudaFuncAttributeMaxDynamicSharedMemorySize, BF_SMEM);
    cudaFuncSetAttribute(mma_nn, cudaFuncAttributeMaxDynamicSharedMemorySize, NN_SMEM);

    float *p_qkv_x, *p_qkv_y, *p_catt1, *p_catt2, *p_catt, *p_x2y,
          *p_big, *p_big2, *p_cval, *p_sval, *p_gs, *p_z;
    __nv_bfloat16 *p_x2yh, *p_y2xh;
    cudaGetSymbolAddress((void**)&p_qkv_x, g_qkv_x);
    cudaGetSymbolAddress((void**)&p_qkv_y, g_qkv_y);
    cudaGetSymbolAddress((void**)&p_catt1, g_catt1);
    cudaGetSymbolAddress((void**)&p_catt2, g_catt2);
    cudaGetSymbolAddress((void**)&p_catt, g_catt);
    cudaGetSymbolAddress((void**)&p_x2y, g_x2y);
    cudaGetSymbolAddress((void**)&p_x2yh, g_x2yh);
    cudaGetSymbolAddress((void**)&p_y2xh, g_y2xh);
    cudaGetSymbolAddress((void**)&p_big, g_big);
    cudaGetSymbolAddress((void**)&p_big2, g_big2);
    cudaGetSymbolAddress((void**)&p_cval, g_cval);
    cudaGetSymbolAddress((void**)&p_sval, g_sval);
    cudaGetSymbolAddress((void**)&p_gs, g_gs);
    cudaGetSymbolAddress((void**)&p_z, g_z);

    const float scale = 0.125f;
    const float invSqrtM = 0.0625f;

    // 1-2. QKV projections (tf32-rounded outputs)
    mma_nn<<<dim3(C3c / 64, (Bc * Tc) / 128, 1), 256, NN_SMEM>>>(
        x, 0, 0, Cc, Wqkv_x, 0, 0, C3c, bqkv_x,
        p_qkv_x, 0, 0, C3c, Cc, 0, 0, 1, 1, nullptr, nullptr, nullptr, nullptr);
    mma_nn<<<dim3(C3c / 64, (Bc * Mc) / 128, 1), 256, NN_SMEM>>>(
        y, 0, 0, Cc, Wqkv_y, 0, 0, C3c, bqkv_y,
        p_qkv_y, 0, 0, C3c, Cc, 0, 0, 1, 1, nullptr, nullptr, nullptr, nullptr);
    // 3. dotw x
    dotw<<<(BHc * Tc) / 8, 256>>>(p_qkv_x, w4x, Tc, p_catt1);
    // 4. satt NT (tf32)
    mma_nt<<<dim3(Tc / 128, Tc / 128, BHc), 256, NT_SMEM>>>(
        p_qkv_x, (long)Tc * C3c, 64, C3c,
        p_qkv_x + Cc, (long)Tc * C3c, 64, C3c,
        nullptr, nullptr, nullptr,
        p_big2, Tc, Tc, HDc, scale, 1, 0);
    // 5. dotw y
    dotw<<<(BHc * Mc) / 8, 256>>>(p_qkv_y, w4y, Mc, p_catt2);
    // 6. satt softmax
    softmax_causal<<<BHc * Tc, 256>>>(p_big2);
    // 7. sval = satt @ v_x
    mma_nn<<<dim3(1, Tc / 128, BHc), 256, NN_SMEM>>>(
        p_big2, 8L * Tc * Tc, (long)Tc * Tc, Tc,
        p_qkv_x + 2 * Cc, (long)Tc * C3c, 64, C3c, nullptr,
        p_sval, (long)Tc * Cc, 64, Cc, Tc, 0, 1, 0, 0, nullptr, nullptr, nullptr, nullptr);
    // 8. gs = sval @ Wgs + bgs
    mma_nn<<<dim3(Cc / 64, (Bc * Tc) / 128, 1), 256, NN_SMEM>>>(
        p_sval, 0, 0, Cc, Wgs, 0, 0, Cc, bgs,
        p_gs, 0, 0, Cc, Cc, 0, 0, 1, 0, nullptr, nullptr, nullptr, nullptr);

    // 9. catt (tf32)
    mma_nt<<<dim3(Mc / 128, Tc / 128, BHc), 256, NT_SMEM>>>(
        p_qkv_x, (long)Tc * C3c, 64, C3c,
        p_qkv_y + Cc, (long)Mc * C3c, 64, C3c,
        w4xy, p_catt1, p_catt2,
        p_catt, Tc, Mc, HDc, scale, 0, 0);
    // 10-11. softmaxes: x2y -> f32(tf32) + bf16, y2x -> bf16 only
    softmax_row256<<<BHc * Tc, 256>>>(p_catt, p_x2y, p_x2yh);
    softmax_col<<<dim3(Mc / 64, BHc), 256>>>(p_catt, p_y2xh);
    // 12. cval = x2y @ v_y (tf32)
    mma_nn<<<dim3(1, Tc / 128, BHc), 256, NN_SMEM>>>(
        p_x2y, 8L * Tc * Mc, (long)Tc * Mc, Mc,
        p_qkv_y + 2 * Cc, (long)Mc * C3c, 64, C3c, nullptr,
        p_cval, (long)Tc * Cc, 64, Cc, Mc, 0, 0, 0, 0, nullptr, nullptr, nullptr, nullptr);
    // 13. chain scores (bf16 inputs — bounded logits, safe)
    mma_nt_bf<<<dim3(Tc / 128, Tc / 128, BHc), 256, BF_SMEM>>>(
        p_x2yh, (long)Tc * Mc, Mc,
        p_y2xh, (long)Tc * Mc, Mc,
        p_big, Tc, Tc, Mc, invSqrtM, 1);
    // 14. chain softmax
    softmax_causal<<<BHc * Tc, 256>>>(p_big);
    // 15. cval += chain @ v_x + x
    mma_nn<<<dim3(1, Tc / 128, BHc), 256, NN_SMEM>>>(
        p_big, 8L * Tc * Tc, (long)Tc * Tc, Tc,
        p_qkv_x + 2 * Cc, (long)Tc * C3c, 64, C3c, nullptr,
        p_cval, (long)Tc * Cc, 64, Cc, Tc, 1, 1, 0, 0, x, nullptr, nullptr, nullptr);

    // 16. z = sigmoid(gs)*cval + sigmoid(cval@Wgc+bgc)*sval
    mma_nn<<<dim3(Cc / 64, (Bc * Tc) / 128, 1), 256, NN_SMEM>>>(
        p_cval, 0, 0, Cc, Wgc, 0, 0, Cc, bgc,
        p_z, 0, 0, Cc, Cc, 0, 0, 1, 0, nullptr, p_gs, p_cval, p_sval);

    // 17. out = z @ Wp + bp
    mma_nn<<<dim3(Cc / 64, (Bc * Tc) / 128, 1), 256, NN_SMEM>>>(
        p_z, 0, 0, Cc, Wp, 0, 0, Cc, bp,
        out, 0, 0, Cc, Cc, 0, 0, 1, 0, nullptr, nullptr, nullptr, nullptr);
}

// round 11
// speedup vs baseline: 1.1256x; 1.0288x over previous
#include <cuda_runtime.h>
#include <cuda_bf16.h>
#include <math.h>

#define Bc 4
#define Tc 1024
#define Mc 256
#define Cc 512
#define Hc 8
#define HDc 64
#define C3c 1536
#define BHc 32

// ---------------- scratch ----------------
__device__ float g_qkv_x[Bc * Tc * C3c];
__device__ float g_qkv_y[Bc * Mc * C3c];
__device__ float g_catt1[BHc * Tc];
__device__ float g_catt2[BHc * Mc];
__device__ float g_catt[(long)BHc * Tc * Mc];
__device__ float g_x2y[(long)BHc * Tc * Mc];
__device__ __nv_bfloat16 g_x2yh[(long)BHc * Tc * Mc];
__device__ __nv_bfloat16 g_y2xh[(long)BHc * Tc * Mc];
__device__ float g_big[(long)BHc * Tc * Tc];
__device__ float g_big2[(long)BHc * Tc * Tc];
__device__ float g_cval[Bc * Tc * Cc];
__device__ float g_sval[Bc * Tc * Cc];
__device__ float g_gs[Bc * Tc * Cc];
__device__ float g_z[Bc * Tc * Cc];

// ---------------- helpers ----------------
__device__ __forceinline__ float rnd(float f) {
    unsigned u;
    asm("cvt.rna.tf32.f32 %0, %1;" : "=r"(u) : "f"(f));
    return __uint_as_float(u);
}
__device__ __forceinline__ unsigned f2tf(float f) {
    unsigned u;
    asm("cvt.rna.tf32.f32 %0, %1;" : "=r"(u) : "f"(f));
    return u;
}
__device__ __forceinline__ void mma8(float* d, const unsigned* a, const unsigned* b) {
    asm volatile(
        "mma.sync.aligned.m16n8k8.row.col.f32.tf32.tf32.f32 "
        "{%0,%1,%2,%3},{%4,%5,%6,%7},{%8,%9},{%0,%1,%2,%3};"
        : "+f"(d[0]), "+f"(d[1]), "+f"(d[2]), "+f"(d[3])
        : "r"(a[0]), "r"(a[1]), "r"(a[2]), "r"(a[3]), "r"(b[0]), "r"(b[1]));
}
__device__ __forceinline__ void mma16bf(float* d, const unsigned* a, const unsigned* b) {
    asm volatile(
        "mma.sync.aligned.m16n8k16.row.col.f32.bf16.bf16.f32 "
        "{%0,%1,%2,%3},{%4,%5,%6,%7},{%8,%9},{%0,%1,%2,%3};"
        : "+f"(d[0]), "+f"(d[1]), "+f"(d[2]), "+f"(d[3])
        : "r"(a[0]), "r"(a[1]), "r"(a[2]), "r"(a[3]), "r"(b[0]), "r"(b[1]));
}
__device__ __forceinline__ void cpa16(unsigned dst, const void* src) {
    asm volatile("cp.async.cg.shared.global [%0], [%1], 16;" :: "r"(dst), "l"(src));
}
__device__ __forceinline__ void cpcommit() { asm volatile("cp.async.commit_group;"); }
__device__ __forceinline__ void ldsm4(unsigned& r0, unsigned& r1, unsigned& r2, unsigned& r3,
                                      unsigned addr) {
    asm volatile("ldmatrix.sync.aligned.m8n8.x4.shared.b16 {%0,%1,%2,%3},[%4];"
                 : "=r"(r0), "=r"(r1), "=r"(r2), "=r"(r3) : "r"(addr));
}

// 3-stage pipelines
#define NT_STG (128 * 36)
#define NT_SMEM (6 * NT_STG * 4)
#define NN_ASTG (128 * 36)
#define NN_BSTG (32 * 68)
#define NN_SMEM ((3 * NN_ASTG + 3 * NN_BSTG) * 4)
#define BF_STG (128 * 72)
#define BF_SMEM (6 * BF_STG * 2)
#define NW_ASTG (128 * 36)
#define NW_BSTG (32 * 136)
#define NW_SMEM ((3 * NW_ASTG + 3 * NW_BSTG) * 4)   // 107520 B

extern __shared__ unsigned smem_u[];

// ================= NT GEMM (tf32) =================
__global__ void __launch_bounds__(256, 2)
mma_nt(const float* __restrict__ A, long Abs, long Ahs, int ldA,
       const float* __restrict__ Bp, long Bbs, long Bhs, int ldB,
       const float* __restrict__ scaleA,
       const float* __restrict__ rbias, const float* __restrict__ cbias,
       float* __restrict__ Cp, int I, int J, int K, float alpha, int causal,
       int cvtIn) {
    const int bh = blockIdx.z, b = bh >> 3, h = bh & 7;
    const int j0 = blockIdx.x * 128;
    const int i0 = causal ? (I - 128 - blockIdx.y * 128) : blockIdx.y * 128;
    if (causal && j0 > i0) return;
    unsigned* As = smem_u;
    unsigned* Bs = smem_u + 3 * NT_STG;
    const unsigned sA0 = (unsigned)__cvta_generic_to_shared(As);
    const unsigned sB0 = (unsigned)__cvta_generic_to_shared(Bs);
    const float* Ab = A + (long)b * Abs + (long)h * Ahs + (long)i0 * ldA;
    const float* Bb = Bp + (long)b * Bbs + (long)h * Bhs + (long)j0 * ldB;

    const int tid = threadIdx.x, wid = tid >> 5, lane = tid & 31;
    const int g = lane >> 2, t = lane & 3;
    const int wm = (wid & 1) * 64, wn = (wid >> 1) * 32;
    const int lrow = lane & 15, lblk = lane >> 4;
    const int ldrow = tid >> 3, ldc4 = (tid & 7) * 4;

    float sreg[16];
    const bool hasS = (scaleA != nullptr);
    if (hasS) {
        const float* sA = scaleA + h * HDc;
        #pragma unroll
        for (int j = 0; j < 8; j++) {
            sreg[2 * j] = sA[8 * j + t];
            sreg[2 * j + 1] = sA[8 * j + t + 4];
        }
    }

    const int niter = K / 32;
    float acc[4][4][4] = {};

    #pragma unroll
    for (int s = 0; s < 2; s++) {
        if (s < niter) {
            const int k0 = s * 32;
            #pragma unroll
            for (int w = 0; w < 4; w++) {
                int r = ldrow + w * 32;
                cpa16(sA0 + (s * NT_STG + r * 36 + ldc4) * 4, Ab + (long)r * ldA + k0 + ldc4);
                cpa16(sB0 + (s * NT_STG + r * 36 + ldc4) * 4, Bb + (long)r * ldB + k0 + ldc4);
            }
            cpcommit();
        }
    }

    int slot = 0, pslot = 2;
    for (int it = 0; it < niter; it++) {
        if (it < niter - 1) asm volatile("cp.async.wait_group 1;");
        else                asm volatile("cp.async.wait_group 0;");
        __syncthreads();

        const unsigned aBase = sA0 + slot * NT_STG * 4;
        const unsigned bBase = sB0 + slot * NT_STG * 4;
        #pragma unroll
        for (int kk = 0; kk < 4; kk++) {
            const int kb = kk * 8 + 4 * lblk;
            unsigned a[4][4], bb[4][2];
            #pragma unroll
            for (int mf = 0; mf < 4; mf++)
                ldsm4(a[mf][0], a[mf][1], a[mf][2], a[mf][3],
                      aBase + ((wm + mf * 16 + lrow) * 36 + kb) * 4);
            #pragma unroll
            for (int p = 0; p < 2; p++) {
                unsigned r0, r1, r2, r3;
                ldsm4(r0, r1, r2, r3, bBase + ((wn + p * 16 + lrow) * 36 + kb) * 4);
                bb[2 * p][0] = r0;
                bb[2 * p][1] = r2;
                bb[2 * p + 1][0] = r1;
                bb[2 * p + 1][1] = r3;
            }
            if (cvtIn) {
                #pragma unroll
                for (int nf = 0; nf < 4; nf++) {
                    bb[nf][0] = f2tf(__uint_as_float(bb[nf][0]));
                    bb[nf][1] = f2tf(__uint_as_float(bb[nf][1]));
                }
            }
            if (hasS) {
                const int j = it * 4 + kk;
                const float slo = sreg[2 * j], shi = sreg[2 * j + 1];
                #pragma unroll
                for (int mf = 0; mf < 4; mf++) {
                    a[mf][0] = f2tf(__uint_as_float(a[mf][0]) * slo);
                    a[mf][1] = f2tf(__uint_as_float(a[mf][1]) * slo);
                    a[mf][2] = f2tf(__uint_as_float(a[mf][2]) * shi);
                    a[mf][3] = f2tf(__uint_as_float(a[mf][3]) * shi);
                }
            } else if (cvtIn) {
                #pragma unroll
                for (int mf = 0; mf < 4; mf++)
                    #pragma unroll
                    for (int q = 0; q < 4; q++)
                        a[mf][q] = f2tf(__uint_as_float(a[mf][q]));
            }
            #pragma unroll
            for (int mf = 0; mf < 4; mf++)
                #pragma unroll
                for (int nf = 0; nf < 4; nf++) mma8(acc[mf][nf], a[mf], bb[nf]);
        }

        if (it + 2 < niter) {
            const int k0 = (it + 2) * 32;
            #pragma unroll
            for (int w = 0; w < 4; w++) {
                int r = ldrow + w * 32;
                cpa16(sA0 + (pslot * NT_STG + r * 36 + ldc4) * 4,
                      Ab + (long)r * ldA + k0 + ldc4);
                cpa16(sB0 + (pslot * NT_STG + r * 36 + ldc4) * 4,
                      Bb + (long)r * ldB + k0 + ldc4);
            }
            cpcommit();
        }
        slot = (slot == 2) ? 0 : slot + 1;
        pslot = (pslot == 2) ? 0 : pslot + 1;
    }

    float* Cb = Cp + (long)bh * I * J;
    const float* rb = rbias ? rbias + (long)bh * I : nullptr;
    const float* cb = cbias ? cbias + (long)bh * J : nullptr;
    #pragma unroll
    for (int mf = 0; mf < 4; mf++)
        #pragma unroll
        for (int nf = 0; nf < 4; nf++) {
            int r0 = i0 + wm + mf * 16 + g;
            int c0 = j0 + wn + nf * 8 + 2 * t;
            #pragma unroll
            for (int ep = 0; ep < 2; ep++) {
                int rr = r0 + ep * 8;
                float v0 = acc[mf][nf][2 * ep] * alpha;
                float v1 = acc[mf][nf][2 * ep + 1] * alpha;
                if (rb) { v0 += rb[rr]; v1 += rb[rr]; }
                if (cb) { v0 += cb[c0]; v1 += cb[c0 + 1]; }
                *(float2*)&Cb[(long)rr * J + c0] = make_float2(v0, v1);
            }
        }
}

// ================= NT GEMM (bf16): chain scores =================
__global__ void __launch_bounds__(256, 2)
mma_nt_bf(const __nv_bfloat16* __restrict__ A, long Ahs, int ldA,
          const __nv_bfloat16* __restrict__ Bp, long Bhs, int ldB,
          float* __restrict__ Cp, int I, int J, int K, float alpha, int causal) {
    const int bh = blockIdx.z;
    const int j0 = blockIdx.x * 128;
    const int i0 = causal ? (I - 128 - blockIdx.y * 128) : blockIdx.y * 128;
    if (causal && j0 > i0) return;
    const unsigned sA0 = (unsigned)__cvta_generic_to_shared(smem_u);
    const unsigned sB0 = sA0 + 3 * BF_STG * 2;
    const __nv_bfloat16* Ab = A + (long)bh * Ahs + (long)i0 * ldA;
    const __nv_bfloat16* Bb = Bp + (long)bh * Bhs + (long)j0 * ldB;

    const int tid = threadIdx.x, wid = tid >> 5, lane = tid & 31;
    const int g = lane >> 2, t = lane & 3;
    const int wm = (wid & 1) * 64, wn = (wid >> 1) * 32;
    const int lrow = lane & 15, lblk = lane >> 4;
    const int ldrow = tid >> 3, hc8 = (tid & 7) * 8;

    const int niter = K / 64;
    float acc[4][4][4] = {};

    #pragma unroll
    for (int s = 0; s < 2; s++) {
        if (s < niter) {
            const int k0 = s * 64;
            #pragma unroll
            for (int w = 0; w < 4; w++) {
                int r = ldrow + w * 32;
                cpa16(sA0 + (s * BF_STG + r * 72 + hc8) * 2, Ab + (long)r * ldA + k0 + hc8);
                cpa16(sB0 + (s * BF_STG + r * 72 + hc8) * 2, Bb + (long)r * ldB + k0 + hc8);
            }
            cpcommit();
        }
    }

    int slot = 0, pslot = 2;
    for (int it = 0; it < niter; it++) {
        if (it < niter - 1) asm volatile("cp.async.wait_group 1;");
        else                asm volatile("cp.async.wait_group 0;");
        __syncthreads();

        const unsigned aBase = sA0 + slot * BF_STG * 2;
        const unsigned bBase = sB0 + slot * BF_STG * 2;
        #pragma unroll
        for (int kk = 0; kk < 4; kk++) {
            const int kb = kk * 16 + 8 * lblk;
            unsigned a[4][4], bb[4][2];
            #pragma unroll
            for (int mf = 0; mf < 4; mf++)
                ldsm4(a[mf][0], a[mf][1], a[mf][2], a[mf][3],
                      aBase + ((wm + mf * 16 + lrow) * 72 + kb) * 2);
            #pragma unroll
            for (int p = 0; p < 2; p++) {
                unsigned r0, r1, r2, r3;
                ldsm4(r0, r1, r2, r3, bBase + ((wn + p * 16 + lrow) * 72 + kb) * 2);
                bb[2 * p][0] = r0;
                bb[2 * p][1] = r2;
                bb[2 * p + 1][0] = r1;
                bb[2 * p + 1][1] = r3;
            }
            #pragma unroll
            for (int mf = 0; mf < 4; mf++)
                #pragma unroll
                for (int nf = 0; nf < 4; nf++) mma16bf(acc[mf][nf], a[mf], bb[nf]);
        }

        if (it + 2 < niter) {
            const int k0 = (it + 2) * 64;
            #pragma unroll
            for (int w = 0; w < 4; w++) {
                int r = ldrow + w * 32;
                cpa16(sA0 + (pslot * BF_STG + r * 72 + hc8) * 2,
                      Ab + (long)r * ldA + k0 + hc8);
                cpa16(sB0 + (pslot * BF_STG + r * 72 + hc8) * 2,
                      Bb + (long)r * ldB + k0 + hc8);
            }
            cpcommit();
        }
        slot = (slot == 2) ? 0 : slot + 1;
        pslot = (pslot == 2) ? 0 : pslot + 1;
    }

    float* Cb = Cp + (long)bh * I * J;
    #pragma unroll
    for (int mf = 0; mf < 4; mf++)
        #pragma unroll
        for (int nf = 0; nf < 4; nf++) {
            int r0 = i0 + wm + mf * 16 + g;
            int c0 = j0 + wn + nf * 8 + 2 * t;
            #pragma unroll
            for (int ep = 0; ep < 2; ep++) {
                int rr = r0 + ep * 8;
                *(float2*)&Cb[(long)rr * J + c0] =
                    make_float2(acc[mf][nf][2 * ep] * alpha,
                                acc[mf][nf][2 * ep + 1] * alpha);
            }
        }
}

// ================= narrow NN GEMM (J=64 value GEMMs) =================
__global__ void __launch_bounds__(256, 2)
mma_nn(const float* __restrict__ A, long Abs, long Ahs, int ldA,
       const float* __restrict__ Bp, long Bbs, long Bhs, int ldB,
       const float* __restrict__ bias,
       float* __restrict__ Cp, long Cbs, long Chs, int ldC,
       int K, int accumulate, int trailK, int cvtIn,
       const float* __restrict__ addV) {
    const int bh = blockIdx.z, b = bh >> 3, h = bh & 7;
    const int col0 = blockIdx.x * 64;
    const int i0 = trailK ? ((gridDim.y - 1 - blockIdx.y) * 128) : blockIdx.y * 128;
    unsigned* As = smem_u;
    unsigned* Bs = smem_u + 3 * NN_ASTG;
    const unsigned sA0 = (unsigned)__cvta_generic_to_shared(As);
    const unsigned sB0 = (unsigned)__cvta_generic_to_shared(Bs);
    const float* Ab = A + (long)b * Abs + (long)h * Ahs + (long)i0 * ldA;
    const float* Bb = Bp + (long)b * Bbs + (long)h * Bhs + col0;

    const int tid = threadIdx.x, wid = tid >> 5, lane = tid & 31;
    const int g = lane >> 2, t = lane & 3;
    const int wm = (wid & 1) * 64, wn = (wid >> 1) * 16;
    const int lrow = lane & 15, lblk = lane >> 4;
    const int ldrow = tid >> 3, ldc4 = (tid & 7) * 4;

    const int Keff = trailK ? min(K, i0 + 128) : K;
    const int niter = Keff / 32;
    float acc[4][2][4] = {};

    #pragma unroll
    for (int s = 0; s < 2; s++) {
        if (s < niter) {
            const int k0 = s * 32;
            #pragma unroll
            for (int w = 0; w < 4; w++) {
                int r = ldrow + w * 32;
                cpa16(sA0 + (s * NN_ASTG + r * 36 + ldc4) * 4, Ab + (long)r * ldA + k0 + ldc4);
            }
            #pragma unroll
            for (int w = 0; w < 2; w++) {
                int li = tid + w * 256;
                int r = li >> 4, c4 = (li & 15) * 4;
                cpa16(sB0 + (s * NN_BSTG + r * 68 + c4) * 4, Bb + (long)(k0 + r) * ldB + c4);
            }
            cpcommit();
        }
    }

    int slot = 0, pslot = 2;
    for (int it = 0; it < niter; it++) {
        if (it < niter - 1) asm volatile("cp.async.wait_group 1;");
        else                asm volatile("cp.async.wait_group 0;");
        __syncthreads();

        const unsigned aBase = sA0 + slot * NN_ASTG * 4;
        const unsigned* Bbuf = Bs + slot * NN_BSTG;
        #pragma unroll
        for (int kk = 0; kk < 4; kk++) {
            const int kb8 = kk * 8;
            unsigned a[4][4], bb[2][2];
            #pragma unroll
            for (int mf = 0; mf < 4; mf++) {
                ldsm4(a[mf][0], a[mf][1], a[mf][2], a[mf][3],
                      aBase + ((wm + mf * 16 + lrow) * 36 + kb8 + 4 * lblk) * 4);
                if (cvtIn) {
                    #pragma unroll
                    for (int q = 0; q < 4; q++)
                        a[mf][q] = f2tf(__uint_as_float(a[mf][q]));
                }
            }
            #pragma unroll
            for (int nf = 0; nf < 2; nf++) {
                bb[nf][0] = Bbuf[(kb8 + t) * 68 + wn + nf * 8 + g];
                bb[nf][1] = Bbuf[(kb8 + t + 4) * 68 + wn + nf * 8 + g];
                if (cvtIn) {
                    bb[nf][0] = f2tf(__uint_as_float(bb[nf][0]));
                    bb[nf][1] = f2tf(__uint_as_float(bb[nf][1]));
                }
            }
            #pragma unroll
            for (int mf = 0; mf < 4; mf++)
                #pragma unroll
                for (int nf = 0; nf < 2; nf++) mma8(acc[mf][nf], a[mf], bb[nf]);
        }

        if (it + 2 < niter) {
            const int k0 = (it + 2) * 32;
            #pragma unroll
            for (int w = 0; w < 4; w++) {
                int r = ldrow + w * 32;
                cpa16(sA0 + (pslot * NN_ASTG + r * 36 + ldc4) * 4,
                      Ab + (long)r * ldA + k0 + ldc4);
            }
            #pragma unroll
            for (int w = 0; w < 2; w++) {
                int li = tid + w * 256;
                int r = li >> 4, c4 = (li & 15) * 4;
                cpa16(sB0 + (pslot * NN_BSTG + r * 68 + c4) * 4,
                      Bb + (long)(k0 + r) * ldB + c4);
            }
            cpcommit();
        }
        slot = (slot == 2) ? 0 : slot + 1;
        pslot = (pslot == 2) ? 0 : pslot + 1;
    }

    const long baseoff = (long)b * Cbs + (long)h * Chs + (long)i0 * ldC + col0;
    float* Cb = Cp + baseoff;
    const float* Xb = addV ? addV + baseoff : nullptr;
    #pragma unroll
    for (int mf = 0; mf < 4; mf++)
        #pragma unroll
        for (int nf = 0; nf < 2; nf++) {
            int r0 = wm + mf * 16 + g;
            int c0 = wn + nf * 8 + 2 * t;
            #pragma unroll
            for (int e = 0; e < 4; e++) {
                int rr = r0 + (e >> 1) * 8;
                int cc = c0 + (e & 1);
                float v = acc[mf][nf][e];
                if (bias) v += bias[col0 + cc];
                long off = (long)rr * ldC + cc;
                if (accumulate) v += Cb[off];
                if (Xb) v += Xb[off];
                Cb[off] = v;
            }
        }
}

// ================= wide NN GEMM (dense 128x128): qkv / gates / out =================
// C(I,J) = A(I,K) @ B(K,J) + bias; optional tf32 roundOut; optional fused gate:
//   v = sigmoid(gGs)*gA2 + sigmoid(v)*gB2
__global__ void __launch_bounds__(256, 2)
mma_nn_wide(const float* __restrict__ A, int ldA,
            const float* __restrict__ Bp, int ldB,
            const float* __restrict__ bias,
            float* __restrict__ Cp, int ldC,
            int K, int cvtIn, int roundOut,
            const float* __restrict__ gGs, const float* __restrict__ gA2,
            const float* __restrict__ gB2) {
    const int col0 = blockIdx.x * 128, i0 = blockIdx.y * 128;
    unsigned* As = smem_u;
    unsigned* Bs = smem_u + 3 * NW_ASTG;
    const unsigned sA0 = (unsigned)__cvta_generic_to_shared(As);
    const unsigned sB0 = (unsigned)__cvta_generic_to_shared(Bs);
    const float* Ab = A + (long)i0 * ldA;
    const float* Bb = Bp + col0;

    const int tid = threadIdx.x, wid = tid >> 5, lane = tid & 31;
    const int g = lane >> 2, t = lane & 3;
    const int wm = (wid & 1) * 64, wn = (wid >> 1) * 32;
    const int lrow = lane & 15, lblk = lane >> 4;
    const int ldrow = tid >> 3, ldc4 = (tid & 7) * 4;

    const int niter = K / 32;
    float acc[4][4][4] = {};

    #pragma unroll
    for (int s = 0; s < 2; s++) {
        if (s < niter) {
            const int k0 = s * 32;
            #pragma unroll
            for (int w = 0; w < 4; w++) {
                int r = ldrow + w * 32;
                cpa16(sA0 + (s * NW_ASTG + r * 36 + ldc4) * 4, Ab + (long)r * ldA + k0 + ldc4);
            }
            #pragma unroll
            for (int w = 0; w < 4; w++) {
                int li = tid + w * 256;
                int r = li >> 5, c4 = (li & 31) * 4;
                cpa16(sB0 + (s * NW_BSTG + r * 136 + c4) * 4, Bb + (long)(k0 + r) * ldB + c4);
            }
            cpcommit();
        }
    }

    int slot = 0, pslot = 2;
    for (int it = 0; it < niter; it++) {
        if (it < niter - 1) asm volatile("cp.async.wait_group 1;");
        else                asm volatile("cp.async.wait_group 0;");
        __syncthreads();

        const unsigned aBase = sA0 + slot * NW_ASTG * 4;
        const unsigned* Bbuf = Bs + slot * NW_BSTG;
        #pragma unroll
        for (int kk = 0; kk < 4; kk++) {
            const int kb8 = kk * 8;
            unsigned a[4][4], bb[4][2];
            #pragma unroll
            for (int mf = 0; mf < 4; mf++) {
                ldsm4(a[mf][0], a[mf][1], a[mf][2], a[mf][3],
                      aBase + ((wm + mf * 16 + lrow) * 36 + kb8 + 4 * lblk) * 4);
                if (cvtIn) {
                    #pragma unroll
                    for (int q = 0; q < 4; q++)
                        a[mf][q] = f2tf(__uint_as_float(a[mf][q]));
                }
            }
            #pragma unroll
            for (int nf = 0; nf < 4; nf++) {
                bb[nf][0] = Bbuf[(kb8 + t) * 136 + wn + nf * 8 + g];
                bb[nf][1] = Bbuf[(kb8 + t + 4) * 136 + wn + nf * 8 + g];
                if (cvtIn) {
                    bb[nf][0] = f2tf(__uint_as_float(bb[nf][0]));
                    bb[nf][1] = f2tf(__uint_as_float(bb[nf][1]));
                }
            }
            #pragma unroll
            for (int mf = 0; mf < 4; mf++)
                #pragma unroll
                for (int nf = 0; nf < 4; nf++) mma8(acc[mf][nf], a[mf], bb[nf]);
        }

        if (it + 2 < niter) {
            const int k0 = (it + 2) * 32;
            #pragma unroll
            for (int w = 0; w < 4; w++) {
                int r = ldrow + w * 32;
                cpa16(sA0 + (pslot * NW_ASTG + r * 36 + ldc4) * 4,
                      Ab + (long)r * ldA + k0 + ldc4);
            }
            #pragma unroll
            for (int w = 0; w < 4; w++) {
                int li = tid + w * 256;
                int r = li >> 5, c4 = (li & 31) * 4;
                cpa16(sB0 + (pslot * NW_BSTG + r * 136 + c4) * 4,
                      Bb + (long)(k0 + r) * ldB + c4);
            }
            cpcommit();
        }
        slot = (slot == 2) ? 0 : slot + 1;
        pslot = (pslot == 2) ? 0 : pslot + 1;
    }

    #pragma unroll
    for (int mf = 0; mf < 4; mf++)
        #pragma unroll
        for (int nf = 0; nf < 4; nf++) {
            int rr0 = i0 + wm + mf * 16 + g;
            int cc0 = col0 + wn + nf * 8 + 2 * t;
            #pragma unroll
            for (int e = 0; e < 4; e++) {
                int rr = rr0 + (e >> 1) * 8;
                int cc = cc0 + (e & 1);
                float v = acc[mf][nf][e];
                if (bias) v += bias[cc];
                long off = (long)rr * ldC + cc;
                if (gGs) {
                    float sg = 1.f / (1.f + expf(-gGs[off]));
                    float cg = 1.f / (1.f + expf(-v));
                    v = sg * gA2[off] + cg * gB2[off];
                }
                if (roundOut) v = rnd(v);
                Cp[off] = v;
            }
        }
}

// -------- catt1/catt2 dot products --------
__global__ void dotw(const float* __restrict__ qkv, const float* __restrict__ w,
                     int rows, float* __restrict__ out) {
    int gw = (blockIdx.x * blockDim.x + threadIdx.x) >> 5;
    int lane = threadIdx.x & 31;
    if (gw >= BHc * rows) return;
    int bh = gw / rows, r = gw % rows;
    int b = bh >> 3, h = bh & 7;
    const float* p = qkv + (long)(b * rows + r) * C3c + h * HDc;
    float s = p[lane] * w[h * HDc + lane] + p[lane + 32] * w[h * HDc + lane + 32];
    #pragma unroll
    for (int o = 16; o; o >>= 1) s += __shfl_xor_sync(0xffffffffu, s, o);
    if (lane == 0) out[gw] = s;
}

// -------- row softmax over M=256: f32(tf32) + bf16 outputs --------
__global__ void softmax_row256(const float* __restrict__ in, float* __restrict__ out,
                               __nv_bfloat16* __restrict__ outh) {
    long row = blockIdx.x;
    int tid = threadIdx.x;
    __shared__ float sh[8];
    float v = in[row * 256 + tid];
    float m = v;
    #pragma unroll
    for (int o = 16; o; o >>= 1) m = fmaxf(m, __shfl_xor_sync(0xffffffffu, m, o));
    if ((tid & 31) == 0) sh[tid >> 5] = m;
    __syncthreads();
    float bm = sh[0];
    #pragma unroll
    for (int i = 1; i < 8; i++) bm = fmaxf(bm, sh[i]);
    __syncthreads();
    float e = expf(v - bm);
    float s = e;
    #pragma unroll
    for (int o = 16; o; o >>= 1) s += __shfl_xor_sync(0xffffffffu, s, o);
    if ((tid & 31) == 0) sh[tid >> 5] = s;
    __syncthreads();
    float bs = 0.f;
    #pragma unroll
    for (int i = 0; i < 8; i++) bs += sh[i];
    float p = e / bs;
    out[row * 256 + tid] = rnd(p);
    outh[row * 256 + tid] = __float2bfloat16(p);
}

// -------- column softmax over T=1024: bf16 output --------
__global__ void softmax_col(const float* __restrict__ in, __nv_bfloat16* __restrict__ out) {
    int bh = blockIdx.y;
    int mx = threadIdx.x & 63;
    int ty = threadIdx.x >> 6;
    int m = blockIdx.x * 64 + mx;
    const float* base = in + (long)bh * Tc * Mc + m;
    __shared__ float red[256];
    __shared__ float cstat[64];
    float acc = -3.4e38f;
    for (int t = ty; t < Tc; t += 4) acc = fmaxf(acc, base[(long)t * Mc]);
    red[threadIdx.x] = acc;
    __syncthreads();
    if (ty == 0)
        cstat[mx] = fmaxf(fmaxf(red[mx], red[64 + mx]), fmaxf(red[128 + mx], red[192 + mx]));
    __syncthreads();
    float cm = cstat[mx];
    __syncthreads();
    float s = 0.f;
    for (int t = ty; t < Tc; t += 4) s += expf(base[(long)t * Mc] - cm);
    red[threadIdx.x] = s;
    __syncthreads();
    if (ty == 0) cstat[mx] = red[mx] + red[64 + mx] + red[128 + mx] + red[192 + mx];
    __syncthreads();
    float inv = 1.f / cstat[mx];
    __nv_bfloat16* ob = out + (long)bh * Tc * Mc + m;
    for (int t = ty; t < Tc; t += 4)
        ob[(long)t * Mc] = __float2bfloat16(expf(base[(long)t * Mc] - cm) * inv);
}

// -------- causal row softmax, trimmed, static unroll --------
__global__ void softmax_causal(float* __restrict__ buf) {
    long row = blockIdx.x;
    int t = (int)(row & 1023);
    const int len = ((t >> 7) + 1) << 7;
    float* p = buf + row * 1024;
    int tid = threadIdx.x;
    __shared__ float sh[8];
    float v[4];
    float m = -3.4e38f;
    #pragma unroll
    for (int j = 0; j < 4; j++) {
        int s = tid + j * 256;
        float val = -3.4e38f;
        if (j * 256 < len) {
            if (s <= t) val = p[s];
        }
        v[j] = val;
        m = fmaxf(m, val);
    }
    #pragma unroll
    for (int o = 16; o; o >>= 1) m = fmaxf(m, __shfl_xor_sync(0xffffffffu, m, o));
    if ((tid & 31) == 0) sh[tid >> 5] = m;
    __syncthreads();
    float bm = sh[0];
    #pragma unroll
    for (int i = 1; i < 8; i++) bm = fmaxf(bm, sh[i]);
    __syncthreads();
    float sum = 0.f;
    #pragma unroll
    for (int j = 0; j < 4; j++) {
        int s = tid + j * 256;
        float e = 0.f;
        if (j * 256 < len) {
            if (s <= t) e = expf(v[j] - bm);
        }
        v[j] = e;
        sum += e;
    }
    #pragma unroll
    for (int o = 16; o; o >>= 1) sum += __shfl_xor_sync(0xffffffffu, sum, o);
    if ((tid & 31) == 0) sh[tid >> 5] = sum;
    __syncthreads();
    float bs = 0.f;
    #pragma unroll
    for (int i = 0; i < 8; i++) bs += sh[i];
    float inv = 1.f / bs;
    #pragma unroll
    for (int j = 0; j < 4; j++) {
        int s = tid + j * 256;
        if (j * 256 < len) {
            if (s < len) p[s] = rnd(v[j] * inv);
        }
    }
}

extern "C" void kernel_launch(void* const* d_in, const int* in_sizes, int n_in,
                              void* d_out, int out_size) {
    const float* x      = (const float*)d_in[0];
    const float* y      = (const float*)d_in[1];
    const float* Wqkv_x = (const float*)d_in[3];
    const float* bqkv_x = (const float*)d_in[4];
    const float* Wqkv_y = (const float*)d_in[5];
    const float* bqkv_y = (const float*)d_in[6];
    const float* w4x    = (const float*)d_in[7];
    const float* w4y    = (const float*)d_in[8];
    const float* w4xy   = (const float*)d_in[9];
    const float* Wgs    = (const float*)d_in[10];
    const float* bgs    = (const float*)d_in[11];
    const float* Wgc    = (const float*)d_in[12];
    const float* bgc    = (const float*)d_in[13];
    const float* Wp     = (const float*)d_in[14];
    const float* bp     = (const float*)d_in[15];
    float* out = (float*)d_out;

    cudaFuncSetAttribute(mma_nt, cudaFuncAttributeMaxDynamicSharedMemorySize, NT_SMEM);
    cudaFuncSetAttribute(mma_nt_bf, cudaFuncAttributeMaxDynamicSharedMemorySize, BF_SMEM);
    cudaFuncSetAttribute(mma_nn, cudaFuncAttributeMaxDynamicSharedMemorySize, NN_SMEM);
    cudaFuncSetAttribute(mma_nn_wide, cudaFuncAttributeMaxDynamicSharedMemorySize, NW_SMEM);

    float *p_qkv_x, *p_qkv_y, *p_catt1, *p_catt2, *p_catt, *p_x2y,
          *p_big, *p_big2, *p_cval, *p_sval, *p_gs, *p_z;
    __nv_bfloat16 *p_x2yh, *p_y2xh;
    cudaGetSymbolAddress((void**)&p_qkv_x, g_qkv_x);
    cudaGetSymbolAddress((void**)&p_qkv_y, g_qkv_y);
    cudaGetSymbolAddress((void**)&p_catt1, g_catt1);
    cudaGetSymbolAddress((void**)&p_catt2, g_catt2);
    cudaGetSymbolAddress((void**)&p_catt, g_catt);
    cudaGetSymbolAddress((void**)&p_x2y, g_x2y);
    cudaGetSymbolAddress((void**)&p_x2yh, g_x2yh);
    cudaGetSymbolAddress((void**)&p_y2xh, g_y2xh);
    cudaGetSymbolAddress((void**)&p_big, g_big);
    cudaGetSymbolAddress((void**)&p_big2, g_big2);
    cudaGetSymbolAddress((void**)&p_cval, g_cval);
    cudaGetSymbolAddress((void**)&p_sval, g_sval);
    cudaGetSymbolAddress((void**)&p_gs, g_gs);
    cudaGetSymbolAddress((void**)&p_z, g_z);

    const float scale = 0.125f;
    const float invSqrtM = 0.0625f;

    // 1-2. QKV projections (wide NN, tf32-rounded outputs)
    mma_nn_wide<<<dim3(C3c / 128, (Bc * Tc) / 128), 256, NW_SMEM>>>(
        x, Cc, Wqkv_x, C3c, bqkv_x, p_qkv_x, C3c, Cc, 1, 1,
        nullptr, nullptr, nullptr);
    mma_nn_wide<<<dim3(C3c / 128, (Bc * Mc) / 128), 256, NW_SMEM>>>(
        y, Cc, Wqkv_y, C3c, bqkv_y, p_qkv_y, C3c, Cc, 1, 1,
        nullptr, nullptr, nullptr);
    // 3. dotw x
    dotw<<<(BHc * Tc) / 8, 256>>>(p_qkv_x, w4x, Tc, p_catt1);
    // 4. satt NT (tf32)
    mma_nt<<<dim3(Tc / 128, Tc / 128, BHc), 256, NT_SMEM>>>(
        p_qkv_x, (long)Tc * C3c, 64, C3c,
        p_qkv_x + Cc, (long)Tc * C3c, 64, C3c,
        nullptr, nullptr, nullptr,
        p_big2, Tc, Tc, HDc, scale, 1, 0);
    // 5. dotw y
    dotw<<<(BHc * Mc) / 8, 256>>>(p_qkv_y, w4y, Mc, p_catt2);
    // 6. satt softmax
    softmax_causal<<<BHc * Tc, 256>>>(p_big2);
    // 7. sval = satt @ v_x
    mma_nn<<<dim3(1, Tc / 128, BHc), 256, NN_SMEM>>>(
        p_big2, 8L * Tc * Tc, (long)Tc * Tc, Tc,
        p_qkv_x + 2 * Cc, (long)Tc * C3c, 64, C3c, nullptr,
        p_sval, (long)Tc * Cc, 64, Cc, Tc, 0, 1, 0, nullptr);
    // 8. gs = sval @ Wgs + bgs (wide)
    mma_nn_wide<<<dim3(Cc / 128, (Bc * Tc) / 128), 256, NW_SMEM>>>(
        p_sval, Cc, Wgs, Cc, bgs, p_gs, Cc, Cc, 1, 0,
        nullptr, nullptr, nullptr);

    // 9. catt
    mma_nt<<<dim3(Mc / 128, Tc / 128, BHc), 256, NT_SMEM>>>(
        p_qkv_x, (long)Tc * C3c, 64, C3c,
        p_qkv_y + Cc, (long)Mc * C3c, 64, C3c,
        w4xy, p_catt1, p_catt2,
        p_catt, Tc, Mc, HDc, scale, 0, 0);
    // 10-11. softmaxes
    softmax_row256<<<BHc * Tc, 256>>>(p_catt, p_x2y, p_x2yh);
    softmax_col<<<dim3(Mc / 64, BHc), 256>>>(p_catt, p_y2xh);
    // 12. cval = x2y @ v_y
    mma_nn<<<dim3(1, Tc / 128, BHc), 256, NN_SMEM>>>(
        p_x2y, 8L * Tc * Mc, (long)Tc * Mc, Mc,
        p_qkv_y + 2 * Cc, (long)Mc * C3c, 64, C3c, nullptr,
        p_cval, (long)Tc * Cc, 64, Cc, Mc, 0, 0, 0, nullptr);
    // 13. chain scores (bf16)
    mma_nt_bf<<<dim3(Tc / 128, Tc / 128, BHc), 256, BF_SMEM>>>(
        p_x2yh, (long)Tc * Mc, Mc,
        p_y2xh, (long)Tc * Mc, Mc,
        p_big, Tc, Tc, Mc, invSqrtM, 1);
    // 14. chain softmax
    softmax_causal<<<BHc * Tc, 256>>>(p_big);
    // 15. cval += chain @ v_x + x
    mma_nn<<<dim3(1, Tc / 128, BHc), 256, NN_SMEM>>>(
        p_big, 8L * Tc * Tc, (long)Tc * Tc, Tc,
        p_qkv_x + 2 * Cc, (long)Tc * C3c, 64, C3c, nullptr,
        p_cval, (long)Tc * Cc, 64, Cc, Tc, 1, 1, 0, x);

    // 16. z = sigmoid(gs)*cval + sigmoid(cval@Wgc+bgc)*sval (wide + fused gate)
    mma_nn_wide<<<dim3(Cc / 128, (Bc * Tc) / 128), 256, NW_SMEM>>>(
        p_cval, Cc, Wgc, Cc, bgc, p_z, Cc, Cc, 1, 0,
        p_gs, p_cval, p_sval);

    // 17. out = z @ Wp + bp (wide)
    mma_nn_wide<<<dim3(Cc / 128, (Bc * Tc) / 128), 256, NW_SMEM>>>(
        p_z, Cc, Wp, Cc, bp, out, Cc, Cc, 1, 0,
        nullptr, nullptr, nullptr);
}

// round 12
// speedup vs baseline: 1.2071x; 1.0724x over previous
#include <cuda_runtime.h>
#include <cuda_bf16.h>
#include <cuda_fp16.h>
#include <math.h>

#define Bc 4
#define Tc 1024
#define Mc 256
#define Cc 512
#define Hc 8
#define HDc 64
#define C3c 1536
#define BHc 32

// ---------------- scratch ----------------
__device__ float g_qkv_x[Bc * Tc * C3c];
__device__ float g_qkv_y[Bc * Mc * C3c];
__device__ __half g_vhx[Bc * Tc * Cc];
__device__ __half g_vhy[Bc * Mc * Cc];
__device__ float g_catt1[BHc * Tc];
__device__ float g_catt2[BHc * Mc];
__device__ float g_catt[(long)BHc * Tc * Mc];
__device__ __half g_pxyh[(long)BHc * Tc * Mc];          // x2y probs fp16 (for NN)
__device__ __nv_bfloat16 g_x2yh[(long)BHc * Tc * Mc];   // x2y probs bf16 (chain NT)
__device__ __nv_bfloat16 g_y2xh[(long)BHc * Tc * Mc];   // y2x probs bf16 (chain NT)
__device__ float g_big[(long)BHc * Tc * Tc];            // chain scores f32
__device__ float g_big2[(long)BHc * Tc * Tc];           // satt scores f32
__device__ __half g_bigh[(long)BHc * Tc * Tc];          // probs fp16 (satt then chain)
__device__ float g_cval[Bc * Tc * Cc];
__device__ float g_sval[Bc * Tc * Cc];
__device__ float g_gs[Bc * Tc * Cc];
__device__ float g_z[Bc * Tc * Cc];

// ---------------- helpers ----------------
__device__ __forceinline__ float rnd(float f) {
    unsigned u;
    asm("cvt.rna.tf32.f32 %0, %1;" : "=r"(u) : "f"(f));
    return __uint_as_float(u);
}
__device__ __forceinline__ unsigned f2tf(float f) {
    unsigned u;
    asm("cvt.rna.tf32.f32 %0, %1;" : "=r"(u) : "f"(f));
    return u;
}
__device__ __forceinline__ void mma8(float* d, const unsigned* a, const unsigned* b) {
    asm volatile(
        "mma.sync.aligned.m16n8k8.row.col.f32.tf32.tf32.f32 "
        "{%0,%1,%2,%3},{%4,%5,%6,%7},{%8,%9},{%0,%1,%2,%3};"
        : "+f"(d[0]), "+f"(d[1]), "+f"(d[2]), "+f"(d[3])
        : "r"(a[0]), "r"(a[1]), "r"(a[2]), "r"(a[3]), "r"(b[0]), "r"(b[1]));
}
__device__ __forceinline__ void mma16bf(float* d, const unsigned* a, const unsigned* b) {
    asm volatile(
        "mma.sync.aligned.m16n8k16.row.col.f32.bf16.bf16.f32 "
        "{%0,%1,%2,%3},{%4,%5,%6,%7},{%8,%9},{%0,%1,%2,%3};"
        : "+f"(d[0]), "+f"(d[1]), "+f"(d[2]), "+f"(d[3])
        : "r"(a[0]), "r"(a[1]), "r"(a[2]), "r"(a[3]), "r"(b[0]), "r"(b[1]));
}
__device__ __forceinline__ void mma16h(float* d, const unsigned* a, const unsigned* b) {
    asm volatile(
        "mma.sync.aligned.m16n8k16.row.col.f32.f16.f16.f32 "
        "{%0,%1,%2,%3},{%4,%5,%6,%7},{%8,%9},{%0,%1,%2,%3};"
        : "+f"(d[0]), "+f"(d[1]), "+f"(d[2]), "+f"(d[3])
        : "r"(a[0]), "r"(a[1]), "r"(a[2]), "r"(a[3]), "r"(b[0]), "r"(b[1]));
}
__device__ __forceinline__ void cpa16(unsigned dst, const void* src) {
    asm volatile("cp.async.cg.shared.global [%0], [%1], 16;" :: "r"(dst), "l"(src));
}
__device__ __forceinline__ void cpcommit() { asm volatile("cp.async.commit_group;"); }
__device__ __forceinline__ void ldsm4(unsigned& r0, unsigned& r1, unsigned& r2, unsigned& r3,
                                      unsigned addr) {
    asm volatile("ldmatrix.sync.aligned.m8n8.x4.shared.b16 {%0,%1,%2,%3},[%4];"
                 : "=r"(r0), "=r"(r1), "=r"(r2), "=r"(r3) : "r"(addr));
}
__device__ __forceinline__ void ldsm4t(unsigned& r0, unsigned& r1, unsigned& r2, unsigned& r3,
                                       unsigned addr) {
    asm volatile("ldmatrix.sync.aligned.m8n8.x4.trans.shared.b16 {%0,%1,%2,%3},[%4];"
                 : "=r"(r0), "=r"(r1), "=r"(r2), "=r"(r3) : "r"(addr));
}

// pipelines
#define NT_STG (128 * 36)
#define NT_SMEM (6 * NT_STG * 4)
#define BF_STG (128 * 72)
#define BF_SMEM (6 * BF_STG * 2)
#define NW_ASTG (128 * 36)
#define NW_BSTG (32 * 136)
#define NW_SMEM ((3 * NW_ASTG + 3 * NW_BSTG) * 4)
#define H_ASTG (128 * 72)      // halfs
#define H_BSTG (64 * 72)
#define H_SMEM ((3 * H_ASTG + 3 * H_BSTG) * 2)   // 82944 B

extern __shared__ unsigned smem_u[];

// ================= NT GEMM (tf32) =================
__global__ void __launch_bounds__(256, 2)
mma_nt(const float* __restrict__ A, long Abs, long Ahs, int ldA,
       const float* __restrict__ Bp, long Bbs, long Bhs, int ldB,
       const float* __restrict__ scaleA,
       const float* __restrict__ rbias, const float* __restrict__ cbias,
       float* __restrict__ Cp, int I, int J, int K, float alpha, int causal,
       int cvtIn) {
    const int bh = blockIdx.z, b = bh >> 3, h = bh & 7;
    const int j0 = blockIdx.x * 128;
    const int i0 = causal ? (I - 128 - blockIdx.y * 128) : blockIdx.y * 128;
    if (causal && j0 > i0) return;
    unsigned* As = smem_u;
    unsigned* Bs = smem_u + 3 * NT_STG;
    const unsigned sA0 = (unsigned)__cvta_generic_to_shared(As);
    const unsigned sB0 = (unsigned)__cvta_generic_to_shared(Bs);
    const float* Ab = A + (long)b * Abs + (long)h * Ahs + (long)i0 * ldA;
    const float* Bb = Bp + (long)b * Bbs + (long)h * Bhs + (long)j0 * ldB;

    const int tid = threadIdx.x, wid = tid >> 5, lane = tid & 31;
    const int g = lane >> 2, t = lane & 3;
    const int wm = (wid & 1) * 64, wn = (wid >> 1) * 32;
    const int lrow = lane & 15, lblk = lane >> 4;
    const int ldrow = tid >> 3, ldc4 = (tid & 7) * 4;

    float sreg[16];
    const bool hasS = (scaleA != nullptr);
    if (hasS) {
        const float* sA = scaleA + h * HDc;
        #pragma unroll
        for (int j = 0; j < 8; j++) {
            sreg[2 * j] = sA[8 * j + t];
            sreg[2 * j + 1] = sA[8 * j + t + 4];
        }
    }

    const int niter = K / 32;
    float acc[4][4][4] = {};

    #pragma unroll
    for (int s = 0; s < 2; s++) {
        if (s < niter) {
            const int k0 = s * 32;
            #pragma unroll
            for (int w = 0; w < 4; w++) {
                int r = ldrow + w * 32;
                cpa16(sA0 + (s * NT_STG + r * 36 + ldc4) * 4, Ab + (long)r * ldA + k0 + ldc4);
                cpa16(sB0 + (s * NT_STG + r * 36 + ldc4) * 4, Bb + (long)r * ldB + k0 + ldc4);
            }
            cpcommit();
        }
    }

    int slot = 0, pslot = 2;
    for (int it = 0; it < niter; it++) {
        if (it < niter - 1) asm volatile("cp.async.wait_group 1;");
        else                asm volatile("cp.async.wait_group 0;");
        __syncthreads();

        const unsigned aBase = sA0 + slot * NT_STG * 4;
        const unsigned bBase = sB0 + slot * NT_STG * 4;
        #pragma unroll
        for (int kk = 0; kk < 4; kk++) {
            const int kb = kk * 8 + 4 * lblk;
            unsigned a[4][4], bb[4][2];
            #pragma unroll
            for (int mf = 0; mf < 4; mf++)
                ldsm4(a[mf][0], a[mf][1], a[mf][2], a[mf][3],
                      aBase + ((wm + mf * 16 + lrow) * 36 + kb) * 4);
            #pragma unroll
            for (int p = 0; p < 2; p++) {
                unsigned r0, r1, r2, r3;
                ldsm4(r0, r1, r2, r3, bBase + ((wn + p * 16 + lrow) * 36 + kb) * 4);
                bb[2 * p][0] = r0;
                bb[2 * p][1] = r2;
                bb[2 * p + 1][0] = r1;
                bb[2 * p + 1][1] = r3;
            }
            if (cvtIn) {
                #pragma unroll
                for (int nf = 0; nf < 4; nf++) {
                    bb[nf][0] = f2tf(__uint_as_float(bb[nf][0]));
                    bb[nf][1] = f2tf(__uint_as_float(bb[nf][1]));
                }
            }
            if (hasS) {
                const int j = it * 4 + kk;
                const float slo = sreg[2 * j], shi = sreg[2 * j + 1];
                #pragma unroll
                for (int mf = 0; mf < 4; mf++) {
                    a[mf][0] = f2tf(__uint_as_float(a[mf][0]) * slo);
                    a[mf][1] = f2tf(__uint_as_float(a[mf][1]) * slo);
                    a[mf][2] = f2tf(__uint_as_float(a[mf][2]) * shi);
                    a[mf][3] = f2tf(__uint_as_float(a[mf][3]) * shi);
                }
            } else if (cvtIn) {
                #pragma unroll
                for (int mf = 0; mf < 4; mf++)
                    #pragma unroll
                    for (int q = 0; q < 4; q++)
                        a[mf][q] = f2tf(__uint_as_float(a[mf][q]));
            }
            #pragma unroll
            for (int mf = 0; mf < 4; mf++)
                #pragma unroll
                for (int nf = 0; nf < 4; nf++) mma8(acc[mf][nf], a[mf], bb[nf]);
        }

        if (it + 2 < niter) {
            const int k0 = (it + 2) * 32;
            #pragma unroll
            for (int w = 0; w < 4; w++) {
                int r = ldrow + w * 32;
                cpa16(sA0 + (pslot * NT_STG + r * 36 + ldc4) * 4,
                      Ab + (long)r * ldA + k0 + ldc4);
                cpa16(sB0 + (pslot * NT_STG + r * 36 + ldc4) * 4,
                      Bb + (long)r * ldB + k0 + ldc4);
            }
            cpcommit();
        }
        slot = (slot == 2) ? 0 : slot + 1;
        pslot = (pslot == 2) ? 0 : pslot + 1;
    }

    float* Cb = Cp + (long)bh * I * J;
    const float* rb = rbias ? rbias + (long)bh * I : nullptr;
    const float* cb = cbias ? cbias + (long)bh * J : nullptr;
    #pragma unroll
    for (int mf = 0; mf < 4; mf++)
        #pragma unroll
        for (int nf = 0; nf < 4; nf++) {
            int r0 = i0 + wm + mf * 16 + g;
            int c0 = j0 + wn + nf * 8 + 2 * t;
            #pragma unroll
            for (int ep = 0; ep < 2; ep++) {
                int rr = r0 + ep * 8;
                float v0 = acc[mf][nf][2 * ep] * alpha;
                float v1 = acc[mf][nf][2 * ep + 1] * alpha;
                if (rb) { v0 += rb[rr]; v1 += rb[rr]; }
                if (cb) { v0 += cb[c0]; v1 += cb[c0 + 1]; }
                *(float2*)&Cb[(long)rr * J + c0] = make_float2(v0, v1);
            }
        }
}

// ================= NT GEMM (bf16): chain scores =================
__global__ void __launch_bounds__(256, 2)
mma_nt_bf(const __nv_bfloat16* __restrict__ A, long Ahs, int ldA,
          const __nv_bfloat16* __restrict__ Bp, long Bhs, int ldB,
          float* __restrict__ Cp, int I, int J, int K, float alpha, int causal) {
    const int bh = blockIdx.z;
    const int j0 = blockIdx.x * 128;
    const int i0 = causal ? (I - 128 - blockIdx.y * 128) : blockIdx.y * 128;
    if (causal && j0 > i0) return;
    const unsigned sA0 = (unsigned)__cvta_generic_to_shared(smem_u);
    const unsigned sB0 = sA0 + 3 * BF_STG * 2;
    const __nv_bfloat16* Ab = A + (long)bh * Ahs + (long)i0 * ldA;
    const __nv_bfloat16* Bb = Bp + (long)bh * Bhs + (long)j0 * ldB;

    const int tid = threadIdx.x, wid = tid >> 5, lane = tid & 31;
    const int g = lane >> 2, t = lane & 3;
    const int wm = (wid & 1) * 64, wn = (wid >> 1) * 32;
    const int lrow = lane & 15, lblk = lane >> 4;
    const int ldrow = tid >> 3, hc8 = (tid & 7) * 8;

    const int niter = K / 64;
    float acc[4][4][4] = {};

    #pragma unroll
    for (int s = 0; s < 2; s++) {
        if (s < niter) {
            const int k0 = s * 64;
            #pragma unroll
            for (int w = 0; w < 4; w++) {
                int r = ldrow + w * 32;
                cpa16(sA0 + (s * BF_STG + r * 72 + hc8) * 2, Ab + (long)r * ldA + k0 + hc8);
                cpa16(sB0 + (s * BF_STG + r * 72 + hc8) * 2, Bb + (long)r * ldB + k0 + hc8);
            }
            cpcommit();
        }
    }

    int slot = 0, pslot = 2;
    for (int it = 0; it < niter; it++) {
        if (it < niter - 1) asm volatile("cp.async.wait_group 1;");
        else                asm volatile("cp.async.wait_group 0;");
        __syncthreads();

        const unsigned aBase = sA0 + slot * BF_STG * 2;
        const unsigned bBase = sB0 + slot * BF_STG * 2;
        #pragma unroll
        for (int kk = 0; kk < 4; kk++) {
            const int kb = kk * 16 + 8 * lblk;
            unsigned a[4][4], bb[4][2];
            #pragma unroll
            for (int mf = 0; mf < 4; mf++)
                ldsm4(a[mf][0], a[mf][1], a[mf][2], a[mf][3],
                      aBase + ((wm + mf * 16 + lrow) * 72 + kb) * 2);
            #pragma unroll
            for (int p = 0; p < 2; p++) {
                unsigned r0, r1, r2, r3;
                ldsm4(r0, r1, r2, r3, bBase + ((wn + p * 16 + lrow) * 72 + kb) * 2);
                bb[2 * p][0] = r0;
                bb[2 * p][1] = r2;
                bb[2 * p + 1][0] = r1;
                bb[2 * p + 1][1] = r3;
            }
            #pragma unroll
            for (int mf = 0; mf < 4; mf++)
                #pragma unroll
                for (int nf = 0; nf < 4; nf++) mma16bf(acc[mf][nf], a[mf], bb[nf]);
        }

        if (it + 2 < niter) {
            const int k0 = (it + 2) * 64;
            #pragma unroll
            for (int w = 0; w < 4; w++) {
                int r = ldrow + w * 32;
                cpa16(sA0 + (pslot * BF_STG + r * 72 + hc8) * 2,
                      Ab + (long)r * ldA + k0 + hc8);
                cpa16(sB0 + (pslot * BF_STG + r * 72 + hc8) * 2,
                      Bb + (long)r * ldB + k0 + hc8);
            }
            cpcommit();
        }
        slot = (slot == 2) ? 0 : slot + 1;
        pslot = (pslot == 2) ? 0 : pslot + 1;
    }

    float* Cb = Cp + (long)bh * I * J;
    #pragma unroll
    for (int mf = 0; mf < 4; mf++)
        #pragma unroll
        for (int nf = 0; nf < 4; nf++) {
            int r0 = i0 + wm + mf * 16 + g;
            int c0 = j0 + wn + nf * 8 + 2 * t;
            #pragma unroll
            for (int ep = 0; ep < 2; ep++) {
                int rr = r0 + ep * 8;
                *(float2*)&Cb[(long)rr * J + c0] =
                    make_float2(acc[mf][nf][2 * ep] * alpha,
                                acc[mf][nf][2 * ep + 1] * alpha);
            }
        }
}

// ================= fp16 NN GEMM (value GEMMs): C = P(I,K)h @ V(K,64)h =================
// A fp16 row-major [I][K]; B fp16 [K][n..n+64). K-chunk 64 halfs, 3-stage.
__global__ void __launch_bounds__(256, 2)
mma_nn_h(const __half* __restrict__ A, long Ahs, int ldA,
         const __half* __restrict__ Bp, long Bbs, int ldB,
         float* __restrict__ Cp, long Cbs, long Chs, int ldC,
         int K, int accumulate, int trailK, const float* __restrict__ addV) {
    const int bh = blockIdx.z, b = bh >> 3, h = bh & 7;
    const int i0 = trailK ? ((gridDim.y - 1 - blockIdx.y) * 128) : blockIdx.y * 128;
    const unsigned sA0 = (unsigned)__cvta_generic_to_shared(smem_u);
    const unsigned sB0 = sA0 + 3 * H_ASTG * 2;
    const __half* Ab = A + (long)bh * Ahs + (long)i0 * ldA;
    const __half* Bb = Bp + (long)b * Bbs + h * HDc;

    const int tid = threadIdx.x, wid = tid >> 5, lane = tid & 31;
    const int g = lane >> 2, t = lane & 3;
    const int wm = (wid & 1) * 64, wn = (wid >> 1) * 16;
    const int lrow = lane & 15, lblk = lane >> 4;
    const int ldrow = tid >> 3, hc8 = (tid & 7) * 8;
    // B trans-ldsm lane addressing
    const int trow = lane & 7, tsel = lane >> 3;
    const int tko = (tsel & 1) * 8 + trow;
    const int tno = wn + (tsel >> 1) * 8;

    const int Keff = trailK ? min(K, i0 + 128) : K;
    const int niter = Keff / 64;
    float acc[4][2][4] = {};

    #pragma unroll
    for (int s = 0; s < 2; s++) {
        if (s < niter) {
            const int k0 = s * 64;
            #pragma unroll
            for (int w = 0; w < 4; w++) {
                int r = ldrow + w * 32;
                cpa16(sA0 + (s * H_ASTG + r * 72 + hc8) * 2, Ab + (long)r * ldA + k0 + hc8);
            }
            #pragma unroll
            for (int w = 0; w < 2; w++) {
                int li = tid + w * 256;
                int r = li >> 3, c8 = (li & 7) * 8;
                cpa16(sB0 + (s * H_BSTG + r * 72 + c8) * 2, Bb + (long)(k0 + r) * ldB + c8);
            }
            cpcommit();
        }
    }

    int slot = 0, pslot = 2;
    for (int it = 0; it < niter; it++) {
        if (it < niter - 1) asm volatile("cp.async.wait_group 1;");
        else                asm volatile("cp.async.wait_group 0;");
        __syncthreads();

        const unsigned aBase = sA0 + slot * H_ASTG * 2;
        const unsigned bBase = sB0 + slot * H_BSTG * 2;
        #pragma unroll
        for (int kk = 0; kk < 4; kk++) {
            const int kb = kk * 16;
            unsigned a[4][4], bb[2][2];
            #pragma unroll
            for (int mf = 0; mf < 4; mf++)
                ldsm4(a[mf][0], a[mf][1], a[mf][2], a[mf][3],
                      aBase + ((wm + mf * 16 + lrow) * 72 + kb + 8 * lblk) * 2);
            {
                unsigned r0, r1, r2, r3;
                ldsm4t(r0, r1, r2, r3, bBase + ((kb + tko) * 72 + tno) * 2);
                bb[0][0] = r0; bb[0][1] = r1;
                bb[1][0] = r2; bb[1][1] = r3;
            }
            #pragma unroll
            for (int mf = 0; mf < 4; mf++)
                #pragma unroll
                for (int nf = 0; nf < 2; nf++) mma16h(acc[mf][nf], a[mf], bb[nf]);
        }

        if (it + 2 < niter) {
            const int k0 = (it + 2) * 64;
            #pragma unroll
            for (int w = 0; w < 4; w++) {
                int r = ldrow + w * 32;
                cpa16(sA0 + (pslot * H_ASTG + r * 72 + hc8) * 2,
                      Ab + (long)r * ldA + k0 + hc8);
            }
            #pragma unroll
            for (int w = 0; w < 2; w++) {
                int li = tid + w * 256;
                int r = li >> 3, c8 = (li & 7) * 8;
                cpa16(sB0 + (pslot * H_BSTG + r * 72 + c8) * 2,
                      Bb + (long)(k0 + r) * ldB + c8);
            }
            cpcommit();
        }
        slot = (slot == 2) ? 0 : slot + 1;
        pslot = (pslot == 2) ? 0 : pslot + 1;
    }

    const long baseoff = (long)b * Cbs + (long)h * Chs + (long)i0 * ldC;
    float* Cb = Cp + baseoff;
    const float* Xb = addV ? addV + baseoff : nullptr;
    #pragma unroll
    for (int mf = 0; mf < 4; mf++)
        #pragma unroll
        for (int nf = 0; nf < 2; nf++) {
            int r0 = wm + mf * 16 + g;
            int c0 = wn + nf * 8 + 2 * t;
            #pragma unroll
            for (int e = 0; e < 4; e++) {
                int rr = r0 + (e >> 1) * 8;
                int cc = c0 + (e & 1);
                float v = acc[mf][nf][e];
                long off = (long)rr * ldC + cc;
                if (accumulate) v += Cb[off];
                if (Xb) v += Xb[off];
                Cb[off] = v;
            }
        }
}

// ================= wide NN GEMM (dense): qkv / gates / out =================
__global__ void __launch_bounds__(256, 2)
mma_nn_wide(const float* __restrict__ A, int ldA,
            const float* __restrict__ Bp, int ldB,
            const float* __restrict__ bias,
            float* __restrict__ Cp, int ldC,
            int K, int cvtIn, int roundOut,
            const float* __restrict__ gGs, const float* __restrict__ gA2,
            const float* __restrict__ gB2) {
    const int col0 = blockIdx.x * 128, i0 = blockIdx.y * 128;
    unsigned* As = smem_u;
    unsigned* Bs = smem_u + 3 * NW_ASTG;
    const unsigned sA0 = (unsigned)__cvta_generic_to_shared(As);
    const unsigned sB0 = (unsigned)__cvta_generic_to_shared(Bs);
    const float* Ab = A + (long)i0 * ldA;
    const float* Bb = Bp + col0;

    const int tid = threadIdx.x, wid = tid >> 5, lane = tid & 31;
    const int g = lane >> 2, t = lane & 3;
    const int wm = (wid & 1) * 64, wn = (wid >> 1) * 32;
    const int lrow = lane & 15, lblk = lane >> 4;
    const int ldrow = tid >> 3, ldc4 = (tid & 7) * 4;

    const int niter = K / 32;
    float acc[4][4][4] = {};

    #pragma unroll
    for (int s = 0; s < 2; s++) {
        if (s < niter) {
            const int k0 = s * 32;
            #pragma unroll
            for (int w = 0; w < 4; w++) {
                int r = ldrow + w * 32;
                cpa16(sA0 + (s * NW_ASTG + r * 36 + ldc4) * 4, Ab + (long)r * ldA + k0 + ldc4);
            }
            #pragma unroll
            for (int w = 0; w < 4; w++) {
                int li = tid + w * 256;
                int r = li >> 5, c4 = (li & 31) * 4;
                cpa16(sB0 + (s * NW_BSTG + r * 136 + c4) * 4, Bb + (long)(k0 + r) * ldB + c4);
            }
            cpcommit();
        }
    }

    int slot = 0, pslot = 2;
    for (int it = 0; it < niter; it++) {
        if (it < niter - 1) asm volatile("cp.async.wait_group 1;");
        else                asm volatile("cp.async.wait_group 0;");
        __syncthreads();

        const unsigned aBase = sA0 + slot * NW_ASTG * 4;
        const unsigned* Bbuf = Bs + slot * NW_BSTG;
        #pragma unroll
        for (int kk = 0; kk < 4; kk++) {
            const int kb8 = kk * 8;
            unsigned a[4][4], bb[4][2];
            #pragma unroll
            for (int mf = 0; mf < 4; mf++) {
                ldsm4(a[mf][0], a[mf][1], a[mf][2], a[mf][3],
                      aBase + ((wm + mf * 16 + lrow) * 36 + kb8 + 4 * lblk) * 4);
                if (cvtIn) {
                    #pragma unroll
                    for (int q = 0; q < 4; q++)
                        a[mf][q] = f2tf(__uint_as_float(a[mf][q]));
                }
            }
            #pragma unroll
            for (int nf = 0; nf < 4; nf++) {
                bb[nf][0] = Bbuf[(kb8 + t) * 136 + wn + nf * 8 + g];
                bb[nf][1] = Bbuf[(kb8 + t + 4) * 136 + wn + nf * 8 + g];
                if (cvtIn) {
                    bb[nf][0] = f2tf(__uint_as_float(bb[nf][0]));
                    bb[nf][1] = f2tf(__uint_as_float(bb[nf][1]));
                }
            }
            #pragma unroll
            for (int mf = 0; mf < 4; mf++)
                #pragma unroll
                for (int nf = 0; nf < 4; nf++) mma8(acc[mf][nf], a[mf], bb[nf]);
        }

        if (it + 2 < niter) {
            const int k0 = (it + 2) * 32;
            #pragma unroll
            for (int w = 0; w < 4; w++) {
                int r = ldrow + w * 32;
                cpa16(sA0 + (pslot * NW_ASTG + r * 36 + ldc4) * 4,
                      Ab + (long)r * ldA + k0 + ldc4);
            }
            #pragma unroll
            for (int w = 0; w < 4; w++) {
                int li = tid + w * 256;
                int r = li >> 5, c4 = (li & 31) * 4;
                cpa16(sB0 + (pslot * NW_BSTG + r * 136 + c4) * 4,
                      Bb + (long)(k0 + r) * ldB + c4);
            }
            cpcommit();
        }
        slot = (slot == 2) ? 0 : slot + 1;
        pslot = (pslot == 2) ? 0 : pslot + 1;
    }

    #pragma unroll
    for (int mf = 0; mf < 4; mf++)
        #pragma unroll
        for (int nf = 0; nf < 4; nf++) {
            int rr0 = i0 + wm + mf * 16 + g;
            int cc0 = col0 + wn + nf * 8 + 2 * t;
            #pragma unroll
            for (int e = 0; e < 4; e++) {
                int rr = rr0 + (e >> 1) * 8;
                int cc = cc0 + (e & 1);
                float v = acc[mf][nf][e];
                if (bias) v += bias[cc];
                long off = (long)rr * ldC + cc;
                if (gGs) {
                    float sg = 1.f / (1.f + expf(-gGs[off]));
                    float cg = 1.f / (1.f + expf(-v));
                    v = sg * gA2[off] + cg * gB2[off];
                }
                if (roundOut) v = rnd(v);
                Cp[off] = v;
            }
        }
}

// -------- v slice fp16 convert: vh[row*512+c] = h(qkv[row*1536 + 1024 + c]) --------
__global__ void conv_v(const float* __restrict__ qkv, __half* __restrict__ vh, int rows) {
    int i4 = blockIdx.x * blockDim.x + threadIdx.x;
    if (i4 >= rows * 128) return;
    int row = i4 >> 7, c4 = (i4 & 127) * 4;
    const float4 v = *(const float4*)&qkv[(long)row * C3c + 2 * Cc + c4];
    __half2 h0 = __floats2half2_rn(v.x, v.y);
    __half2 h1 = __floats2half2_rn(v.z, v.w);
    uint2 u;
    u.x = *(unsigned*)&h0;
    u.y = *(unsigned*)&h1;
    *(uint2*)&vh[(long)row * Cc + c4] = u;
}

// -------- catt1/catt2 dot products --------
__global__ void dotw(const float* __restrict__ qkv, const float* __restrict__ w,
                     int rows, float* __restrict__ out) {
    int gw = (blockIdx.x * blockDim.x + threadIdx.x) >> 5;
    int lane = threadIdx.x & 31;
    if (gw >= BHc * rows) return;
    int bh = gw / rows, r = gw % rows;
    int b = bh >> 3, h = bh & 7;
    const float* p = qkv + (long)(b * rows + r) * C3c + h * HDc;
    float s = p[lane] * w[h * HDc + lane] + p[lane + 32] * w[h * HDc + lane + 32];
    #pragma unroll
    for (int o = 16; o; o >>= 1) s += __shfl_xor_sync(0xffffffffu, s, o);
    if (lane == 0) out[gw] = s;
}

// -------- row softmax over M=256: fp16 + bf16 outputs --------
__global__ void softmax_row256(const float* __restrict__ in, __half* __restrict__ outh16,
                               __nv_bfloat16* __restrict__ outbf) {
    long row = blockIdx.x;
    int tid = threadIdx.x;
    __shared__ float sh[8];
    float v = in[row * 256 + tid];
    float m = v;
    #pragma unroll
    for (int o = 16; o; o >>= 1) m = fmaxf(m, __shfl_xor_sync(0xffffffffu, m, o));
    if ((tid & 31) == 0) sh[tid >> 5] = m;
    __syncthreads();
    float bm = sh[0];
    #pragma unroll
    for (int i = 1; i < 8; i++) bm = fmaxf(bm, sh[i]);
    __syncthreads();
    float e = expf(v - bm);
    float s = e;
    #pragma unroll
    for (int o = 16; o; o >>= 1) s += __shfl_xor_sync(0xffffffffu, s, o);
    if ((tid & 31) == 0) sh[tid >> 5] = s;
    __syncthreads();
    float bs = 0.f;
    #pragma unroll
    for (int i = 0; i < 8; i++) bs += sh[i];
    float p = e / bs;
    outh16[row * 256 + tid] = __float2half_rn(p);
    outbf[row * 256 + tid] = __float2bfloat16(p);
}

// -------- column softmax over T=1024: bf16 output --------
__global__ void softmax_col(const float* __restrict__ in, __nv_bfloat16* __restrict__ out) {
    int bh = blockIdx.y;
    int mx = threadIdx.x & 63;
    int ty = threadIdx.x >> 6;
    int m = blockIdx.x * 64 + mx;
    const float* base = in + (long)bh * Tc * Mc + m;
    __shared__ float red[256];
    __shared__ float cstat[64];
    float acc = -3.4e38f;
    for (int t = ty; t < Tc; t += 4) acc = fmaxf(acc, base[(long)t * Mc]);
    red[threadIdx.x] = acc;
    __syncthreads();
    if (ty == 0)
        cstat[mx] = fmaxf(fmaxf(red[mx], red[64 + mx]), fmaxf(red[128 + mx], red[192 + mx]));
    __syncthreads();
    float cm = cstat[mx];
    __syncthreads();
    float s = 0.f;
    for (int t = ty; t < Tc; t += 4) s += expf(base[(long)t * Mc] - cm);
    red[threadIdx.x] = s;
    __syncthreads();
    if (ty == 0) cstat[mx] = red[mx] + red[64 + mx] + red[128 + mx] + red[192 + mx];
    __syncthreads();
    float inv = 1.f / cstat[mx];
    __nv_bfloat16* ob = out + (long)bh * Tc * Mc + m;
    for (int t = ty; t < Tc; t += 4)
        ob[(long)t * Mc] = __float2bfloat16(expf(base[(long)t * Mc] - cm) * inv);
}

// -------- causal row softmax: read f32 scores, write fp16 probs --------
__global__ void softmax_causal(const float* __restrict__ buf, __half* __restrict__ outp) {
    long row = blockIdx.x;
    int t = (int)(row & 1023);
    const int len = ((t >> 7) + 1) << 7;
    const float* p = buf + row * 1024;
    __half* op = outp + row * 1024;
    int tid = threadIdx.x;
    __shared__ float sh[8];
    float v[4];
    float m = -3.4e38f;
    #pragma unroll
    for (int j = 0; j < 4; j++) {
        int s = tid + j * 256;
        float val = -3.4e38f;
        if (j * 256 < len) {
            if (s <= t) val = p[s];
        }
        v[j] = val;
        m = fmaxf(m, val);
    }
    #pragma unroll
    for (int o = 16; o; o >>= 1) m = fmaxf(m, __shfl_xor_sync(0xffffffffu, m, o));
    if ((tid & 31) == 0) sh[tid >> 5] = m;
    __syncthreads();
    float bm = sh[0];
    #pragma unroll
    for (int i = 1; i < 8; i++) bm = fmaxf(bm, sh[i]);
    __syncthreads();
    float sum = 0.f;
    #pragma unroll
    for (int j = 0; j < 4; j++) {
        int s = tid + j * 256;
        float e = 0.f;
        if (j * 256 < len) {
            if (s <= t) e = expf(v[j] - bm);
        }
        v[j] = e;
        sum += e;
    }
    #pragma unroll
    for (int o = 16; o; o >>= 1) sum += __shfl_xor_sync(0xffffffffu, sum, o);
    if ((tid & 31) == 0) sh[tid >> 5] = sum;
    __syncthreads();
    float bs = 0.f;
    #pragma unroll
    for (int i = 0; i < 8; i++) bs += sh[i];
    float inv = 1.f / bs;
    #pragma unroll
    for (int j = 0; j < 4; j++) {
        int s = tid + j * 256;
        if (j * 256 < len) {
            if (s < len) op[s] = __float2half_rn(v[j] * inv);
        }
    }
}

extern "C" void kernel_launch(void* const* d_in, const int* in_sizes, int n_in,
                              void* d_out, int out_size) {
    const float* x      = (const float*)d_in[0];
    const float* y      = (const float*)d_in[1];
    const float* Wqkv_x = (const float*)d_in[3];
    const float* bqkv_x = (const float*)d_in[4];
    const float* Wqkv_y = (const float*)d_in[5];
    const float* bqkv_y = (const float*)d_in[6];
    const float* w4x    = (const float*)d_in[7];
    const float* w4y    = (const float*)d_in[8];
    const float* w4xy   = (const float*)d_in[9];
    const float* Wgs    = (const float*)d_in[10];
    const float* bgs    = (const float*)d_in[11];
    const float* Wgc    = (const float*)d_in[12];
    const float* bgc    = (const float*)d_in[13];
    const float* Wp     = (const float*)d_in[14];
    const float* bp     = (const float*)d_in[15];
    float* out = (float*)d_out;

    cudaFuncSetAttribute(mma_nt, cudaFuncAttributeMaxDynamicSharedMemorySize, NT_SMEM);
    cudaFuncSetAttribute(mma_nt_bf, cudaFuncAttributeMaxDynamicSharedMemorySize, BF_SMEM);
    cudaFuncSetAttribute(mma_nn_h, cudaFuncAttributeMaxDynamicSharedMemorySize, H_SMEM);
    cudaFuncSetAttribute(mma_nn_wide, cudaFuncAttributeMaxDynamicSharedMemorySize, NW_SMEM);

    float *p_qkv_x, *p_qkv_y, *p_catt1, *p_catt2, *p_catt,
          *p_big, *p_big2, *p_cval, *p_sval, *p_gs, *p_z;
    __half *p_vhx, *p_vhy, *p_pxyh, *p_bigh;
    __nv_bfloat16 *p_x2yh, *p_y2xh;
    cudaGetSymbolAddress((void**)&p_qkv_x, g_qkv_x);
    cudaGetSymbolAddress((void**)&p_qkv_y, g_qkv_y);
    cudaGetSymbolAddress((void**)&p_vhx, g_vhx);
    cudaGetSymbolAddress((void**)&p_vhy, g_vhy);
    cudaGetSymbolAddress((void**)&p_catt1, g_catt1);
    cudaGetSymbolAddress((void**)&p_catt2, g_catt2);
    cudaGetSymbolAddress((void**)&p_catt, g_catt);
    cudaGetSymbolAddress((void**)&p_pxyh, g_pxyh);
    cudaGetSymbolAddress((void**)&p_x2yh, g_x2yh);
    cudaGetSymbolAddress((void**)&p_y2xh, g_y2xh);
    cudaGetSymbolAddress((void**)&p_big, g_big);
    cudaGetSymbolAddress((void**)&p_big2, g_big2);
    cudaGetSymbolAddress((void**)&p_bigh, g_bigh);
    cudaGetSymbolAddress((void**)&p_cval, g_cval);
    cudaGetSymbolAddress((void**)&p_sval, g_sval);
    cudaGetSymbolAddress((void**)&p_gs, g_gs);
    cudaGetSymbolAddress((void**)&p_z, g_z);

    const float scale = 0.125f;
    const float invSqrtM = 0.0625f;

    // 1-2. QKV projections (wide NN, tf32-rounded outputs)
    mma_nn_wide<<<dim3(C3c / 128, (Bc * Tc) / 128), 256, NW_SMEM>>>(
        x, Cc, Wqkv_x, C3c, bqkv_x, p_qkv_x, C3c, Cc, 1, 1,
        nullptr, nullptr, nullptr);
    mma_nn_wide<<<dim3(C3c / 128, (Bc * Mc) / 128), 256, NW_SMEM>>>(
        y, Cc, Wqkv_y, C3c, bqkv_y, p_qkv_y, C3c, Cc, 1, 1,
        nullptr, nullptr, nullptr);
    // 2b. fp16 copies of v slices
    conv_v<<<(Bc * Tc * 128 + 255) / 256, 256>>>(p_qkv_x, p_vhx, Bc * Tc);
    conv_v<<<(Bc * Mc * 128 + 255) / 256, 256>>>(p_qkv_y, p_vhy, Bc * Mc);
    // 3. dotw x
    dotw<<<(BHc * Tc) / 8, 256>>>(p_qkv_x, w4x, Tc, p_catt1);
    // 4. satt NT (tf32)
    mma_nt<<<dim3(Tc / 128, Tc / 128, BHc), 256, NT_SMEM>>>(
        p_qkv_x, (long)Tc * C3c, 64, C3c,
        p_qkv_x + Cc, (long)Tc * C3c, 64, C3c,
        nullptr, nullptr, nullptr,
        p_big2, Tc, Tc, HDc, scale, 1, 0);
    // 5. dotw y
    dotw<<<(BHc * Mc) / 8, 256>>>(p_qkv_y, w4y, Mc, p_catt2);
    // 6. satt softmax -> fp16 probs
    softmax_causal<<<BHc * Tc, 256>>>(p_big2, p_bigh);
    // 7. sval = satt @ v_x (fp16)
    mma_nn_h<<<dim3(1, Tc / 128, BHc), 256, H_SMEM>>>(
        p_bigh, (long)Tc * Tc, Tc,
        p_vhx, (long)Tc * Cc, Cc,
        p_sval, (long)Tc * Cc, HDc, Cc, Tc, 0, 1, nullptr);
    // 8. gs = sval @ Wgs + bgs (wide)
    mma_nn_wide<<<dim3(Cc / 128, (Bc * Tc) / 128), 256, NW_SMEM>>>(
        p_sval, Cc, Wgs, Cc, bgs, p_gs, Cc, Cc, 1, 0,
        nullptr, nullptr, nullptr);

    // 9. catt
    mma_nt<<<dim3(Mc / 128, Tc / 128, BHc), 256, NT_SMEM>>>(
        p_qkv_x, (long)Tc * C3c, 64, C3c,
        p_qkv_y + Cc, (long)Mc * C3c, 64, C3c,
        w4xy, p_catt1, p_catt2,
        p_catt, Tc, Mc, HDc, scale, 0, 0);
    // 10-11. softmaxes: x2y -> fp16 + bf16, y2x -> bf16
    softmax_row256<<<BHc * Tc, 256>>>(p_catt, p_pxyh, p_x2yh);
    softmax_col<<<dim3(Mc / 64, BHc), 256>>>(p_catt, p_y2xh);
    // 12. cval = x2y @ v_y (fp16)
    mma_nn_h<<<dim3(1, Tc / 128, BHc), 256, H_SMEM>>>(
        p_pxyh, (long)Tc * Mc, Mc,
        p_vhy, (long)Mc * Cc, Cc,
        p_cval, (long)Tc * Cc, HDc, Cc, Mc, 0, 0, nullptr);
    // 13. chain scores (bf16)
    mma_nt_bf<<<dim3(Tc / 128, Tc / 128, BHc), 256, BF_SMEM>>>(
        p_x2yh, (long)Tc * Mc, Mc,
        p_y2xh, (long)Tc * Mc, Mc,
        p_big, Tc, Tc, Mc, invSqrtM, 1);
    // 14. chain softmax -> fp16 probs
    softmax_causal<<<BHc * Tc, 256>>>(p_big, p_bigh);
    // 15. cval += chain @ v_x + x (fp16, fused residual)
    mma_nn_h<<<dim3(1, Tc / 128, BHc), 256, H_SMEM>>>(
        p_bigh, (long)Tc * Tc, Tc,
        p_vhx, (long)Tc * Cc, Cc,
        p_cval, (long)Tc * Cc, HDc, Cc, Tc, 1, 1, x);

    // 16. z = sigmoid(gs)*cval + sigmoid(cval@Wgc+bgc)*sval (wide + fused gate)
    mma_nn_wide<<<dim3(Cc / 128, (Bc * Tc) / 128), 256, NW_SMEM>>>(
        p_cval, Cc, Wgc, Cc, bgc, p_z, Cc, Cc, 1, 0,
        p_gs, p_cval, p_sval);

    // 17. out = z @ Wp + bp (wide)
    mma_nn_wide<<<dim3(Cc / 128, (Bc * Tc) / 128), 256, NW_SMEM>>>(
        p_z, Cc, Wp, Cc, bp, out, Cc, Cc, 1, 0,
        nullptr, nullptr, nullptr);
}

// round 13
// speedup vs baseline: 1.3953x; 1.1559x over previous
#include <cuda_runtime.h>
#include <cuda_bf16.h>
#include <cuda_fp16.h>
#include <math.h>

#define Bc 4
#define Tc 1024
#define Mc 256
#define Cc 512
#define Hc 8
#define HDc 64
#define C3c 1536
#define BHc 32

// ---------------- scratch ----------------
__device__ __half g_xh[Bc * Tc * Cc];
__device__ __half g_yh[Bc * Mc * Cc];
__device__ __half g_wqxh[Cc * C3c];
__device__ __half g_wqyh[Cc * C3c];
__device__ __half g_wgsh[Cc * Cc];
__device__ __half g_wgch[Cc * Cc];
__device__ __half g_wph[Cc * Cc];
__device__ __half g_qkvxh[Bc * Tc * C3c];
__device__ __half g_qkvyh[Bc * Mc * C3c];
__device__ __half g_qsh[Bc * Tc * Cc];                  // q_x * w4xy
__device__ float g_catt1[BHc * Tc];
__device__ float g_catt2[BHc * Mc];
__device__ float g_catt[(long)BHc * Tc * Mc];
__device__ __half g_pxy[(long)BHc * Tc * Mc];           // x2y probs
__device__ __half g_y2xh[(long)BHc * Tc * Mc];          // y2x probs
__device__ float g_big[(long)BHc * Tc * Tc];            // scores f32 (chain)
__device__ float g_big2[(long)BHc * Tc * Tc];           // scores f32 (satt)
__device__ __half g_bigh[(long)BHc * Tc * Tc];          // probs fp16 (reused)
__device__ float g_cval[Bc * Tc * Cc];
__device__ __half g_cvalh[Bc * Tc * Cc];
__device__ float g_sval[Bc * Tc * Cc];
__device__ __half g_svalh[Bc * Tc * Cc];
__device__ float g_gs[Bc * Tc * Cc];
__device__ __half g_zh[Bc * Tc * Cc];

// ---------------- helpers ----------------
__device__ __forceinline__ void mma16h(float* d, const unsigned* a, const unsigned* b) {
    asm volatile(
        "mma.sync.aligned.m16n8k16.row.col.f32.f16.f16.f32 "
        "{%0,%1,%2,%3},{%4,%5,%6,%7},{%8,%9},{%0,%1,%2,%3};"
        : "+f"(d[0]), "+f"(d[1]), "+f"(d[2]), "+f"(d[3])
        : "r"(a[0]), "r"(a[1]), "r"(a[2]), "r"(a[3]), "r"(b[0]), "r"(b[1]));
}
__device__ __forceinline__ void cpa16(unsigned dst, const void* src) {
    asm volatile("cp.async.cg.shared.global [%0], [%1], 16;" :: "r"(dst), "l"(src));
}
__device__ __forceinline__ void cpcommit() { asm volatile("cp.async.commit_group;"); }
__device__ __forceinline__ void ldsm4(unsigned& r0, unsigned& r1, unsigned& r2, unsigned& r3,
                                      unsigned addr) {
    asm volatile("ldmatrix.sync.aligned.m8n8.x4.shared.b16 {%0,%1,%2,%3},[%4];"
                 : "=r"(r0), "=r"(r1), "=r"(r2), "=r"(r3) : "r"(addr));
}
__device__ __forceinline__ void ldsm4t(unsigned& r0, unsigned& r1, unsigned& r2, unsigned& r3,
                                       unsigned addr) {
    asm volatile("ldmatrix.sync.aligned.m8n8.x4.trans.shared.b16 {%0,%1,%2,%3},[%4];"
                 : "=r"(r0), "=r"(r1), "=r"(r2), "=r"(r3) : "r"(addr));
}

// pipelines (halfs)
#define NT_STG (128 * 72)
#define NT_SMEM (6 * NT_STG * 2)                   // 110592 B
#define H_ASTG (128 * 72)
#define H_BSTG (64 * 72)
#define H_SMEM ((3 * H_ASTG + 3 * H_BSTG) * 2)     // 82944 B
#define W_ASTG (128 * 72)
#define W_BSTG (64 * 136)
#define W_SMEM ((3 * W_ASTG + 3 * W_BSTG) * 2)     // 107520 B

extern __shared__ unsigned smem_u[];

// ================= fp16 NT GEMM: C = alpha*A(I,K)@B(J,K)^T (+rb[i]+cb[j]) ============
// CTA 128x128, warp 64x32, K-chunk 64 halfs, 3-stage. f32 output.
__global__ void __launch_bounds__(256, 2)
mma_nt_h(const __half* __restrict__ A, long Abs, long Ahs, int ldA,
         const __half* __restrict__ Bp, long Bbs, long Bhs, int ldB,
         const float* __restrict__ rbias, const float* __restrict__ cbias,
         float* __restrict__ Cp, int I, int J, int K, float alpha, int causal) {
    const int bh = blockIdx.z, b = bh >> 3, h = bh & 7;
    const int j0 = blockIdx.x * 128;
    const int i0 = causal ? (I - 128 - blockIdx.y * 128) : blockIdx.y * 128;
    if (causal && j0 > i0) return;
    const unsigned sA0 = (unsigned)__cvta_generic_to_shared(smem_u);
    const unsigned sB0 = sA0 + 3 * NT_STG * 2;
    const __half* Ab = A + (long)b * Abs + (long)h * Ahs + (long)i0 * ldA;
    const __half* Bb = Bp + (long)b * Bbs + (long)h * Bhs + (long)j0 * ldB;

    const int tid = threadIdx.x, wid = tid >> 5, lane = tid & 31;
    const int g = lane >> 2, t = lane & 3;
    const int wm = (wid & 1) * 64, wn = (wid >> 1) * 32;
    const int lrow = lane & 15, lblk = lane >> 4;
    const int ldrow = tid >> 3, hc8 = (tid & 7) * 8;

    const int niter = K / 64;
    float acc[4][4][4] = {};

    #pragma unroll
    for (int s = 0; s < 2; s++) {
        if (s < niter) {
            const int k0 = s * 64;
            #pragma unroll
            for (int w = 0; w < 4; w++) {
                int r = ldrow + w * 32;
                cpa16(sA0 + (s * NT_STG + r * 72 + hc8) * 2, Ab + (long)r * ldA + k0 + hc8);
                cpa16(sB0 + (s * NT_STG + r * 72 + hc8) * 2, Bb + (long)r * ldB + k0 + hc8);
            }
            cpcommit();
        }
    }

    int slot = 0, pslot = 2;
    for (int it = 0; it < niter; it++) {
        if (it < niter - 1) asm volatile("cp.async.wait_group 1;");
        else                asm volatile("cp.async.wait_group 0;");
        __syncthreads();

        const unsigned aBase = sA0 + slot * NT_STG * 2;
        const unsigned bBase = sB0 + slot * NT_STG * 2;
        #pragma unroll
        for (int kk = 0; kk < 4; kk++) {
            const int kb = kk * 16 + 8 * lblk;
            unsigned a[4][4], bb[4][2];
            #pragma unroll
            for (int mf = 0; mf < 4; mf++)
                ldsm4(a[mf][0], a[mf][1], a[mf][2], a[mf][3],
                      aBase + ((wm + mf * 16 + lrow) * 72 + kb) * 2);
            #pragma unroll
            for (int p = 0; p < 2; p++) {
                unsigned r0, r1, r2, r3;
                ldsm4(r0, r1, r2, r3, bBase + ((wn + p * 16 + lrow) * 72 + kb) * 2);
                bb[2 * p][0] = r0;
                bb[2 * p][1] = r2;
                bb[2 * p + 1][0] = r1;
                bb[2 * p + 1][1] = r3;
            }
            #pragma unroll
            for (int mf = 0; mf < 4; mf++)
                #pragma unroll
                for (int nf = 0; nf < 4; nf++) mma16h(acc[mf][nf], a[mf], bb[nf]);
        }

        if (it + 2 < niter) {
            const int k0 = (it + 2) * 64;
            #pragma unroll
            for (int w = 0; w < 4; w++) {
                int r = ldrow + w * 32;
                cpa16(sA0 + (pslot * NT_STG + r * 72 + hc8) * 2,
                      Ab + (long)r * ldA + k0 + hc8);
                cpa16(sB0 + (pslot * NT_STG + r * 72 + hc8) * 2,
                      Bb + (long)r * ldB + k0 + hc8);
            }
            cpcommit();
        }
        slot = (slot == 2) ? 0 : slot + 1;
        pslot = (pslot == 2) ? 0 : pslot + 1;
    }

    float* Cb = Cp + (long)bh * I * J;
    const float* rb = rbias ? rbias + (long)bh * I : nullptr;
    const float* cb = cbias ? cbias + (long)bh * J : nullptr;
    #pragma unroll
    for (int mf = 0; mf < 4; mf++)
        #pragma unroll
        for (int nf = 0; nf < 4; nf++) {
            int r0 = i0 + wm + mf * 16 + g;
            int c0 = j0 + wn + nf * 8 + 2 * t;
            #pragma unroll
            for (int ep = 0; ep < 2; ep++) {
                int rr = r0 + ep * 8;
                float v0 = acc[mf][nf][2 * ep] * alpha;
                float v1 = acc[mf][nf][2 * ep + 1] * alpha;
                if (rb) { v0 += rb[rr]; v1 += rb[rr]; }
                if (cb) { v0 += cb[c0]; v1 += cb[c0 + 1]; }
                *(float2*)&Cb[(long)rr * J + c0] = make_float2(v0, v1);
            }
        }
}

// ================= fp16 NN GEMM (value GEMMs): C = P(I,K)h @ V(K,64)h =================
__global__ void __launch_bounds__(256, 2)
mma_nn_h(const __half* __restrict__ A, long Ahs, int ldA,
         const __half* __restrict__ Bp, long Bbs, int ldB,
         float* __restrict__ Cp, __half* __restrict__ CpH,
         long Cbs, long Chs, int ldC,
         int K, int accumulate, int trailK, const float* __restrict__ addV) {
    const int bh = blockIdx.z, b = bh >> 3, h = bh & 7;
    const int i0 = trailK ? ((gridDim.y - 1 - blockIdx.y) * 128) : blockIdx.y * 128;
    const unsigned sA0 = (unsigned)__cvta_generic_to_shared(smem_u);
    const unsigned sB0 = sA0 + 3 * H_ASTG * 2;
    const __half* Ab = A + (long)bh * Ahs + (long)i0 * ldA;
    const __half* Bb = Bp + (long)b * Bbs + h * HDc;

    const int tid = threadIdx.x, wid = tid >> 5, lane = tid & 31;
    const int g = lane >> 2, t = lane & 3;
    const int wm = (wid & 1) * 64, wn = (wid >> 1) * 16;
    const int lrow = lane & 15, lblk = lane >> 4;
    const int ldrow = tid >> 3, hc8 = (tid & 7) * 8;
    const int trow = lane & 7, tsel = lane >> 3;
    const int tko = (tsel & 1) * 8 + trow;
    const int tno = wn + (tsel >> 1) * 8;

    const int Keff = trailK ? min(K, i0 + 128) : K;
    const int niter = Keff / 64;
    float acc[4][2][4] = {};

    #pragma unroll
    for (int s = 0; s < 2; s++) {
        if (s < niter) {
            const int k0 = s * 64;
            #pragma unroll
            for (int w = 0; w < 4; w++) {
                int r = ldrow + w * 32;
                cpa16(sA0 + (s * H_ASTG + r * 72 + hc8) * 2, Ab + (long)r * ldA + k0 + hc8);
            }
            #pragma unroll
            for (int w = 0; w < 2; w++) {
                int li = tid + w * 256;
                int r = li >> 3, c8 = (li & 7) * 8;
                cpa16(sB0 + (s * H_BSTG + r * 72 + c8) * 2, Bb + (long)(k0 + r) * ldB + c8);
            }
            cpcommit();
        }
    }

    int slot = 0, pslot = 2;
    for (int it = 0; it < niter; it++) {
        if (it < niter - 1) asm volatile("cp.async.wait_group 1;");
        else                asm volatile("cp.async.wait_group 0;");
        __syncthreads();

        const unsigned aBase = sA0 + slot * H_ASTG * 2;
        const unsigned bBase = sB0 + slot * H_BSTG * 2;
        #pragma unroll
        for (int kk = 0; kk < 4; kk++) {
            const int kb = kk * 16;
            unsigned a[4][4], bb[2][2];
            #pragma unroll
            for (int mf = 0; mf < 4; mf++)
                ldsm4(a[mf][0], a[mf][1], a[mf][2], a[mf][3],
                      aBase + ((wm + mf * 16 + lrow) * 72 + kb + 8 * lblk) * 2);
            {
                unsigned r0, r1, r2, r3;
                ldsm4t(r0, r1, r2, r3, bBase + ((kb + tko) * 72 + tno) * 2);
                bb[0][0] = r0; bb[0][1] = r1;
                bb[1][0] = r2; bb[1][1] = r3;
            }
            #pragma unroll
            for (int mf = 0; mf < 4; mf++)
                #pragma unroll
                for (int nf = 0; nf < 2; nf++) mma16h(acc[mf][nf], a[mf], bb[nf]);
        }

        if (it + 2 < niter) {
            const int k0 = (it + 2) * 64;
            #pragma unroll
            for (int w = 0; w < 4; w++) {
                int r = ldrow + w * 32;
                cpa16(sA0 + (pslot * H_ASTG + r * 72 + hc8) * 2,
                      Ab + (long)r * ldA + k0 + hc8);
            }
            #pragma unroll
            for (int w = 0; w < 2; w++) {
                int li = tid + w * 256;
                int r = li >> 3, c8 = (li & 7) * 8;
                cpa16(sB0 + (pslot * H_BSTG + r * 72 + c8) * 2,
                      Bb + (long)(k0 + r) * ldB + c8);
            }
            cpcommit();
        }
        slot = (slot == 2) ? 0 : slot + 1;
        pslot = (pslot == 2) ? 0 : pslot + 1;
    }

    const long baseoff = (long)b * Cbs + (long)h * Chs + (long)i0 * ldC;
    float* Cb = Cp + baseoff;
    __half* Ch = CpH ? CpH + baseoff : nullptr;
    const float* Xb = addV ? addV + baseoff : nullptr;
    #pragma unroll
    for (int mf = 0; mf < 4; mf++)
        #pragma unroll
        for (int nf = 0; nf < 2; nf++) {
            int r0 = wm + mf * 16 + g;
            int c0 = wn + nf * 8 + 2 * t;
            #pragma unroll
            for (int e = 0; e < 4; e++) {
                int rr = r0 + (e >> 1) * 8;
                int cc = c0 + (e & 1);
                float v = acc[mf][nf][e];
                long off = (long)rr * ldC + cc;
                if (accumulate) v += Cb[off];
                if (Xb) v += Xb[off];
                Cb[off] = v;
                if (Ch) Ch[off] = __float2half_rn(v);
            }
        }
}

// ================= fp16 wide NN GEMM (dense): C = A(I,K)h @ B(K,J)h + bias ============
// optional fused gate: v = sig(gGs)*gA2 + sig(v)*gB2. outF (f32) and/or outH (fp16).
__global__ void __launch_bounds__(256, 2)
mma_nn_wide_h(const __half* __restrict__ A, int ldA,
              const __half* __restrict__ Bp, int ldB,
              const float* __restrict__ bias,
              float* __restrict__ outF, __half* __restrict__ outH, int ldC,
              int K,
              const float* __restrict__ gGs, const float* __restrict__ gA2,
              const float* __restrict__ gB2) {
    const int col0 = blockIdx.x * 128, i0 = blockIdx.y * 128;
    const unsigned sA0 = (unsigned)__cvta_generic_to_shared(smem_u);
    const unsigned sB0 = sA0 + 3 * W_ASTG * 2;
    const __half* Ab = A + (long)i0 * ldA;
    const __half* Bb = Bp + col0;

    const int tid = threadIdx.x, wid = tid >> 5, lane = tid & 31;
    const int g = lane >> 2, t = lane & 3;
    const int wm = (wid & 1) * 64, wn = (wid >> 1) * 32;
    const int lrow = lane & 15, lblk = lane >> 4;
    const int ldrow = tid >> 3, hc8 = (tid & 7) * 8;
    const int trow = lane & 7, tsel = lane >> 3;
    const int tko = (tsel & 1) * 8 + trow;
    const int tnb = (tsel >> 1) * 8;

    const int niter = K / 64;
    float acc[4][4][4] = {};

    #pragma unroll
    for (int s = 0; s < 2; s++) {
        if (s < niter) {
            const int k0 = s * 64;
            #pragma unroll
            for (int w = 0; w < 4; w++) {
                int r = ldrow + w * 32;
                cpa16(sA0 + (s * W_ASTG + r * 72 + hc8) * 2, Ab + (long)r * ldA + k0 + hc8);
            }
            #pragma unroll
            for (int w = 0; w < 4; w++) {
                int li = tid + w * 256;
                int r = li >> 4, c8 = (li & 15) * 8;
                cpa16(sB0 + (s * W_BSTG + r * 136 + c8) * 2, Bb + (long)(k0 + r) * ldB + c8);
            }
            cpcommit();
        }
    }

    int slot = 0, pslot = 2;
    for (int it = 0; it < niter; it++) {
        if (it < niter - 1) asm volatile("cp.async.wait_group 1;");
        else                asm volatile("cp.async.wait_group 0;");
        __syncthreads();

        const unsigned aBase = sA0 + slot * W_ASTG * 2;
        const unsigned bBase = sB0 + slot * W_BSTG * 2;
        #pragma unroll
        for (int kk = 0; kk < 4; kk++) {
            const int kb = kk * 16;
            unsigned a[4][4], bb[4][2];
            #pragma unroll
            for (int mf = 0; mf < 4; mf++)
                ldsm4(a[mf][0], a[mf][1], a[mf][2], a[mf][3],
                      aBase + ((wm + mf * 16 + lrow) * 72 + kb + 8 * lblk) * 2);
            #pragma unroll
            for (int p = 0; p < 2; p++) {
                unsigned r0, r1, r2, r3;
                ldsm4t(r0, r1, r2, r3,
                       bBase + ((kb + tko) * 136 + wn + p * 16 + tnb) * 2);
                bb[2 * p][0] = r0; bb[2 * p][1] = r1;
                bb[2 * p + 1][0] = r2; bb[2 * p + 1][1] = r3;
            }
            #pragma unroll
            for (int mf = 0; mf < 4; mf++)
                #pragma unroll
                for (int nf = 0; nf < 4; nf++) mma16h(acc[mf][nf], a[mf], bb[nf]);
        }

        if (it + 2 < niter) {
            const int k0 = (it + 2) * 64;
            #pragma unroll
            for (int w = 0; w < 4; w++) {
                int r = ldrow + w * 32;
                cpa16(sA0 + (pslot * W_ASTG + r * 72 + hc8) * 2,
                      Ab + (long)r * ldA + k0 + hc8);
            }
            #pragma unroll
            for (int w = 0; w < 4; w++) {
                int li = tid + w * 256;
                int r = li >> 4, c8 = (li & 15) * 8;
                cpa16(sB0 + (pslot * W_BSTG + r * 136 + c8) * 2,
                      Bb + (long)(k0 + r) * ldB + c8);
            }
            cpcommit();
        }
        slot = (slot == 2) ? 0 : slot + 1;
        pslot = (pslot == 2) ? 0 : pslot + 1;
    }

    #pragma unroll
    for (int mf = 0; mf < 4; mf++)
        #pragma unroll
        for (int nf = 0; nf < 4; nf++) {
            int rr0 = i0 + wm + mf * 16 + g;
            int cc0 = col0 + wn + nf * 8 + 2 * t;
            #pragma unroll
            for (int e = 0; e < 4; e++) {
                int rr = rr0 + (e >> 1) * 8;
                int cc = cc0 + (e & 1);
                float v = acc[mf][nf][e];
                if (bias) v += bias[cc];
                long off = (long)rr * ldC + cc;
                if (gGs) {
                    float sg = 1.f / (1.f + expf(-gGs[off]));
                    float cg = 1.f / (1.f + expf(-v));
                    v = sg * gA2[off] + cg * gB2[off];
                }
                if (outF) outF[off] = v;
                if (outH) outH[off] = __float2half_rn(v);
            }
        }
}

// -------- f32 -> fp16 convert --------
__global__ void cvt_h(const float4* __restrict__ in, __half* __restrict__ out, int n4) {
    int i = blockIdx.x * blockDim.x + threadIdx.x;
    if (i >= n4) return;
    float4 v = in[i];
    __half2 h0 = __floats2half2_rn(v.x, v.y);
    __half2 h1 = __floats2half2_rn(v.z, v.w);
    uint2 u;
    u.x = *(unsigned*)&h0;
    u.y = *(unsigned*)&h1;
    *(uint2*)&out[i * 4] = u;
}

// -------- qs = q_x * w4xy (fp16) --------
__global__ void qscale(const __half* __restrict__ qkvh, const float* __restrict__ w4xy,
                       __half* __restrict__ qs, int rows) {
    int i = blockIdx.x * blockDim.x + threadIdx.x;
    if (i >= rows * Cc) return;
    int row = i >> 9, c = i & 511;
    float q = __half2float(qkvh[(long)row * C3c + c]);
    qs[i] = __float2half_rn(q * w4xy[c]);
}

// -------- dot products on fp16 qkv --------
__global__ void dotw(const __half* __restrict__ qkv, const float* __restrict__ w,
                     int rows, float* __restrict__ out) {
    int gw = (blockIdx.x * blockDim.x + threadIdx.x) >> 5;
    int lane = threadIdx.x & 31;
    if (gw >= BHc * rows) return;
    int bh = gw / rows, r = gw % rows;
    int b = bh >> 3, h = bh & 7;
    const __half* p = qkv + (long)(b * rows + r) * C3c + h * HDc;
    float s = __half2float(p[lane]) * w[h * HDc + lane]
            + __half2float(p[lane + 32]) * w[h * HDc + lane + 32];
    #pragma unroll
    for (int o = 16; o; o >>= 1) s += __shfl_xor_sync(0xffffffffu, s, o);
    if (lane == 0) out[gw] = s;
}

// -------- row softmax over M=256 -> fp16 --------
__global__ void softmax_row256(const float* __restrict__ in, __half* __restrict__ out) {
    long row = blockIdx.x;
    int tid = threadIdx.x;
    __shared__ float sh[8];
    float v = in[row * 256 + tid];
    float m = v;
    #pragma unroll
    for (int o = 16; o; o >>= 1) m = fmaxf(m, __shfl_xor_sync(0xffffffffu, m, o));
    if ((tid & 31) == 0) sh[tid >> 5] = m;
    __syncthreads();
    float bm = sh[0];
    #pragma unroll
    for (int i = 1; i < 8; i++) bm = fmaxf(bm, sh[i]);
    __syncthreads();
    float e = expf(v - bm);
    float s = e;
    #pragma unroll
    for (int o = 16; o; o >>= 1) s += __shfl_xor_sync(0xffffffffu, s, o);
    if ((tid & 31) == 0) sh[tid >> 5] = s;
    __syncthreads();
    float bs = 0.f;
    #pragma unroll
    for (int i = 0; i < 8; i++) bs += sh[i];
    out[row * 256 + tid] = __float2half_rn(e / bs);
}

// -------- column softmax over T=1024 -> fp16 --------
__global__ void softmax_col(const float* __restrict__ in, __half* __restrict__ out) {
    int bh = blockIdx.y;
    int mx = threadIdx.x & 63;
    int ty = threadIdx.x >> 6;
    int m = blockIdx.x * 64 + mx;
    const float* base = in + (long)bh * Tc * Mc + m;
    __shared__ float red[256];
    __shared__ float cstat[64];
    float acc = -3.4e38f;
    for (int t = ty; t < Tc; t += 4) acc = fmaxf(acc, base[(long)t * Mc]);
    red[threadIdx.x] = acc;
    __syncthreads();
    if (ty == 0)
        cstat[mx] = fmaxf(fmaxf(red[mx], red[64 + mx]), fmaxf(red[128 + mx], red[192 + mx]));
    __syncthreads();
    float cm = cstat[mx];
    __syncthreads();
    float s = 0.f;
    for (int t = ty; t < Tc; t += 4) s += expf(base[(long)t * Mc] - cm);
    red[threadIdx.x] = s;
    __syncthreads();
    if (ty == 0) cstat[mx] = red[mx] + red[64 + mx] + red[128 + mx] + red[192 + mx];
    __syncthreads();
    float inv = 1.f / cstat[mx];
    __half* ob = out + (long)bh * Tc * Mc + m;
    for (int t = ty; t < Tc; t += 4)
        ob[(long)t * Mc] = __float2half_rn(expf(base[(long)t * Mc] - cm) * inv);
}

// -------- causal row softmax: f32 scores -> fp16 probs --------
__global__ void softmax_causal(const float* __restrict__ buf, __half* __restrict__ outp) {
    long row = blockIdx.x;
    int t = (int)(row & 1023);
    const int len = ((t >> 7) + 1) << 7;
    const float* p = buf + row * 1024;
    __half* op = outp + row * 1024;
    int tid = threadIdx.x;
    __shared__ float sh[8];
    float v[4];
    float m = -3.4e38f;
    #pragma unroll
    for (int j = 0; j < 4; j++) {
        int s = tid + j * 256;
        float val = -3.4e38f;
        if (j * 256 < len) {
            if (s <= t) val = p[s];
        }
        v[j] = val;
        m = fmaxf(m, val);
    }
    #pragma unroll
    for (int o = 16; o; o >>= 1) m = fmaxf(m, __shfl_xor_sync(0xffffffffu, m, o));
    if ((tid & 31) == 0) sh[tid >> 5] = m;
    __syncthreads();
    float bm = sh[0];
    #pragma unroll
    for (int i = 1; i < 8; i++) bm = fmaxf(bm, sh[i]);
    __syncthreads();
    float sum = 0.f;
    #pragma unroll
    for (int j = 0; j < 4; j++) {
        int s = tid + j * 256;
        float e = 0.f;
        if (j * 256 < len) {
            if (s <= t) e = expf(v[j] - bm);
        }
        v[j] = e;
        sum += e;
    }
    #pragma unroll
    for (int o = 16; o; o >>= 1) sum += __shfl_xor_sync(0xffffffffu, sum, o);
    if ((tid & 31) == 0) sh[tid >> 5] = sum;
    __syncthreads();
    float bs = 0.f;
    #pragma unroll
    for (int i = 0; i < 8; i++) bs += sh[i];
    float inv = 1.f / bs;
    #pragma unroll
    for (int j = 0; j < 4; j++) {
        int s = tid + j * 256;
        if (j * 256 < len) {
            if (s < len) op[s] = __float2half_rn(v[j] * inv);
        }
    }
}

extern "C" void kernel_launch(void* const* d_in, const int* in_sizes, int n_in,
                              void* d_out, int out_size) {
    const float* x      = (const float*)d_in[0];
    const float* y      = (const float*)d_in[1];
    const float* Wqkv_x = (const float*)d_in[3];
    const float* bqkv_x = (const float*)d_in[4];
    const float* Wqkv_y = (const float*)d_in[5];
    const float* bqkv_y = (const float*)d_in[6];
    const float* w4x    = (const float*)d_in[7];
    const float* w4y    = (const float*)d_in[8];
    const float* w4xy   = (const float*)d_in[9];
    const float* Wgs    = (const float*)d_in[10];
    const float* bgs    = (const float*)d_in[11];
    const float* Wgc    = (const float*)d_in[12];
    const float* bgc    = (const float*)d_in[13];
    const float* Wp     = (const float*)d_in[14];
    const float* bp     = (const float*)d_in[15];
    float* out = (float*)d_out;

    cudaFuncSetAttribute(mma_nt_h, cudaFuncAttributeMaxDynamicSharedMemorySize, NT_SMEM);
    cudaFuncSetAttribute(mma_nn_h, cudaFuncAttributeMaxDynamicSharedMemorySize, H_SMEM);
    cudaFuncSetAttribute(mma_nn_wide_h, cudaFuncAttributeMaxDynamicSharedMemorySize, W_SMEM);

    __half *p_xh, *p_yh, *p_wqxh, *p_wqyh, *p_wgsh, *p_wgch, *p_wph,
           *p_qkvxh, *p_qkvyh, *p_qsh, *p_pxy, *p_y2xh, *p_bigh,
           *p_cvalh, *p_svalh, *p_zh;
    float *p_catt1, *p_catt2, *p_catt, *p_big, *p_big2, *p_cval, *p_sval, *p_gs;
    cudaGetSymbolAddress((void**)&p_xh, g_xh);
    cudaGetSymbolAddress((void**)&p_yh, g_yh);
    cudaGetSymbolAddress((void**)&p_wqxh, g_wqxh);
    cudaGetSymbolAddress((void**)&p_wqyh, g_wqyh);
    cudaGetSymbolAddress((void**)&p_wgsh, g_wgsh);
    cudaGetSymbolAddress((void**)&p_wgch, g_wgch);
    cudaGetSymbolAddress((void**)&p_wph, g_wph);
    cudaGetSymbolAddress((void**)&p_qkvxh, g_qkvxh);
    cudaGetSymbolAddress((void**)&p_qkvyh, g_qkvyh);
    cudaGetSymbolAddress((void**)&p_qsh, g_qsh);
    cudaGetSymbolAddress((void**)&p_pxy, g_pxy);
    cudaGetSymbolAddress((void**)&p_y2xh, g_y2xh);
    cudaGetSymbolAddress((void**)&p_bigh, g_bigh);
    cudaGetSymbolAddress((void**)&p_cvalh, g_cvalh);
    cudaGetSymbolAddress((void**)&p_svalh, g_svalh);
    cudaGetSymbolAddress((void**)&p_zh, g_zh);
    cudaGetSymbolAddress((void**)&p_catt1, g_catt1);
    cudaGetSymbolAddress((void**)&p_catt2, g_catt2);
    cudaGetSymbolAddress((void**)&p_catt, g_catt);
    cudaGetSymbolAddress((void**)&p_big, g_big);
    cudaGetSymbolAddress((void**)&p_big2, g_big2);
    cudaGetSymbolAddress((void**)&p_cval, g_cval);
    cudaGetSymbolAddress((void**)&p_sval, g_sval);
    cudaGetSymbolAddress((void**)&p_gs, g_gs);

    const float scale = 0.125f;
    const float invSqrtM = 0.0625f;

    // 0. fp16 conversions of harness tensors
    cvt_h<<<(Bc * Tc * Cc / 4 + 255) / 256, 256>>>((const float4*)x, p_xh, Bc * Tc * Cc / 4);
    cvt_h<<<(Bc * Mc * Cc / 4 + 255) / 256, 256>>>((const float4*)y, p_yh, Bc * Mc * Cc / 4);
    cvt_h<<<(Cc * C3c / 4 + 255) / 256, 256>>>((const float4*)Wqkv_x, p_wqxh, Cc * C3c / 4);
    cvt_h<<<(Cc * C3c / 4 + 255) / 256, 256>>>((const float4*)Wqkv_y, p_wqyh, Cc * C3c / 4);
    cvt_h<<<(Cc * Cc / 4 + 255) / 256, 256>>>((const float4*)Wgs, p_wgsh, Cc * Cc / 4);
    cvt_h<<<(Cc * Cc / 4 + 255) / 256, 256>>>((const float4*)Wgc, p_wgch, Cc * Cc / 4);
    cvt_h<<<(Cc * Cc / 4 + 255) / 256, 256>>>((const float4*)Wp, p_wph, Cc * Cc / 4);

    // 1-2. QKV projections (fp16 out only)
    mma_nn_wide_h<<<dim3(C3c / 128, (Bc * Tc) / 128), 256, W_SMEM>>>(
        p_xh, Cc, p_wqxh, C3c, bqkv_x, nullptr, p_qkvxh, C3c, Cc,
        nullptr, nullptr, nullptr);
    mma_nn_wide_h<<<dim3(C3c / 128, (Bc * Mc) / 128), 256, W_SMEM>>>(
        p_yh, Cc, p_wqyh, C3c, bqkv_y, nullptr, p_qkvyh, C3c, Cc,
        nullptr, nullptr, nullptr);
    // 3. catt1/catt2 + q scaling
    dotw<<<(BHc * Tc) / 8, 256>>>(p_qkvxh, w4x, Tc, p_catt1);
    dotw<<<(BHc * Mc) / 8, 256>>>(p_qkvyh, w4y, Mc, p_catt2);
    qscale<<<(Bc * Tc * Cc + 255) / 256, 256>>>(p_qkvxh, w4xy, p_qsh, Bc * Tc);
    // 4. satt scores (fp16 NT)
    mma_nt_h<<<dim3(Tc / 128, Tc / 128, BHc), 256, NT_SMEM>>>(
        p_qkvxh, (long)Tc * C3c, 64, C3c,
        p_qkvxh + Cc, (long)Tc * C3c, 64, C3c,
        nullptr, nullptr,
        p_big2, Tc, Tc, HDc, scale, 1);
    // 5. satt softmax -> fp16
    softmax_causal<<<BHc * Tc, 256>>>(p_big2, p_bigh);
    // 6. sval = satt @ v_x (f32 + fp16)
    mma_nn_h<<<dim3(1, Tc / 128, BHc), 256, H_SMEM>>>(
        p_bigh, (long)Tc * Tc, Tc,
        p_qkvxh + 2 * Cc, (long)Tc * C3c, C3c,
        p_sval, p_svalh, (long)Tc * Cc, HDc, Cc, Tc, 0, 1, nullptr);
    // 7. gs = sval @ Wgs + bgs (f32)
    mma_nn_wide_h<<<dim3(Cc / 128, (Bc * Tc) / 128), 256, W_SMEM>>>(
        p_svalh, Cc, p_wgsh, Cc, bgs, p_gs, nullptr, Cc, Cc,
        nullptr, nullptr, nullptr);

    // 8. catt scores (fp16 NT with biases)
    mma_nt_h<<<dim3(Mc / 128, Tc / 128, BHc), 256, NT_SMEM>>>(
        p_qsh, (long)Tc * Cc, 64, Cc,
        p_qkvyh + Cc, (long)Mc * C3c, 64, C3c,
        p_catt1, p_catt2,
        p_catt, Tc, Mc, HDc, scale, 0);
    // 9-10. softmaxes -> fp16
    softmax_row256<<<BHc * Tc, 256>>>(p_catt, p_pxy);
    softmax_col<<<dim3(Mc / 64, BHc), 256>>>(p_catt, p_y2xh);
    // 11. cval = x2y @ v_y (f32)
    mma_nn_h<<<dim3(1, Tc / 128, BHc), 256, H_SMEM>>>(
        p_pxy, (long)Tc * Mc, Mc,
        p_qkvyh + 2 * Cc, (long)Mc * C3c, C3c,
        p_cval, nullptr, (long)Tc * Cc, HDc, Cc, Mc, 0, 0, nullptr);
    // 12. chain scores (fp16 NT)
    mma_nt_h<<<dim3(Tc / 128, Tc / 128, BHc), 256, NT_SMEM>>>(
        p_pxy, 8L * Tc * Mc, (long)Tc * Mc, Mc,
        p_y2xh, 8L * Tc * Mc, (long)Tc * Mc, Mc,
        nullptr, nullptr,
        p_big, Tc, Tc, Mc, invSqrtM, 1);
    // 13. chain softmax -> fp16
    softmax_causal<<<BHc * Tc, 256>>>(p_big, p_bigh);
    // 14. cval += chain @ v_x + x  (f32 + fp16)
    mma_nn_h<<<dim3(1, Tc / 128, BHc), 256, H_SMEM>>>(
        p_bigh, (long)Tc * Tc, Tc,
        p_qkvxh + 2 * Cc, (long)Tc * C3c, C3c,
        p_cval, p_cvalh, (long)Tc * Cc, HDc, Cc, Tc, 1, 1, x);

    // 15. z = sig(gs)*cval + sig(cval@Wgc+bgc)*sval (fp16 out)
    mma_nn_wide_h<<<dim3(Cc / 128, (Bc * Tc) / 128), 256, W_SMEM>>>(
        p_cvalh, Cc, p_wgch, Cc, bgc, nullptr, p_zh, Cc, Cc,
        p_gs, p_cval, p_sval);

    // 16. out = z @ Wp + bp (f32)
    mma_nn_wide_h<<<dim3(Cc / 128, (Bc * Tc) / 128), 256, W_SMEM>>>(
        p_zh, Cc, p_wph, Cc, bp, out, nullptr, Cc, Cc,
        nullptr, nullptr, nullptr);
}

// round 14
// speedup vs baseline: 1.6315x; 1.1693x over previous
#include <cuda_runtime.h>
#include <cuda_bf16.h>
#include <cuda_fp16.h>
#include <math.h>

#define Bc 4
#define Tc 1024
#define Mc 256
#define Cc 512
#define Hc 8
#define HDc 64
#define C3c 1536
#define BHc 32

// ---------------- scratch ----------------
__device__ __half g_xh[Bc * Tc * Cc];
__device__ __half g_yh[Bc * Mc * Cc];
__device__ __half g_wqxh[Cc * C3c];
__device__ __half g_wqyh[Cc * C3c];
__device__ __half g_wgsh[Cc * Cc];
__device__ __half g_wgch[Cc * Cc];
__device__ __half g_wph[Cc * Cc];
__device__ __half g_qkvxh[Bc * Tc * C3c];
__device__ __half g_qkvyh[Bc * Mc * C3c];
__device__ __half g_qsh[Bc * Tc * Cc];
__device__ float g_catt1[BHc * Tc];
__device__ float g_catt2[BHc * Mc];
__device__ float g_catt[(long)BHc * Tc * Mc];
__device__ __half g_pxy[(long)BHc * Tc * Mc];
__device__ __half g_y2xh[(long)BHc * Tc * Mc];
__device__ float g_cval[Bc * Tc * Cc];
__device__ __half g_cvalh[Bc * Tc * Cc];
__device__ float g_sval[Bc * Tc * Cc];
__device__ __half g_svalh[Bc * Tc * Cc];
__device__ float g_gs[Bc * Tc * Cc];
__device__ __half g_zh[Bc * Tc * Cc];

// ---------------- helpers ----------------
__device__ __forceinline__ void mma16h(float* d, const unsigned* a, const unsigned* b) {
    asm volatile(
        "mma.sync.aligned.m16n8k16.row.col.f32.f16.f16.f32 "
        "{%0,%1,%2,%3},{%4,%5,%6,%7},{%8,%9},{%0,%1,%2,%3};"
        : "+f"(d[0]), "+f"(d[1]), "+f"(d[2]), "+f"(d[3])
        : "r"(a[0]), "r"(a[1]), "r"(a[2]), "r"(a[3]), "r"(b[0]), "r"(b[1]));
}
__device__ __forceinline__ void cpa16(unsigned dst, const void* src) {
    asm volatile("cp.async.cg.shared.global [%0], [%1], 16;" :: "r"(dst), "l"(src));
}
__device__ __forceinline__ void cpcommit() { asm volatile("cp.async.commit_group;"); }
__device__ __forceinline__ void ldsm4(unsigned& r0, unsigned& r1, unsigned& r2, unsigned& r3,
                                      unsigned addr) {
    asm volatile("ldmatrix.sync.aligned.m8n8.x4.shared.b16 {%0,%1,%2,%3},[%4];"
                 : "=r"(r0), "=r"(r1), "=r"(r2), "=r"(r3) : "r"(addr));
}
__device__ __forceinline__ void ldsm4t(unsigned& r0, unsigned& r1, unsigned& r2, unsigned& r3,
                                       unsigned addr) {
    asm volatile("ldmatrix.sync.aligned.m8n8.x4.trans.shared.b16 {%0,%1,%2,%3},[%4];"
                 : "=r"(r0), "=r"(r1), "=r"(r2), "=r"(r3) : "r"(addr));
}
__device__ __forceinline__ unsigned packh2(float lo, float hi) {
    __half2 h = __floats2half2_rn(lo, hi);
    return *(unsigned*)&h;
}

// pipelines (halfs)
#define NT_STG (128 * 72)
#define NT_SMEM (6 * NT_STG * 2)
#define H_ASTG (128 * 72)
#define H_BSTG (64 * 72)
#define H_SMEM ((3 * H_ASTG + 3 * H_BSTG) * 2)
#define W_ASTG (128 * 72)
#define W_BSTG (64 * 136)
#define W_SMEM ((3 * W_ASTG + 3 * W_BSTG) * 2)
// fused attention: Q[128][Kd+8] + K[128][Kd+8] + V[128][72], Kd max 256
#define FA_SMEM ((2 * 128 * 264 + 128 * 72) * 2)   // 153600 B

extern __shared__ unsigned smem_u[];

// ================= fused flash attention (causal) =================
// O[i] = softmax_causal(scale * A[i,:Kd] @ B[:,:Kd]^T) @ V    (+accumulate +addV)
// grid (Tc/128, BHc), 256 thr, 8 warps x 16 rows. Single-buffer smem.
__global__ void __launch_bounds__(256, 1)
fused_attn(const __half* __restrict__ Aq, long Abs, long Ahs, int ldA,
           const __half* __restrict__ Bk, long Bbs, long Bhs, int ldB,
           const __half* __restrict__ Vp, long Vbs, int ldV,
           float* __restrict__ Cp, __half* __restrict__ CpH,
           long Cbs, long Chs, int ldC,
           int Kd, float scale, int accumulate, const float* __restrict__ addV) {
    const int bh = blockIdx.y, b = bh >> 3, h = bh & 7;
    const int i0 = (gridDim.x - 1 - blockIdx.x) * 128;   // heavy blocks first
    const int tid = threadIdx.x, wid = tid >> 5, lane = tid & 31;
    const int g = lane >> 2, t = lane & 3;
    const int wr = wid * 16;
    const int lrow = lane & 15, lblk = lane >> 4;
    const int trow = lane & 7, tsel = lane >> 3;
    const int tko = (tsel & 1) * 8 + trow;
    const int tnb = (tsel >> 1) * 8;

    const int st = Kd + 8;                 // smem row stride (halfs)
    const int kd8 = Kd >> 3;
    const int kshift = (Kd == 64) ? 3 : 5;
    const unsigned sQ = (unsigned)__cvta_generic_to_shared(smem_u);
    const unsigned sK = sQ + 128 * st * 2;
    const unsigned sV = sK + 128 * st * 2;

    const __half* Ab = Aq + (long)b * Abs + (long)h * Ahs + (long)i0 * ldA;
    const __half* Bb = Bk + (long)b * Bbs + (long)h * Bhs;
    const __half* Vb = Vp + (long)b * Vbs + h * HDc;

    // load Q tile once
    const int nQ = Kd * 16;   // cpa16 ops
    for (int idx = tid; idx < nQ; idx += 256) {
        int r = idx >> kshift, c8 = (idx & (kd8 - 1)) * 8;
        cpa16(sQ + (r * st + c8) * 2, Ab + (long)r * ldA + c8);
    }
    cpcommit();

    const int nkc = Kd >> 4;
    float oAcc[8][4] = {};
    float m0 = -1e30f, m1 = -1e30f, sum0 = 0.f, sum1 = 0.f;

    for (int j0 = 0; j0 <= i0; j0 += 128) {
        // load K,V block
        for (int idx = tid; idx < nQ; idx += 256) {
            int r = idx >> kshift, c8 = (idx & (kd8 - 1)) * 8;
            cpa16(sK + (r * st + c8) * 2, Bb + (long)(j0 + r) * ldB + c8);
        }
        for (int idx = tid; idx < 1024; idx += 256) {
            int r = idx >> 3, c8 = (idx & 7) * 8;
            cpa16(sV + (r * 72 + c8) * 2, Vb + (long)(j0 + r) * ldV + c8);
        }
        cpcommit();
        asm volatile("cp.async.wait_group 0;");
        __syncthreads();

        // S = scale * Q @ K^T   (warp rows wr..wr+15, 128 kv cols)
        float s[16][4] = {};
        for (int kc = 0; kc < nkc; kc++) {
            unsigned a[4];
            ldsm4(a[0], a[1], a[2], a[3],
                  sQ + ((wr + lrow) * st + kc * 16 + 8 * lblk) * 2);
            #pragma unroll
            for (int q = 0; q < 8; q++) {
                unsigned r0, r1, r2, r3;
                ldsm4(r0, r1, r2, r3,
                      sK + ((q * 16 + lrow) * st + kc * 16 + 8 * lblk) * 2);
                unsigned b0[2] = {r0, r2}, b1[2] = {r1, r3};
                mma16h(s[2 * q], a, b0);
                mma16h(s[2 * q + 1], a, b1);
            }
        }
        // scale + causal mask (diagonal block only)
        const bool diag = (j0 == i0);
        #pragma unroll
        for (int nf = 0; nf < 16; nf++)
            #pragma unroll
            for (int e = 0; e < 4; e++) {
                float v = s[nf][e] * scale;
                if (diag) {
                    int row = wr + g + (e >> 1) * 8;
                    int col = 8 * nf + 2 * t + (e & 1);
                    if (col > row) v = -1e30f;
                }
                s[nf][e] = v;
            }
        // online softmax stats
        float mx0 = -1e30f, mx1 = -1e30f;
        #pragma unroll
        for (int nf = 0; nf < 16; nf++) {
            mx0 = fmaxf(mx0, fmaxf(s[nf][0], s[nf][1]));
            mx1 = fmaxf(mx1, fmaxf(s[nf][2], s[nf][3]));
        }
        #pragma unroll
        for (int o = 1; o <= 2; o <<= 1) {
            mx0 = fmaxf(mx0, __shfl_xor_sync(0xffffffffu, mx0, o));
            mx1 = fmaxf(mx1, __shfl_xor_sync(0xffffffffu, mx1, o));
        }
        float mn0 = fmaxf(m0, mx0), mn1 = fmaxf(m1, mx1);
        float f0 = expf(m0 - mn0), f1 = expf(m1 - mn1);
        sum0 *= f0; sum1 *= f1;
        #pragma unroll
        for (int nf = 0; nf < 8; nf++) {
            oAcc[nf][0] *= f0; oAcc[nf][1] *= f0;
            oAcc[nf][2] *= f1; oAcc[nf][3] *= f1;
        }
        float ps0 = 0.f, ps1 = 0.f;
        #pragma unroll
        for (int nf = 0; nf < 16; nf++) {
            float e0 = expf(s[nf][0] - mn0), e1 = expf(s[nf][1] - mn0);
            float e2 = expf(s[nf][2] - mn1), e3 = expf(s[nf][3] - mn1);
            s[nf][0] = e0; s[nf][1] = e1; s[nf][2] = e2; s[nf][3] = e3;
            ps0 += e0 + e1; ps1 += e2 + e3;
        }
        #pragma unroll
        for (int o = 1; o <= 2; o <<= 1) {
            ps0 += __shfl_xor_sync(0xffffffffu, ps0, o);
            ps1 += __shfl_xor_sync(0xffffffffu, ps1, o);
        }
        sum0 += ps0; sum1 += ps1;
        m0 = mn0; m1 = mn1;

        // O += P @ V  (kv chunks of 16)
        #pragma unroll
        for (int c = 0; c < 8; c++) {
            unsigned aP[4];
            aP[0] = packh2(s[2 * c][0], s[2 * c][1]);
            aP[1] = packh2(s[2 * c][2], s[2 * c][3]);
            aP[2] = packh2(s[2 * c + 1][0], s[2 * c + 1][1]);
            aP[3] = packh2(s[2 * c + 1][2], s[2 * c + 1][3]);
            #pragma unroll
            for (int q = 0; q < 4; q++) {
                unsigned r0, r1, r2, r3;
                ldsm4t(r0, r1, r2, r3,
                       sV + ((c * 16 + tko) * 72 + q * 16 + tnb) * 2);
                unsigned b0[2] = {r0, r1}, b1[2] = {r2, r3};
                mma16h(oAcc[2 * q], aP, b0);
                mma16h(oAcc[2 * q + 1], aP, b1);
            }
        }
        __syncthreads();
    }

    const float inv0 = 1.f / sum0, inv1 = 1.f / sum1;
    const long baseoff = (long)b * Cbs + (long)h * Chs + (long)i0 * ldC;
    float* Cb = Cp + baseoff;
    __half* Ch = CpH ? CpH + baseoff : nullptr;
    const float* Xb = addV ? addV + baseoff : nullptr;
    #pragma unroll
    for (int nf = 0; nf < 8; nf++)
        #pragma unroll
        for (int e = 0; e < 4; e++) {
            int row = wr + g + (e >> 1) * 8;
            int cc = 8 * nf + 2 * t + (e & 1);
            float v = oAcc[nf][e] * ((e >> 1) ? inv1 : inv0);
            long off = (long)row * ldC + cc;
            if (accumulate) v += Cb[off];
            if (Xb) v += Xb[off];
            Cb[off] = v;
            if (Ch) Ch[off] = __float2half_rn(v);
        }
}

// ================= fp16 NT GEMM (catt): C = alpha*A@B^T (+rb+cb) =================
__global__ void __launch_bounds__(256, 2)
mma_nt_h(const __half* __restrict__ A, long Abs, long Ahs, int ldA,
         const __half* __restrict__ Bp, long Bbs, long Bhs, int ldB,
         const float* __restrict__ rbias, const float* __restrict__ cbias,
         float* __restrict__ Cp, int I, int J, int K, float alpha, int causal) {
    const int bh = blockIdx.z, b = bh >> 3, h = bh & 7;
    const int j0 = blockIdx.x * 128;
    const int i0 = causal ? (I - 128 - blockIdx.y * 128) : blockIdx.y * 128;
    if (causal && j0 > i0) return;
    const unsigned sA0 = (unsigned)__cvta_generic_to_shared(smem_u);
    const unsigned sB0 = sA0 + 3 * NT_STG * 2;
    const __half* Ab = A + (long)b * Abs + (long)h * Ahs + (long)i0 * ldA;
    const __half* Bb = Bp + (long)b * Bbs + (long)h * Bhs + (long)j0 * ldB;

    const int tid = threadIdx.x, wid = tid >> 5, lane = tid & 31;
    const int g = lane >> 2, t = lane & 3;
    const int wm = (wid & 1) * 64, wn = (wid >> 1) * 32;
    const int lrow = lane & 15, lblk = lane >> 4;
    const int ldrow = tid >> 3, hc8 = (tid & 7) * 8;

    const int niter = K / 64;
    float acc[4][4][4] = {};

    #pragma unroll
    for (int s = 0; s < 2; s++) {
        if (s < niter) {
            const int k0 = s * 64;
            #pragma unroll
            for (int w = 0; w < 4; w++) {
                int r = ldrow + w * 32;
                cpa16(sA0 + (s * NT_STG + r * 72 + hc8) * 2, Ab + (long)r * ldA + k0 + hc8);
                cpa16(sB0 + (s * NT_STG + r * 72 + hc8) * 2, Bb + (long)r * ldB + k0 + hc8);
            }
            cpcommit();
        }
    }

    int slot = 0, pslot = 2;
    for (int it = 0; it < niter; it++) {
        if (it < niter - 1) asm volatile("cp.async.wait_group 1;");
        else                asm volatile("cp.async.wait_group 0;");
        __syncthreads();

        const unsigned aBase = sA0 + slot * NT_STG * 2;
        const unsigned bBase = sB0 + slot * NT_STG * 2;
        #pragma unroll
        for (int kk = 0; kk < 4; kk++) {
            const int kb = kk * 16 + 8 * lblk;
            unsigned a[4][4], bb[4][2];
            #pragma unroll
            for (int mf = 0; mf < 4; mf++)
                ldsm4(a[mf][0], a[mf][1], a[mf][2], a[mf][3],
                      aBase + ((wm + mf * 16 + lrow) * 72 + kb) * 2);
            #pragma unroll
            for (int p = 0; p < 2; p++) {
                unsigned r0, r1, r2, r3;
                ldsm4(r0, r1, r2, r3, bBase + ((wn + p * 16 + lrow) * 72 + kb) * 2);
                bb[2 * p][0] = r0;
                bb[2 * p][1] = r2;
                bb[2 * p + 1][0] = r1;
                bb[2 * p + 1][1] = r3;
            }
            #pragma unroll
            for (int mf = 0; mf < 4; mf++)
                #pragma unroll
                for (int nf = 0; nf < 4; nf++) mma16h(acc[mf][nf], a[mf], bb[nf]);
        }

        if (it + 2 < niter) {
            const int k0 = (it + 2) * 64;
            #pragma unroll
            for (int w = 0; w < 4; w++) {
                int r = ldrow + w * 32;
                cpa16(sA0 + (pslot * NT_STG + r * 72 + hc8) * 2,
                      Ab + (long)r * ldA + k0 + hc8);
                cpa16(sB0 + (pslot * NT_STG + r * 72 + hc8) * 2,
                      Bb + (long)r * ldB + k0 + hc8);
            }
            cpcommit();
        }
        slot = (slot == 2) ? 0 : slot + 1;
        pslot = (pslot == 2) ? 0 : pslot + 1;
    }

    float* Cb = Cp + (long)bh * I * J;
    const float* rb = rbias ? rbias + (long)bh * I : nullptr;
    const float* cb = cbias ? cbias + (long)bh * J : nullptr;
    #pragma unroll
    for (int mf = 0; mf < 4; mf++)
        #pragma unroll
        for (int nf = 0; nf < 4; nf++) {
            int r0 = i0 + wm + mf * 16 + g;
            int c0 = j0 + wn + nf * 8 + 2 * t;
            #pragma unroll
            for (int ep = 0; ep < 2; ep++) {
                int rr = r0 + ep * 8;
                float v0 = acc[mf][nf][2 * ep] * alpha;
                float v1 = acc[mf][nf][2 * ep + 1] * alpha;
                if (rb) { v0 += rb[rr]; v1 += rb[rr]; }
                if (cb) { v0 += cb[c0]; v1 += cb[c0 + 1]; }
                *(float2*)&Cb[(long)rr * J + c0] = make_float2(v0, v1);
            }
        }
}

// ================= fp16 NN GEMM (cval = x2y @ v_y) =================
__global__ void __launch_bounds__(256, 2)
mma_nn_h(const __half* __restrict__ A, long Ahs, int ldA,
         const __half* __restrict__ Bp, long Bbs, int ldB,
         float* __restrict__ Cp, __half* __restrict__ CpH,
         long Cbs, long Chs, int ldC, int K) {
    const int bh = blockIdx.z, b = bh >> 3, h = bh & 7;
    const int i0 = blockIdx.y * 128;
    const unsigned sA0 = (unsigned)__cvta_generic_to_shared(smem_u);
    const unsigned sB0 = sA0 + 3 * H_ASTG * 2;
    const __half* Ab = A + (long)bh * Ahs + (long)i0 * ldA;
    const __half* Bb = Bp + (long)b * Bbs + h * HDc;

    const int tid = threadIdx.x, wid = tid >> 5, lane = tid & 31;
    const int g = lane >> 2, t = lane & 3;
    const int wm = (wid & 1) * 64, wn = (wid >> 1) * 16;
    const int lrow = lane & 15, lblk = lane >> 4;
    const int ldrow = tid >> 3, hc8 = (tid & 7) * 8;
    const int trow = lane & 7, tsel = lane >> 3;
    const int tko = (tsel & 1) * 8 + trow;
    const int tno = wn + (tsel >> 1) * 8;

    const int niter = K / 64;
    float acc[4][2][4] = {};

    #pragma unroll
    for (int s = 0; s < 2; s++) {
        if (s < niter) {
            const int k0 = s * 64;
            #pragma unroll
            for (int w = 0; w < 4; w++) {
                int r = ldrow + w * 32;
                cpa16(sA0 + (s * H_ASTG + r * 72 + hc8) * 2, Ab + (long)r * ldA + k0 + hc8);
            }
            #pragma unroll
            for (int w = 0; w < 2; w++) {
                int li = tid + w * 256;
                int r = li >> 3, c8 = (li & 7) * 8;
                cpa16(sB0 + (s * H_BSTG + r * 72 + c8) * 2, Bb + (long)(k0 + r) * ldB + c8);
            }
            cpcommit();
        }
    }

    int slot = 0, pslot = 2;
    for (int it = 0; it < niter; it++) {
        if (it < niter - 1) asm volatile("cp.async.wait_group 1;");
        else                asm volatile("cp.async.wait_group 0;");
        __syncthreads();

        const unsigned aBase = sA0 + slot * H_ASTG * 2;
        const unsigned bBase = sB0 + slot * H_BSTG * 2;
        #pragma unroll
        for (int kk = 0; kk < 4; kk++) {
            const int kb = kk * 16;
            unsigned a[4][4], bb[2][2];
            #pragma unroll
            for (int mf = 0; mf < 4; mf++)
                ldsm4(a[mf][0], a[mf][1], a[mf][2], a[mf][3],
                      aBase + ((wm + mf * 16 + lrow) * 72 + kb + 8 * lblk) * 2);
            {
                unsigned r0, r1, r2, r3;
                ldsm4t(r0, r1, r2, r3, bBase + ((kb + tko) * 72 + tno) * 2);
                bb[0][0] = r0; bb[0][1] = r1;
                bb[1][0] = r2; bb[1][1] = r3;
            }
            #pragma unroll
            for (int mf = 0; mf < 4; mf++)
                #pragma unroll
                for (int nf = 0; nf < 2; nf++) mma16h(acc[mf][nf], a[mf], bb[nf]);
        }

        if (it + 2 < niter) {
            const int k0 = (it + 2) * 64;
            #pragma unroll
            for (int w = 0; w < 4; w++) {
                int r = ldrow + w * 32;
                cpa16(sA0 + (pslot * H_ASTG + r * 72 + hc8) * 2,
                      Ab + (long)r * ldA + k0 + hc8);
            }
            #pragma unroll
            for (int w = 0; w < 2; w++) {
                int li = tid + w * 256;
                int r = li >> 3, c8 = (li & 7) * 8;
                cpa16(sB0 + (pslot * H_BSTG + r * 72 + c8) * 2,
                      Bb + (long)(k0 + r) * ldB + c8);
            }
            cpcommit();
        }
        slot = (slot == 2) ? 0 : slot + 1;
        pslot = (pslot == 2) ? 0 : pslot + 1;
    }

    const long baseoff = (long)b * Cbs + (long)h * Chs + (long)i0 * ldC;
    float* Cb = Cp + baseoff;
    __half* Ch = CpH ? CpH + baseoff : nullptr;
    #pragma unroll
    for (int mf = 0; mf < 4; mf++)
        #pragma unroll
        for (int nf = 0; nf < 2; nf++) {
            int r0 = wm + mf * 16 + g;
            int c0 = wn + nf * 8 + 2 * t;
            #pragma unroll
            for (int e = 0; e < 4; e++) {
                int rr = r0 + (e >> 1) * 8;
                int cc = c0 + (e & 1);
                float v = acc[mf][nf][e];
                long off = (long)rr * ldC + cc;
                Cb[off] = v;
                if (Ch) Ch[off] = __float2half_rn(v);
            }
        }
}

// ================= fp16 wide NN GEMM (dense) =================
__global__ void __launch_bounds__(256, 2)
mma_nn_wide_h(const __half* __restrict__ A, int ldA,
              const __half* __restrict__ Bp, int ldB,
              const float* __restrict__ bias,
              float* __restrict__ outF, __half* __restrict__ outH, int ldC,
              int K,
              const float* __restrict__ gGs, const float* __restrict__ gA2,
              const float* __restrict__ gB2) {
    const int col0 = blockIdx.x * 128, i0 = blockIdx.y * 128;
    const unsigned sA0 = (unsigned)__cvta_generic_to_shared(smem_u);
    const unsigned sB0 = sA0 + 3 * W_ASTG * 2;
    const __half* Ab = A + (long)i0 * ldA;
    const __half* Bb = Bp + col0;

    const int tid = threadIdx.x, wid = tid >> 5, lane = tid & 31;
    const int g = lane >> 2, t = lane & 3;
    const int wm = (wid & 1) * 64, wn = (wid >> 1) * 32;
    const int lrow = lane & 15, lblk = lane >> 4;
    const int ldrow = tid >> 3, hc8 = (tid & 7) * 8;
    const int trow = lane & 7, tsel = lane >> 3;
    const int tko = (tsel & 1) * 8 + trow;
    const int tnb = (tsel >> 1) * 8;

    const int niter = K / 64;
    float acc[4][4][4] = {};

    #pragma unroll
    for (int s = 0; s < 2; s++) {
        if (s < niter) {
            const int k0 = s * 64;
            #pragma unroll
            for (int w = 0; w < 4; w++) {
                int r = ldrow + w * 32;
                cpa16(sA0 + (s * W_ASTG + r * 72 + hc8) * 2, Ab + (long)r * ldA + k0 + hc8);
            }
            #pragma unroll
            for (int w = 0; w < 4; w++) {
                int li = tid + w * 256;
                int r = li >> 4, c8 = (li & 15) * 8;
                cpa16(sB0 + (s * W_BSTG + r * 136 + c8) * 2, Bb + (long)(k0 + r) * ldB + c8);
            }
            cpcommit();
        }
    }

    int slot = 0, pslot = 2;
    for (int it = 0; it < niter; it++) {
        if (it < niter - 1) asm volatile("cp.async.wait_group 1;");
        else                asm volatile("cp.async.wait_group 0;");
        __syncthreads();

        const unsigned aBase = sA0 + slot * W_ASTG * 2;
        const unsigned bBase = sB0 + slot * W_BSTG * 2;
        #pragma unroll
        for (int kk = 0; kk < 4; kk++) {
            const int kb = kk * 16;
            unsigned a[4][4], bb[4][2];
            #pragma unroll
            for (int mf = 0; mf < 4; mf++)
                ldsm4(a[mf][0], a[mf][1], a[mf][2], a[mf][3],
                      aBase + ((wm + mf * 16 + lrow) * 72 + kb + 8 * lblk) * 2);
            #pragma unroll
            for (int p = 0; p < 2; p++) {
                unsigned r0, r1, r2, r3;
                ldsm4t(r0, r1, r2, r3,
                       bBase + ((kb + tko) * 136 + wn + p * 16 + tnb) * 2);
                bb[2 * p][0] = r0; bb[2 * p][1] = r1;
                bb[2 * p + 1][0] = r2; bb[2 * p + 1][1] = r3;
            }
            #pragma unroll
            for (int mf = 0; mf < 4; mf++)
                #pragma unroll
                for (int nf = 0; nf < 4; nf++) mma16h(acc[mf][nf], a[mf], bb[nf]);
        }

        if (it + 2 < niter) {
            const int k0 = (it + 2) * 64;
            #pragma unroll
            for (int w = 0; w < 4; w++) {
                int r = ldrow + w * 32;
                cpa16(sA0 + (pslot * W_ASTG + r * 72 + hc8) * 2,
                      Ab + (long)r * ldA + k0 + hc8);
            }
            #pragma unroll
            for (int w = 0; w < 4; w++) {
                int li = tid + w * 256;
                int r = li >> 4, c8 = (li & 15) * 8;
                cpa16(sB0 + (pslot * W_BSTG + r * 136 + c8) * 2,
                      Bb + (long)(k0 + r) * ldB + c8);
            }
            cpcommit();
        }
        slot = (slot == 2) ? 0 : slot + 1;
        pslot = (pslot == 2) ? 0 : pslot + 1;
    }

    #pragma unroll
    for (int mf = 0; mf < 4; mf++)
        #pragma unroll
        for (int nf = 0; nf < 4; nf++) {
            int rr0 = i0 + wm + mf * 16 + g;
            int cc0 = col0 + wn + nf * 8 + 2 * t;
            #pragma unroll
            for (int e = 0; e < 4; e++) {
                int rr = rr0 + (e >> 1) * 8;
                int cc = cc0 + (e & 1);
                float v = acc[mf][nf][e];
                if (bias) v += bias[cc];
                long off = (long)rr * ldC + cc;
                if (gGs) {
                    float sg = 1.f / (1.f + expf(-gGs[off]));
                    float cg = 1.f / (1.f + expf(-v));
                    v = sg * gA2[off] + cg * gB2[off];
                }
                if (outF) outF[off] = v;
                if (outH) outH[off] = __float2half_rn(v);
            }
        }
}

// -------- f32 -> fp16 --------
__global__ void cvt_h(const float4* __restrict__ in, __half* __restrict__ out, int n4) {
    int i = blockIdx.x * blockDim.x + threadIdx.x;
    if (i >= n4) return;
    float4 v = in[i];
    __half2 h0 = __floats2half2_rn(v.x, v.y);
    __half2 h1 = __floats2half2_rn(v.z, v.w);
    uint2 u;
    u.x = *(unsigned*)&h0;
    u.y = *(unsigned*)&h1;
    *(uint2*)&out[i * 4] = u;
}

// -------- qs = q_x * w4xy --------
__global__ void qscale(const __half* __restrict__ qkvh, const float* __restrict__ w4xy,
                       __half* __restrict__ qs, int rows) {
    int i = blockIdx.x * blockDim.x + threadIdx.x;
    if (i >= rows * Cc) return;
    int row = i >> 9, c = i & 511;
    float q = __half2float(qkvh[(long)row * C3c + c]);
    qs[i] = __float2half_rn(q * w4xy[c]);
}

// -------- dot products --------
__global__ void dotw(const __half* __restrict__ qkv, const float* __restrict__ w,
                     int rows, float* __restrict__ out) {
    int gw = (blockIdx.x * blockDim.x + threadIdx.x) >> 5;
    int lane = threadIdx.x & 31;
    if (gw >= BHc * rows) return;
    int bh = gw / rows, r = gw % rows;
    int b = bh >> 3, h = bh & 7;
    const __half* p = qkv + (long)(b * rows + r) * C3c + h * HDc;
    float s = __half2float(p[lane]) * w[h * HDc + lane]
            + __half2float(p[lane + 32]) * w[h * HDc + lane + 32];
    #pragma unroll
    for (int o = 16; o; o >>= 1) s += __shfl_xor_sync(0xffffffffu, s, o);
    if (lane == 0) out[gw] = s;
}

// -------- row softmax over M=256 -> fp16 --------
__global__ void softmax_row256(const float* __restrict__ in, __half* __restrict__ out) {
    long row = blockIdx.x;
    int tid = threadIdx.x;
    __shared__ float sh[8];
    float v = in[row * 256 + tid];
    float m = v;
    #pragma unroll
    for (int o = 16; o; o >>= 1) m = fmaxf(m, __shfl_xor_sync(0xffffffffu, m, o));
    if ((tid & 31) == 0) sh[tid >> 5] = m;
    __syncthreads();
    float bm = sh[0];
    #pragma unroll
    for (int i = 1; i < 8; i++) bm = fmaxf(bm, sh[i]);
    __syncthreads();
    float e = expf(v - bm);
    float s = e;
    #pragma unroll
    for (int o = 16; o; o >>= 1) s += __shfl_xor_sync(0xffffffffu, s, o);
    if ((tid & 31) == 0) sh[tid >> 5] = s;
    __syncthreads();
    float bs = 0.f;
    #pragma unroll
    for (int i = 0; i < 8; i++) bs += sh[i];
    out[row * 256 + tid] = __float2half_rn(e / bs);
}

// -------- column softmax over T=1024 -> fp16 --------
__global__ void softmax_col(const float* __restrict__ in, __half* __restrict__ out) {
    int bh = blockIdx.y;
    int mx = threadIdx.x & 63;
    int ty = threadIdx.x >> 6;
    int m = blockIdx.x * 64 + mx;
    const float* base = in + (long)bh * Tc * Mc + m;
    __shared__ float red[256];
    __shared__ float cstat[64];
    float acc = -3.4e38f;
    for (int t = ty; t < Tc; t += 4) acc = fmaxf(acc, base[(long)t * Mc]);
    red[threadIdx.x] = acc;
    __syncthreads();
    if (ty == 0)
        cstat[mx] = fmaxf(fmaxf(red[mx], red[64 + mx]), fmaxf(red[128 + mx], red[192 + mx]));
    __syncthreads();
    float cm = cstat[mx];
    __syncthreads();
    float s = 0.f;
    for (int t = ty; t < Tc; t += 4) s += expf(base[(long)t * Mc] - cm);
    red[threadIdx.x] = s;
    __syncthreads();
    if (ty == 0) cstat[mx] = red[mx] + red[64 + mx] + red[128 + mx] + red[192 + mx];
    __syncthreads();
    float inv = 1.f / cstat[mx];
    __half* ob = out + (long)bh * Tc * Mc + m;
    for (int t = ty; t < Tc; t += 4)
        ob[(long)t * Mc] = __float2half_rn(expf(base[(long)t * Mc] - cm) * inv);
}

extern "C" void kernel_launch(void* const* d_in, const int* in_sizes, int n_in,
                              void* d_out, int out_size) {
    const float* x      = (const float*)d_in[0];
    const float* y      = (const float*)d_in[1];
    const float* Wqkv_x = (const float*)d_in[3];
    const float* bqkv_x = (const float*)d_in[4];
    const float* Wqkv_y = (const float*)d_in[5];
    const float* bqkv_y = (const float*)d_in[6];
    const float* w4x    = (const float*)d_in[7];
    const float* w4y    = (const float*)d_in[8];
    const float* w4xy   = (const float*)d_in[9];
    const float* Wgs    = (const float*)d_in[10];
    const float* bgs    = (const float*)d_in[11];
    const float* Wgc    = (const float*)d_in[12];
    const float* bgc    = (const float*)d_in[13];
    const float* Wp     = (const float*)d_in[14];
    const float* bp     = (const float*)d_in[15];
    float* out = (float*)d_out;

    cudaFuncSetAttribute(mma_nt_h, cudaFuncAttributeMaxDynamicSharedMemorySize, NT_SMEM);
    cudaFuncSetAttribute(mma_nn_h, cudaFuncAttributeMaxDynamicSharedMemorySize, H_SMEM);
    cudaFuncSetAttribute(mma_nn_wide_h, cudaFuncAttributeMaxDynamicSharedMemorySize, W_SMEM);
    cudaFuncSetAttribute(fused_attn, cudaFuncAttributeMaxDynamicSharedMemorySize, FA_SMEM);

    __half *p_xh, *p_yh, *p_wqxh, *p_wqyh, *p_wgsh, *p_wgch, *p_wph,
           *p_qkvxh, *p_qkvyh, *p_qsh, *p_pxy, *p_y2xh,
           *p_cvalh, *p_svalh, *p_zh;
    float *p_catt1, *p_catt2, *p_catt, *p_cval, *p_sval, *p_gs;
    cudaGetSymbolAddress((void**)&p_xh, g_xh);
    cudaGetSymbolAddress((void**)&p_yh, g_yh);
    cudaGetSymbolAddress((void**)&p_wqxh, g_wqxh);
    cudaGetSymbolAddress((void**)&p_wqyh, g_wqyh);
    cudaGetSymbolAddress((void**)&p_wgsh, g_wgsh);
    cudaGetSymbolAddress((void**)&p_wgch, g_wgch);
    cudaGetSymbolAddress((void**)&p_wph, g_wph);
    cudaGetSymbolAddress((void**)&p_qkvxh, g_qkvxh);
    cudaGetSymbolAddress((void**)&p_qkvyh, g_qkvyh);
    cudaGetSymbolAddress((void**)&p_qsh, g_qsh);
    cudaGetSymbolAddress((void**)&p_pxy, g_pxy);
    cudaGetSymbolAddress((void**)&p_y2xh, g_y2xh);
    cudaGetSymbolAddress((void**)&p_cvalh, g_cvalh);
    cudaGetSymbolAddress((void**)&p_svalh, g_svalh);
    cudaGetSymbolAddress((void**)&p_zh, g_zh);
    cudaGetSymbolAddress((void**)&p_catt1, g_catt1);
    cudaGetSymbolAddress((void**)&p_catt2, g_catt2);
    cudaGetSymbolAddress((void**)&p_catt, g_catt);
    cudaGetSymbolAddress((void**)&p_cval, g_cval);
    cudaGetSymbolAddress((void**)&p_sval, g_sval);
    cudaGetSymbolAddress((void**)&p_gs, g_gs);

    const float scale = 0.125f;
    const float invSqrtM = 0.0625f;

    // 0. fp16 conversions
    cvt_h<<<(Bc * Tc * Cc / 4 + 255) / 256, 256>>>((const float4*)x, p_xh, Bc * Tc * Cc / 4);
    cvt_h<<<(Bc * Mc * Cc / 4 + 255) / 256, 256>>>((const float4*)y, p_yh, Bc * Mc * Cc / 4);
    cvt_h<<<(Cc * C3c / 4 + 255) / 256, 256>>>((const float4*)Wqkv_x, p_wqxh, Cc * C3c / 4);
    cvt_h<<<(Cc * C3c / 4 + 255) / 256, 256>>>((const float4*)Wqkv_y, p_wqyh, Cc * C3c / 4);
    cvt_h<<<(Cc * Cc / 4 + 255) / 256, 256>>>((const float4*)Wgs, p_wgsh, Cc * Cc / 4);
    cvt_h<<<(Cc * Cc / 4 + 255) / 256, 256>>>((const float4*)Wgc, p_wgch, Cc * Cc / 4);
    cvt_h<<<(Cc * Cc / 4 + 255) / 256, 256>>>((const float4*)Wp, p_wph, Cc * Cc / 4);

    // 1-2. QKV projections
    mma_nn_wide_h<<<dim3(C3c / 128, (Bc * Tc) / 128), 256, W_SMEM>>>(
        p_xh, Cc, p_wqxh, C3c, bqkv_x, nullptr, p_qkvxh, C3c, Cc,
        nullptr, nullptr, nullptr);
    mma_nn_wide_h<<<dim3(C3c / 128, (Bc * Mc) / 128), 256, W_SMEM>>>(
        p_yh, Cc, p_wqyh, C3c, bqkv_y, nullptr, p_qkvyh, C3c, Cc,
        nullptr, nullptr, nullptr);
    // 3. catt1/catt2 + q scaling
    dotw<<<(BHc * Tc) / 8, 256>>>(p_qkvxh, w4x, Tc, p_catt1);
    dotw<<<(BHc * Mc) / 8, 256>>>(p_qkvyh, w4y, Mc, p_catt2);
    qscale<<<(Bc * Tc * Cc + 255) / 256, 256>>>(p_qkvxh, w4xy, p_qsh, Bc * Tc);
    // 4. satt: fused flash -> sval (+fp16)
    fused_attn<<<dim3(Tc / 128, BHc), 256, FA_SMEM>>>(
        p_qkvxh, (long)Tc * C3c, 64, C3c,
        p_qkvxh + Cc, (long)Tc * C3c, 64, C3c,
        p_qkvxh + 2 * Cc, (long)Tc * C3c, C3c,
        p_sval, p_svalh, (long)Tc * Cc, HDc, Cc,
        HDc, scale, 0, nullptr);
    // 5. gs = sval @ Wgs + bgs
    mma_nn_wide_h<<<dim3(Cc / 128, (Bc * Tc) / 128), 256, W_SMEM>>>(
        p_svalh, Cc, p_wgsh, Cc, bgs, p_gs, nullptr, Cc, Cc,
        nullptr, nullptr, nullptr);

    // 6. catt scores
    mma_nt_h<<<dim3(Mc / 128, Tc / 128, BHc), 256, NT_SMEM>>>(
        p_qsh, (long)Tc * Cc, 64, Cc,
        p_qkvyh + Cc, (long)Mc * C3c, 64, C3c,
        p_catt1, p_catt2,
        p_catt, Tc, Mc, HDc, scale, 0);
    // 7-8. softmaxes -> fp16
    softmax_row256<<<BHc * Tc, 256>>>(p_catt, p_pxy);
    softmax_col<<<dim3(Mc / 64, BHc), 256>>>(p_catt, p_y2xh);
    // 9. cval = x2y @ v_y
    mma_nn_h<<<dim3(1, Tc / 128, BHc), 256, H_SMEM>>>(
        p_pxy, (long)Tc * Mc, Mc,
        p_qkvyh + 2 * Cc, (long)Mc * C3c, C3c,
        p_cval, nullptr, (long)Tc * Cc, HDc, Cc, Mc);
    // 10. chain: fused flash -> cval += chain@v_x + x (+fp16)
    fused_attn<<<dim3(Tc / 128, BHc), 256, FA_SMEM>>>(
        p_pxy, 8L * Tc * Mc, (long)Tc * Mc, Mc,
        p_y2xh, 8L * Tc * Mc, (long)Tc * Mc, Mc,
        p_qkvxh + 2 * Cc, (long)Tc * C3c, C3c,
        p_cval, p_cvalh, (long)Tc * Cc, HDc, Cc,
        Mc, invSqrtM, 1, x);

    // 11. z = sig(gs)*cval + sig(cval@Wgc+bgc)*sval
    mma_nn_wide_h<<<dim3(Cc / 128, (Bc * Tc) / 128), 256, W_SMEM>>>(
        p_cvalh, Cc, p_wgch, Cc, bgc, nullptr, p_zh, Cc, Cc,
        p_gs, p_cval, p_sval);

    // 12. out = z @ Wp + bp
    mma_nn_wide_h<<<dim3(Cc / 128, (Bc * Tc) / 128), 256, W_SMEM>>>(
        p_zh, Cc, p_wph, Cc, bp, out, nullptr, Cc, Cc,
        nullptr, nullptr, nullptr);
}

// round 15
// speedup vs baseline: 1.7049x; 1.0450x over previous
#include <cuda_runtime.h>
#include <cuda_bf16.h>
#include <cuda_fp16.h>
#include <math.h>

#define Bc 4
#define Tc 1024
#define Mc 256
#define Cc 512
#define Hc 8
#define HDc 64
#define C3c 1536
#define BHc 32

// ---------------- scratch ----------------
__device__ __half g_xh[Bc * Tc * Cc];
__device__ __half g_yh[Bc * Mc * Cc];
__device__ __half g_wqxh[Cc * C3c];
__device__ __half g_wqyh[Cc * C3c];
__device__ __half g_wgsh[Cc * Cc];
__device__ __half g_wgch[Cc * Cc];
__device__ __half g_wph[Cc * Cc];
__device__ __half g_qkvxh[Bc * Tc * C3c];
__device__ __half g_qkvyh[Bc * Mc * C3c];
__device__ __half g_qsh[Bc * Tc * Cc];
__device__ float g_catt1[BHc * Tc];
__device__ float g_catt2[BHc * Mc];
__device__ float g_catt[(long)BHc * Tc * Mc];
__device__ __half g_pxy[(long)BHc * Tc * Mc];
__device__ __half g_y2xh[(long)BHc * Tc * Mc];
__device__ float g_cval[Bc * Tc * Cc];
__device__ __half g_cvalh[Bc * Tc * Cc];
__device__ float g_sval[Bc * Tc * Cc];
__device__ __half g_svalh[Bc * Tc * Cc];
__device__ float g_gs[Bc * Tc * Cc];
__device__ __half g_zh[Bc * Tc * Cc];

// ---------------- helpers ----------------
__device__ __forceinline__ void mma16h(float* d, const unsigned* a, const unsigned* b) {
    asm volatile(
        "mma.sync.aligned.m16n8k16.row.col.f32.f16.f16.f32 "
        "{%0,%1,%2,%3},{%4,%5,%6,%7},{%8,%9},{%0,%1,%2,%3};"
        : "+f"(d[0]), "+f"(d[1]), "+f"(d[2]), "+f"(d[3])
        : "r"(a[0]), "r"(a[1]), "r"(a[2]), "r"(a[3]), "r"(b[0]), "r"(b[1]));
}
__device__ __forceinline__ void cpa16(unsigned dst, const void* src) {
    asm volatile("cp.async.cg.shared.global [%0], [%1], 16;" :: "r"(dst), "l"(src));
}
__device__ __forceinline__ void cpcommit() { asm volatile("cp.async.commit_group;"); }
__device__ __forceinline__ void ldsm4(unsigned& r0, unsigned& r1, unsigned& r2, unsigned& r3,
                                      unsigned addr) {
    asm volatile("ldmatrix.sync.aligned.m8n8.x4.shared.b16 {%0,%1,%2,%3},[%4];"
                 : "=r"(r0), "=r"(r1), "=r"(r2), "=r"(r3) : "r"(addr));
}
__device__ __forceinline__ void ldsm4t(unsigned& r0, unsigned& r1, unsigned& r2, unsigned& r3,
                                       unsigned addr) {
    asm volatile("ldmatrix.sync.aligned.m8n8.x4.trans.shared.b16 {%0,%1,%2,%3},[%4];"
                 : "=r"(r0), "=r"(r1), "=r"(r2), "=r"(r3) : "r"(addr));
}
__device__ __forceinline__ unsigned packh2(float lo, float hi) {
    __half2 h = __floats2half2_rn(lo, hi);
    return *(unsigned*)&h;
}

// pipelines (halfs)
#define NT_STG (128 * 72)
#define NT_SMEM (6 * NT_STG * 2)
#define H_ASTG (128 * 72)
#define H_BSTG (64 * 72)
#define H_SMEM ((3 * H_ASTG + 3 * H_BSTG) * 2)
#define W_ASTG (128 * 72)
#define W_BSTG (64 * 136)
#define W_SMEM ((3 * W_ASTG + 3 * W_BSTG) * 2)
// fused attn: Q + 2xK (ping-pong) + V.  chain Kd=256: 3*128*264*2 + 128*72*2 = 221184
#define FA_SMEM_MAX 221184

extern __shared__ unsigned smem_u[];

// ================= fused flash attention (causal, K double-buffered) =================
__global__ void __launch_bounds__(256, 1)
fused_attn(const __half* __restrict__ Aq, long Abs, long Ahs, int ldA,
           const __half* __restrict__ Bk, long Bbs, long Bhs, int ldB,
           const __half* __restrict__ Vp, long Vbs, int ldV,
           float* __restrict__ Cp, __half* __restrict__ CpH,
           long Cbs, long Chs, int ldC,
           int Kd, float scale, int accumulate, const float* __restrict__ addV) {
    const int bh = blockIdx.y, b = bh >> 3, h = bh & 7;
    const int i0 = (gridDim.x - 1 - blockIdx.x) * 128;
    const int tid = threadIdx.x, wid = tid >> 5, lane = tid & 31;
    const int g = lane >> 2, t = lane & 3;
    const int wr = wid * 16;
    const int lrow = lane & 15, lblk = lane >> 4;
    const int trow = lane & 7, tsel = lane >> 3;
    const int tko = (tsel & 1) * 8 + trow;
    const int tnb = (tsel >> 1) * 8;

    const int st = Kd + 8;
    const int kd8 = Kd >> 3;
    const int kshift = (Kd == 64) ? 3 : 5;
    const unsigned sQ = (unsigned)__cvta_generic_to_shared(smem_u);
    const unsigned sK0 = sQ + 128 * st * 2;
    const unsigned sK1 = sK0 + 128 * st * 2;
    const unsigned sV = sK1 + 128 * st * 2;

    const __half* Ab = Aq + (long)b * Abs + (long)h * Ahs + (long)i0 * ldA;
    const __half* Bb = Bk + (long)b * Bbs + (long)h * Bhs;
    const __half* Vb = Vp + (long)b * Vbs + h * HDc;

    const int nQ = Kd * 16;
    // Q + K0 + V0 in one group
    for (int idx = tid; idx < nQ; idx += 256) {
        int r = idx >> kshift, c8 = (idx & (kd8 - 1)) * 8;
        cpa16(sQ + (r * st + c8) * 2, Ab + (long)r * ldA + c8);
        cpa16(sK0 + (r * st + c8) * 2, Bb + (long)r * ldB + c8);
    }
    for (int idx = tid; idx < 1024; idx += 256) {
        int r = idx >> 3, c8 = (idx & 7) * 8;
        cpa16(sV + (r * 72 + c8) * 2, Vb + (long)r * ldV + c8);
    }
    cpcommit();

    const int nkc = Kd >> 4;
    const int nblk = i0 / 128 + 1;
    float oAcc[8][4] = {};
    float m0 = -1e30f, m1 = -1e30f, sum0 = 0.f, sum1 = 0.f;

    for (int jb = 0; jb < nblk; jb++) {
        const int j0 = jb * 128;
        asm volatile("cp.async.wait_group 0;");
        __syncthreads();
        const unsigned sKc = (jb & 1) ? sK1 : sK0;

        // S = scale * Q @ K^T
        float s[16][4] = {};
        for (int kc = 0; kc < nkc; kc++) {
            unsigned a[4];
            ldsm4(a[0], a[1], a[2], a[3],
                  sQ + ((wr + lrow) * st + kc * 16 + 8 * lblk) * 2);
            #pragma unroll
            for (int q = 0; q < 8; q++) {
                unsigned r0, r1, r2, r3;
                ldsm4(r0, r1, r2, r3,
                      sKc + ((q * 16 + lrow) * st + kc * 16 + 8 * lblk) * 2);
                unsigned b0[2] = {r0, r2}, b1[2] = {r1, r3};
                mma16h(s[2 * q], a, b0);
                mma16h(s[2 * q + 1], a, b1);
            }
        }
        // prefetch next K (hidden behind softmax + PV)
        if (jb + 1 < nblk) {
            const unsigned sKn = (jb & 1) ? sK0 : sK1;
            const __half* Bn = Bb + (long)(j0 + 128) * ldB;
            for (int idx = tid; idx < nQ; idx += 256) {
                int r = idx >> kshift, c8 = (idx & (kd8 - 1)) * 8;
                cpa16(sKn + (r * st + c8) * 2, Bn + (long)r * ldB + c8);
            }
            cpcommit();
        }

        // scale + causal mask
        const bool diag = (j0 == i0);
        #pragma unroll
        for (int nf = 0; nf < 16; nf++)
            #pragma unroll
            for (int e = 0; e < 4; e++) {
                float v = s[nf][e] * scale;
                if (diag) {
                    int row = wr + g + (e >> 1) * 8;
                    int col = 8 * nf + 2 * t + (e & 1);
                    if (col > row) v = -1e30f;
                }
                s[nf][e] = v;
            }
        // online softmax
        float mx0 = -1e30f, mx1 = -1e30f;
        #pragma unroll
        for (int nf = 0; nf < 16; nf++) {
            mx0 = fmaxf(mx0, fmaxf(s[nf][0], s[nf][1]));
            mx1 = fmaxf(mx1, fmaxf(s[nf][2], s[nf][3]));
        }
        #pragma unroll
        for (int o = 1; o <= 2; o <<= 1) {
            mx0 = fmaxf(mx0, __shfl_xor_sync(0xffffffffu, mx0, o));
            mx1 = fmaxf(mx1, __shfl_xor_sync(0xffffffffu, mx1, o));
        }
        float mn0 = fmaxf(m0, mx0), mn1 = fmaxf(m1, mx1);
        float f0 = __expf(m0 - mn0), f1 = __expf(m1 - mn1);
        sum0 *= f0; sum1 *= f1;
        #pragma unroll
        for (int nf = 0; nf < 8; nf++) {
            oAcc[nf][0] *= f0; oAcc[nf][1] *= f0;
            oAcc[nf][2] *= f1; oAcc[nf][3] *= f1;
        }
        float ps0 = 0.f, ps1 = 0.f;
        #pragma unroll
        for (int nf = 0; nf < 16; nf++) {
            float e0 = __expf(s[nf][0] - mn0), e1 = __expf(s[nf][1] - mn0);
            float e2 = __expf(s[nf][2] - mn1), e3 = __expf(s[nf][3] - mn1);
            s[nf][0] = e0; s[nf][1] = e1; s[nf][2] = e2; s[nf][3] = e3;
            ps0 += e0 + e1; ps1 += e2 + e3;
        }
        #pragma unroll
        for (int o = 1; o <= 2; o <<= 1) {
            ps0 += __shfl_xor_sync(0xffffffffu, ps0, o);
            ps1 += __shfl_xor_sync(0xffffffffu, ps1, o);
        }
        sum0 += ps0; sum1 += ps1;
        m0 = mn0; m1 = mn1;

        // O += P @ V
        #pragma unroll
        for (int c = 0; c < 8; c++) {
            unsigned aP[4];
            aP[0] = packh2(s[2 * c][0], s[2 * c][1]);
            aP[1] = packh2(s[2 * c][2], s[2 * c][3]);
            aP[2] = packh2(s[2 * c + 1][0], s[2 * c + 1][1]);
            aP[3] = packh2(s[2 * c + 1][2], s[2 * c + 1][3]);
            #pragma unroll
            for (int q = 0; q < 4; q++) {
                unsigned r0, r1, r2, r3;
                ldsm4t(r0, r1, r2, r3,
                       sV + ((c * 16 + tko) * 72 + q * 16 + tnb) * 2);
                unsigned b0[2] = {r0, r1}, b1[2] = {r2, r3};
                mma16h(oAcc[2 * q], aP, b0);
                mma16h(oAcc[2 * q + 1], aP, b1);
            }
        }
        __syncthreads();
        // prefetch next V (buffer now free)
        if (jb + 1 < nblk) {
            const __half* Vn = Vb + (long)(j0 + 128) * ldV;
            for (int idx = tid; idx < 1024; idx += 256) {
                int r = idx >> 3, c8 = (idx & 7) * 8;
                cpa16(sV + (r * 72 + c8) * 2, Vn + (long)r * ldV + c8);
            }
            cpcommit();
        }
    }

    const float inv0 = 1.f / sum0, inv1 = 1.f / sum1;
    const long baseoff = (long)b * Cbs + (long)h * Chs + (long)i0 * ldC;
    float* Cb = Cp + baseoff;
    __half* Ch = CpH ? CpH + baseoff : nullptr;
    const float* Xb = addV ? addV + baseoff : nullptr;
    #pragma unroll
    for (int nf = 0; nf < 8; nf++)
        #pragma unroll
        for (int e = 0; e < 4; e++) {
            int row = wr + g + (e >> 1) * 8;
            int cc = 8 * nf + 2 * t + (e & 1);
            float v = oAcc[nf][e] * ((e >> 1) ? inv1 : inv0);
            long off = (long)row * ldC + cc;
            if (accumulate) v += Cb[off];
            if (Xb) v += Xb[off];
            Cb[off] = v;
            if (Ch) Ch[off] = __float2half_rn(v);
        }
}

// ================= fp16 NT GEMM (catt) =================
__global__ void __launch_bounds__(256, 2)
mma_nt_h(const __half* __restrict__ A, long Abs, long Ahs, int ldA,
         const __half* __restrict__ Bp, long Bbs, long Bhs, int ldB,
         const float* __restrict__ rbias, const float* __restrict__ cbias,
         float* __restrict__ Cp, int I, int J, int K, float alpha, int causal) {
    const int bh = blockIdx.z, b = bh >> 3, h = bh & 7;
    const int j0 = blockIdx.x * 128;
    const int i0 = causal ? (I - 128 - blockIdx.y * 128) : blockIdx.y * 128;
    if (causal && j0 > i0) return;
    const unsigned sA0 = (unsigned)__cvta_generic_to_shared(smem_u);
    const unsigned sB0 = sA0 + 3 * NT_STG * 2;
    const __half* Ab = A + (long)b * Abs + (long)h * Ahs + (long)i0 * ldA;
    const __half* Bb = Bp + (long)b * Bbs + (long)h * Bhs + (long)j0 * ldB;

    const int tid = threadIdx.x, wid = tid >> 5, lane = tid & 31;
    const int g = lane >> 2, t = lane & 3;
    const int wm = (wid & 1) * 64, wn = (wid >> 1) * 32;
    const int lrow = lane & 15, lblk = lane >> 4;
    const int ldrow = tid >> 3, hc8 = (tid & 7) * 8;

    const int niter = K / 64;
    float acc[4][4][4] = {};

    #pragma unroll
    for (int s = 0; s < 2; s++) {
        if (s < niter) {
            const int k0 = s * 64;
            #pragma unroll
            for (int w = 0; w < 4; w++) {
                int r = ldrow + w * 32;
                cpa16(sA0 + (s * NT_STG + r * 72 + hc8) * 2, Ab + (long)r * ldA + k0 + hc8);
                cpa16(sB0 + (s * NT_STG + r * 72 + hc8) * 2, Bb + (long)r * ldB + k0 + hc8);
            }
            cpcommit();
        }
    }

    int slot = 0, pslot = 2;
    for (int it = 0; it < niter; it++) {
        if (it < niter - 1) asm volatile("cp.async.wait_group 1;");
        else                asm volatile("cp.async.wait_group 0;");
        __syncthreads();

        const unsigned aBase = sA0 + slot * NT_STG * 2;
        const unsigned bBase = sB0 + slot * NT_STG * 2;
        #pragma unroll
        for (int kk = 0; kk < 4; kk++) {
            const int kb = kk * 16 + 8 * lblk;
            unsigned a[4][4], bb[4][2];
            #pragma unroll
            for (int mf = 0; mf < 4; mf++)
                ldsm4(a[mf][0], a[mf][1], a[mf][2], a[mf][3],
                      aBase + ((wm + mf * 16 + lrow) * 72 + kb) * 2);
            #pragma unroll
            for (int p = 0; p < 2; p++) {
                unsigned r0, r1, r2, r3;
                ldsm4(r0, r1, r2, r3, bBase + ((wn + p * 16 + lrow) * 72 + kb) * 2);
                bb[2 * p][0] = r0;
                bb[2 * p][1] = r2;
                bb[2 * p + 1][0] = r1;
                bb[2 * p + 1][1] = r3;
            }
            #pragma unroll
            for (int mf = 0; mf < 4; mf++)
                #pragma unroll
                for (int nf = 0; nf < 4; nf++) mma16h(acc[mf][nf], a[mf], bb[nf]);
        }

        if (it + 2 < niter) {
            const int k0 = (it + 2) * 64;
            #pragma unroll
            for (int w = 0; w < 4; w++) {
                int r = ldrow + w * 32;
                cpa16(sA0 + (pslot * NT_STG + r * 72 + hc8) * 2,
                      Ab + (long)r * ldA + k0 + hc8);
                cpa16(sB0 + (pslot * NT_STG + r * 72 + hc8) * 2,
                      Bb + (long)r * ldB + k0 + hc8);
            }
            cpcommit();
        }
        slot = (slot == 2) ? 0 : slot + 1;
        pslot = (pslot == 2) ? 0 : pslot + 1;
    }

    float* Cb = Cp + (long)bh * I * J;
    const float* rb = rbias ? rbias + (long)bh * I : nullptr;
    const float* cb = cbias ? cbias + (long)bh * J : nullptr;
    #pragma unroll
    for (int mf = 0; mf < 4; mf++)
        #pragma unroll
        for (int nf = 0; nf < 4; nf++) {
            int r0 = i0 + wm + mf * 16 + g;
            int c0 = j0 + wn + nf * 8 + 2 * t;
            #pragma unroll
            for (int ep = 0; ep < 2; ep++) {
                int rr = r0 + ep * 8;
                float v0 = acc[mf][nf][2 * ep] * alpha;
                float v1 = acc[mf][nf][2 * ep + 1] * alpha;
                if (rb) { v0 += rb[rr]; v1 += rb[rr]; }
                if (cb) { v0 += cb[c0]; v1 += cb[c0 + 1]; }
                *(float2*)&Cb[(long)rr * J + c0] = make_float2(v0, v1);
            }
        }
}

// ================= fp16 NN GEMM (cval = x2y @ v_y) =================
__global__ void __launch_bounds__(256, 2)
mma_nn_h(const __half* __restrict__ A, long Ahs, int ldA,
         const __half* __restrict__ Bp, long Bbs, int ldB,
         float* __restrict__ Cp, __half* __restrict__ CpH,
         long Cbs, long Chs, int ldC, int K) {
    const int bh = blockIdx.z, b = bh >> 3, h = bh & 7;
    const int i0 = blockIdx.y * 128;
    const unsigned sA0 = (unsigned)__cvta_generic_to_shared(smem_u);
    const unsigned sB0 = sA0 + 3 * H_ASTG * 2;
    const __half* Ab = A + (long)bh * Ahs + (long)i0 * ldA;
    const __half* Bb = Bp + (long)b * Bbs + h * HDc;

    const int tid = threadIdx.x, wid = tid >> 5, lane = tid & 31;
    const int g = lane >> 2, t = lane & 3;
    const int wm = (wid & 1) * 64, wn = (wid >> 1) * 16;
    const int lrow = lane & 15, lblk = lane >> 4;
    const int ldrow = tid >> 3, hc8 = (tid & 7) * 8;
    const int trow = lane & 7, tsel = lane >> 3;
    const int tko = (tsel & 1) * 8 + trow;
    const int tno = wn + (tsel >> 1) * 8;

    const int niter = K / 64;
    float acc[4][2][4] = {};

    #pragma unroll
    for (int s = 0; s < 2; s++) {
        if (s < niter) {
            const int k0 = s * 64;
            #pragma unroll
            for (int w = 0; w < 4; w++) {
                int r = ldrow + w * 32;
                cpa16(sA0 + (s * H_ASTG + r * 72 + hc8) * 2, Ab + (long)r * ldA + k0 + hc8);
            }
            #pragma unroll
            for (int w = 0; w < 2; w++) {
                int li = tid + w * 256;
                int r = li >> 3, c8 = (li & 7) * 8;
                cpa16(sB0 + (s * H_BSTG + r * 72 + c8) * 2, Bb + (long)(k0 + r) * ldB + c8);
            }
            cpcommit();
        }
    }

    int slot = 0, pslot = 2;
    for (int it = 0; it < niter; it++) {
        if (it < niter - 1) asm volatile("cp.async.wait_group 1;");
        else                asm volatile("cp.async.wait_group 0;");
        __syncthreads();

        const unsigned aBase = sA0 + slot * H_ASTG * 2;
        const unsigned bBase = sB0 + slot * H_BSTG * 2;
        #pragma unroll
        for (int kk = 0; kk < 4; kk++) {
            const int kb = kk * 16;
            unsigned a[4][4], bb[2][2];
            #pragma unroll
            for (int mf = 0; mf < 4; mf++)
                ldsm4(a[mf][0], a[mf][1], a[mf][2], a[mf][3],
                      aBase + ((wm + mf * 16 + lrow) * 72 + kb + 8 * lblk) * 2);
            {
                unsigned r0, r1, r2, r3;
                ldsm4t(r0, r1, r2, r3, bBase + ((kb + tko) * 72 + tno) * 2);
                bb[0][0] = r0; bb[0][1] = r1;
                bb[1][0] = r2; bb[1][1] = r3;
            }
            #pragma unroll
            for (int mf = 0; mf < 4; mf++)
                #pragma unroll
                for (int nf = 0; nf < 2; nf++) mma16h(acc[mf][nf], a[mf], bb[nf]);
        }

        if (it + 2 < niter) {
            const int k0 = (it + 2) * 64;
            #pragma unroll
            for (int w = 0; w < 4; w++) {
                int r = ldrow + w * 32;
                cpa16(sA0 + (pslot * H_ASTG + r * 72 + hc8) * 2,
                      Ab + (long)r * ldA + k0 + hc8);
            }
            #pragma unroll
            for (int w = 0; w < 2; w++) {
                int li = tid + w * 256;
                int r = li >> 3, c8 = (li & 7) * 8;
                cpa16(sB0 + (pslot * H_BSTG + r * 72 + c8) * 2,
                      Bb + (long)(k0 + r) * ldB + c8);
            }
            cpcommit();
        }
        slot = (slot == 2) ? 0 : slot + 1;
        pslot = (pslot == 2) ? 0 : pslot + 1;
    }

    const long baseoff = (long)b * Cbs + (long)h * Chs + (long)i0 * ldC;
    float* Cb = Cp + baseoff;
    __half* Ch = CpH ? CpH + baseoff : nullptr;
    #pragma unroll
    for (int mf = 0; mf < 4; mf++)
        #pragma unroll
        for (int nf = 0; nf < 2; nf++) {
            int r0 = wm + mf * 16 + g;
            int c0 = wn + nf * 8 + 2 * t;
            #pragma unroll
            for (int e = 0; e < 4; e++) {
                int rr = r0 + (e >> 1) * 8;
                int cc = c0 + (e & 1);
                float v = acc[mf][nf][e];
                long off = (long)rr * ldC + cc;
                Cb[off] = v;
                if (Ch) Ch[off] = __float2half_rn(v);
            }
        }
}

// ================= fp16 wide NN GEMM (dense) =================
__global__ void __launch_bounds__(256, 2)
mma_nn_wide_h(const __half* __restrict__ A, int ldA,
              const __half* __restrict__ Bp, int ldB,
              const float* __restrict__ bias,
              float* __restrict__ outF, __half* __restrict__ outH, int ldC,
              int K,
              const float* __restrict__ gGs, const float* __restrict__ gA2,
              const float* __restrict__ gB2) {
    const int col0 = blockIdx.x * 128, i0 = blockIdx.y * 128;
    const unsigned sA0 = (unsigned)__cvta_generic_to_shared(smem_u);
    const unsigned sB0 = sA0 + 3 * W_ASTG * 2;
    const __half* Ab = A + (long)i0 * ldA;
    const __half* Bb = Bp + col0;

    const int tid = threadIdx.x, wid = tid >> 5, lane = tid & 31;
    const int g = lane >> 2, t = lane & 3;
    const int wm = (wid & 1) * 64, wn = (wid >> 1) * 32;
    const int lrow = lane & 15, lblk = lane >> 4;
    const int ldrow = tid >> 3, hc8 = (tid & 7) * 8;
    const int trow = lane & 7, tsel = lane >> 3;
    const int tko = (tsel & 1) * 8 + trow;
    const int tnb = (tsel >> 1) * 8;

    const int niter = K / 64;
    float acc[4][4][4] = {};

    #pragma unroll
    for (int s = 0; s < 2; s++) {
        if (s < niter) {
            const int k0 = s * 64;
            #pragma unroll
            for (int w = 0; w < 4; w++) {
                int r = ldrow + w * 32;
                cpa16(sA0 + (s * W_ASTG + r * 72 + hc8) * 2, Ab + (long)r * ldA + k0 + hc8);
            }
            #pragma unroll
            for (int w = 0; w < 4; w++) {
                int li = tid + w * 256;
                int r = li >> 4, c8 = (li & 15) * 8;
                cpa16(sB0 + (s * W_BSTG + r * 136 + c8) * 2, Bb + (long)(k0 + r) * ldB + c8);
            }
            cpcommit();
        }
    }

    int slot = 0, pslot = 2;
    for (int it = 0; it < niter; it++) {
        if (it < niter - 1) asm volatile("cp.async.wait_group 1;");
        else                asm volatile("cp.async.wait_group 0;");
        __syncthreads();

        const unsigned aBase = sA0 + slot * W_ASTG * 2;
        const unsigned bBase = sB0 + slot * W_BSTG * 2;
        #pragma unroll
        for (int kk = 0; kk < 4; kk++) {
            const int kb = kk * 16;
            unsigned a[4][4], bb[4][2];
            #pragma unroll
            for (int mf = 0; mf < 4; mf++)
                ldsm4(a[mf][0], a[mf][1], a[mf][2], a[mf][3],
                      aBase + ((wm + mf * 16 + lrow) * 72 + kb + 8 * lblk) * 2);
            #pragma unroll
            for (int p = 0; p < 2; p++) {
                unsigned r0, r1, r2, r3;
                ldsm4t(r0, r1, r2, r3,
                       bBase + ((kb + tko) * 136 + wn + p * 16 + tnb) * 2);
                bb[2 * p][0] = r0; bb[2 * p][1] = r1;
                bb[2 * p + 1][0] = r2; bb[2 * p + 1][1] = r3;
            }
            #pragma unroll
            for (int mf = 0; mf < 4; mf++)
                #pragma unroll
                for (int nf = 0; nf < 4; nf++) mma16h(acc[mf][nf], a[mf], bb[nf]);
        }

        if (it + 2 < niter) {
            const int k0 = (it + 2) * 64;
            #pragma unroll
            for (int w = 0; w < 4; w++) {
                int r = ldrow + w * 32;
                cpa16(sA0 + (pslot * W_ASTG + r * 72 + hc8) * 2,
                      Ab + (long)r * ldA + k0 + hc8);
            }
            #pragma unroll
            for (int w = 0; w < 4; w++) {
                int li = tid + w * 256;
                int r = li >> 4, c8 = (li & 15) * 8;
                cpa16(sB0 + (pslot * W_BSTG + r * 136 + c8) * 2,
                      Bb + (long)(k0 + r) * ldB + c8);
            }
            cpcommit();
        }
        slot = (slot == 2) ? 0 : slot + 1;
        pslot = (pslot == 2) ? 0 : pslot + 1;
    }

    #pragma unroll
    for (int mf = 0; mf < 4; mf++)
        #pragma unroll
        for (int nf = 0; nf < 4; nf++) {
            int rr0 = i0 + wm + mf * 16 + g;
            int cc0 = col0 + wn + nf * 8 + 2 * t;
            #pragma unroll
            for (int e = 0; e < 4; e++) {
                int rr = rr0 + (e >> 1) * 8;
                int cc = cc0 + (e & 1);
                float v = acc[mf][nf][e];
                if (bias) v += bias[cc];
                long off = (long)rr * ldC + cc;
                if (gGs) {
                    float sg = 1.f / (1.f + __expf(-gGs[off]));
                    float cg = 1.f / (1.f + __expf(-v));
                    v = sg * gA2[off] + cg * gB2[off];
                }
                if (outF) outF[off] = v;
                if (outH) outH[off] = __float2half_rn(v);
            }
        }
}

// -------- merged f32 -> fp16 convert (7 segments) --------
__global__ void cvt_all(const float4* s0, __half* d0, int n0,
                        const float4* s1, __half* d1, int n1,
                        const float4* s2, __half* d2, int n2,
                        const float4* s3, __half* d3, int n3,
                        const float4* s4, __half* d4, int n4c,
                        const float4* s5, __half* d5, int n5,
                        const float4* s6, __half* d6, int n6) {
    int i = blockIdx.x * blockDim.x + threadIdx.x;
    const float4* src; __half* dst; int li = i;
    if (li < n0) { src = s0; dst = d0; }
    else { li -= n0;
    if (li < n1) { src = s1; dst = d1; }
    else { li -= n1;
    if (li < n2) { src = s2; dst = d2; }
    else { li -= n2;
    if (li < n3) { src = s3; dst = d3; }
    else { li -= n3;
    if (li < n4c) { src = s4; dst = d4; }
    else { li -= n4c;
    if (li < n5) { src = s5; dst = d5; }
    else { li -= n5;
    if (li < n6) { src = s6; dst = d6; }
    else return; }}}}}}
    float4 v = src[li];
    __half2 h0 = __floats2half2_rn(v.x, v.y);
    __half2 h1 = __floats2half2_rn(v.z, v.w);
    uint2 u;
    u.x = *(unsigned*)&h0;
    u.y = *(unsigned*)&h1;
    *(uint2*)&dst[li * 4] = u;
}

// -------- qs = q_x * w4xy --------
__global__ void qscale(const __half* __restrict__ qkvh, const float* __restrict__ w4xy,
                       __half* __restrict__ qs, int rows) {
    int i = blockIdx.x * blockDim.x + threadIdx.x;
    if (i >= rows * Cc) return;
    int row = i >> 9, c = i & 511;
    float q = __half2float(qkvh[(long)row * C3c + c]);
    qs[i] = __float2half_rn(q * w4xy[c]);
}

// -------- dot products --------
__global__ void dotw(const __half* __restrict__ qkv, const float* __restrict__ w,
                     int rows, float* __restrict__ out) {
    int gw = (blockIdx.x * blockDim.x + threadIdx.x) >> 5;
    int lane = threadIdx.x & 31;
    if (gw >= BHc * rows) return;
    int bh = gw / rows, r = gw % rows;
    int b = bh >> 3, h = bh & 7;
    const __half* p = qkv + (long)(b * rows + r) * C3c + h * HDc;
    float s = __half2float(p[lane]) * w[h * HDc + lane]
            + __half2float(p[lane + 32]) * w[h * HDc + lane + 32];
    #pragma unroll
    for (int o = 16; o; o >>= 1) s += __shfl_xor_sync(0xffffffffu, s, o);
    if (lane == 0) out[gw] = s;
}

// -------- row softmax over M=256 -> fp16 --------
__global__ void softmax_row256(const float* __restrict__ in, __half* __restrict__ out) {
    long row = blockIdx.x;
    int tid = threadIdx.x;
    __shared__ float sh[8];
    float v = in[row * 256 + tid];
    float m = v;
    #pragma unroll
    for (int o = 16; o; o >>= 1) m = fmaxf(m, __shfl_xor_sync(0xffffffffu, m, o));
    if ((tid & 31) == 0) sh[tid >> 5] = m;
    __syncthreads();
    float bm = sh[0];
    #pragma unroll
    for (int i = 1; i < 8; i++) bm = fmaxf(bm, sh[i]);
    __syncthreads();
    float e = __expf(v - bm);
    float s = e;
    #pragma unroll
    for (int o = 16; o; o >>= 1) s += __shfl_xor_sync(0xffffffffu, s, o);
    if ((tid & 31) == 0) sh[tid >> 5] = s;
    __syncthreads();
    float bs = 0.f;
    #pragma unroll
    for (int i = 0; i < 8; i++) bs += sh[i];
    out[row * 256 + tid] = __float2half_rn(e / bs);
}

// -------- column softmax over T=1024 -> fp16 --------
__global__ void softmax_col(const float* __restrict__ in, __half* __restrict__ out) {
    int bh = blockIdx.y;
    int mx = threadIdx.x & 63;
    int ty = threadIdx.x >> 6;
    int m = blockIdx.x * 64 + mx;
    const float* base = in + (long)bh * Tc * Mc + m;
    __shared__ float red[256];
    __shared__ float cstat[64];
    float acc = -3.4e38f;
    for (int t = ty; t < Tc; t += 4) acc = fmaxf(acc, base[(long)t * Mc]);
    red[threadIdx.x] = acc;
    __syncthreads();
    if (ty == 0)
        cstat[mx] = fmaxf(fmaxf(red[mx], red[64 + mx]), fmaxf(red[128 + mx], red[192 + mx]));
    __syncthreads();
    float cm = cstat[mx];
    __syncthreads();
    float s = 0.f;
    for (int t = ty; t < Tc; t += 4) s += __expf(base[(long)t * Mc] - cm);
    red[threadIdx.x] = s;
    __syncthreads();
    if (ty == 0) cstat[mx] = red[mx] + red[64 + mx] + red[128 + mx] + red[192 + mx];
    __syncthreads();
    float inv = 1.f / cstat[mx];
    __half* ob = out + (long)bh * Tc * Mc + m;
    for (int t = ty; t < Tc; t += 4)
        ob[(long)t * Mc] = __float2half_rn(__expf(base[(long)t * Mc] - cm) * inv);
}

extern "C" void kernel_launch(void* const* d_in, const int* in_sizes, int n_in,
                              void* d_out, int out_size) {
    const float* x      = (const float*)d_in[0];
    const float* y      = (const float*)d_in[1];
    const float* Wqkv_x = (const float*)d_in[3];
    const float* bqkv_x = (const float*)d_in[4];
    const float* Wqkv_y = (const float*)d_in[5];
    const float* bqkv_y = (const float*)d_in[6];
    const float* w4x    = (const float*)d_in[7];
    const float* w4y    = (const float*)d_in[8];
    const float* w4xy   = (const float*)d_in[9];
    const float* Wgs    = (const float*)d_in[10];
    const float* bgs    = (const float*)d_in[11];
    const float* Wgc    = (const float*)d_in[12];
    const float* bgc    = (const float*)d_in[13];
    const float* Wp     = (const float*)d_in[14];
    const float* bp     = (const float*)d_in[15];
    float* out = (float*)d_out;

    cudaFuncSetAttribute(mma_nt_h, cudaFuncAttributeMaxDynamicSharedMemorySize, NT_SMEM);
    cudaFuncSetAttribute(mma_nn_h, cudaFuncAttributeMaxDynamicSharedMemorySize, H_SMEM);
    cudaFuncSetAttribute(mma_nn_wide_h, cudaFuncAttributeMaxDynamicSharedMemorySize, W_SMEM);
    cudaFuncSetAttribute(fused_attn, cudaFuncAttributeMaxDynamicSharedMemorySize, FA_SMEM_MAX);

    __half *p_xh, *p_yh, *p_wqxh, *p_wqyh, *p_wgsh, *p_wgch, *p_wph,
           *p_qkvxh, *p_qkvyh, *p_qsh, *p_pxy, *p_y2xh,
           *p_cvalh, *p_svalh, *p_zh;
    float *p_catt1, *p_catt2, *p_catt, *p_cval, *p_sval, *p_gs;
    cudaGetSymbolAddress((void**)&p_xh, g_xh);
    cudaGetSymbolAddress((void**)&p_yh, g_yh);
    cudaGetSymbolAddress((void**)&p_wqxh, g_wqxh);
    cudaGetSymbolAddress((void**)&p_wqyh, g_wqyh);
    cudaGetSymbolAddress((void**)&p_wgsh, g_wgsh);
    cudaGetSymbolAddress((void**)&p_wgch, g_wgch);
    cudaGetSymbolAddress((void**)&p_wph, g_wph);
    cudaGetSymbolAddress((void**)&p_qkvxh, g_qkvxh);
    cudaGetSymbolAddress((void**)&p_qkvyh, g_qkvyh);
    cudaGetSymbolAddress((void**)&p_qsh, g_qsh);
    cudaGetSymbolAddress((void**)&p_pxy, g_pxy);
    cudaGetSymbolAddress((void**)&p_y2xh, g_y2xh);
    cudaGetSymbolAddress((void**)&p_cvalh, g_cvalh);
    cudaGetSymbolAddress((void**)&p_svalh, g_svalh);
    cudaGetSymbolAddress((void**)&p_zh, g_zh);
    cudaGetSymbolAddress((void**)&p_catt1, g_catt1);
    cudaGetSymbolAddress((void**)&p_catt2, g_catt2);
    cudaGetSymbolAddress((void**)&p_catt, g_catt);
    cudaGetSymbolAddress((void**)&p_cval, g_cval);
    cudaGetSymbolAddress((void**)&p_sval, g_sval);
    cudaGetSymbolAddress((void**)&p_gs, g_gs);

    const float scale = 0.125f;
    const float invSqrtM = 0.0625f;

    // 0. merged fp16 conversions (one launch)
    {
        const int n0 = Bc * Tc * Cc / 4, n1 = Bc * Mc * Cc / 4;
        const int n2 = Cc * C3c / 4, n3 = Cc * C3c / 4;
        const int n4c = Cc * Cc / 4, n5 = Cc * Cc / 4, n6 = Cc * Cc / 4;
        const int ntot = n0 + n1 + n2 + n3 + n4c + n5 + n6;
        cvt_all<<<(ntot + 255) / 256, 256>>>(
            (const float4*)x, p_xh, n0,
            (const float4*)y, p_yh, n1,
            (const float4*)Wqkv_x, p_wqxh, n2,
            (const float4*)Wqkv_y, p_wqyh, n3,
            (const float4*)Wgs, p_wgsh, n4c,
            (const float4*)Wgc, p_wgch, n5,
            (const float4*)Wp, p_wph, n6);
    }

    // 1-2. QKV projections
    mma_nn_wide_h<<<dim3(C3c / 128, (Bc * Tc) / 128), 256, W_SMEM>>>(
        p_xh, Cc, p_wqxh, C3c, bqkv_x, nullptr, p_qkvxh, C3c, Cc,
        nullptr, nullptr, nullptr);
    mma_nn_wide_h<<<dim3(C3c / 128, (Bc * Mc) / 128), 256, W_SMEM>>>(
        p_yh, Cc, p_wqyh, C3c, bqkv_y, nullptr, p_qkvyh, C3c, Cc,
        nullptr, nullptr, nullptr);
    // 3. catt1/catt2 + q scaling
    dotw<<<(BHc * Tc) / 8, 256>>>(p_qkvxh, w4x, Tc, p_catt1);
    dotw<<<(BHc * Mc) / 8, 256>>>(p_qkvyh, w4y, Mc, p_catt2);
    qscale<<<(Bc * Tc * Cc + 255) / 256, 256>>>(p_qkvxh, w4xy, p_qsh, Bc * Tc);
    // 4. satt: fused flash -> sval (+fp16); Kd=64 smem = 4*128*72*2 = 73728
    fused_attn<<<dim3(Tc / 128, BHc), 256, 4 * 128 * 72 * 2>>>(
        p_qkvxh, (long)Tc * C3c, 64, C3c,
        p_qkvxh + Cc, (long)Tc * C3c, 64, C3c,
        p_qkvxh + 2 * Cc, (long)Tc * C3c, C3c,
        p_sval, p_svalh, (long)Tc * Cc, HDc, Cc,
        HDc, scale, 0, nullptr);
    // 5. gs = sval @ Wgs + bgs
    mma_nn_wide_h<<<dim3(Cc / 128, (Bc * Tc) / 128), 256, W_SMEM>>>(
        p_svalh, Cc, p_wgsh, Cc, bgs, p_gs, nullptr, Cc, Cc,
        nullptr, nullptr, nullptr);

    // 6. catt scores
    mma_nt_h<<<dim3(Mc / 128, Tc / 128, BHc), 256, NT_SMEM>>>(
        p_qsh, (long)Tc * Cc, 64, Cc,
        p_qkvyh + Cc, (long)Mc * C3c, 64, C3c,
        p_catt1, p_catt2,
        p_catt, Tc, Mc, HDc, scale, 0);
    // 7-8. softmaxes -> fp16
    softmax_row256<<<BHc * Tc, 256>>>(p_catt, p_pxy);
    softmax_col<<<dim3(Mc / 64, BHc), 256>>>(p_catt, p_y2xh);
    // 9. cval = x2y @ v_y
    mma_nn_h<<<dim3(1, Tc / 128, BHc), 256, H_SMEM>>>(
        p_pxy, (long)Tc * Mc, Mc,
        p_qkvyh + 2 * Cc, (long)Mc * C3c, C3c,
        p_cval, nullptr, (long)Tc * Cc, HDc, Cc, Mc);
    // 10. chain: fused flash -> cval += chain@v_x + x (+fp16); Kd=256 smem = 221184
    fused_attn<<<dim3(Tc / 128, BHc), 256, FA_SMEM_MAX>>>(
        p_pxy, 8L * Tc * Mc, (long)Tc * Mc, Mc,
        p_y2xh, 8L * Tc * Mc, (long)Tc * Mc, Mc,
        p_qkvxh + 2 * Cc, (long)Tc * C3c, C3c,
        p_cval, p_cvalh, (long)Tc * Cc, HDc, Cc,
        Mc, invSqrtM, 1, x);

    // 11. z = sig(gs)*cval + sig(cval@Wgc+bgc)*sval
    mma_nn_wide_h<<<dim3(Cc / 128, (Bc * Tc) / 128), 256, W_SMEM>>>(
        p_cvalh, Cc, p_wgch, Cc, bgc, nullptr, p_zh, Cc, Cc,
        p_gs, p_cval, p_sval);

    // 12. out = z @ Wp + bp
    mma_nn_wide_h<<<dim3(Cc / 128, (Bc * Tc) / 128), 256, W_SMEM>>>(
        p_zh, Cc, p_wph, Cc, bp, out, nullptr, Cc, Cc,
        nullptr, nullptr, nullptr);
}

// round 16
// speedup vs baseline: 1.7597x; 1.0322x over previous
#include <cuda_runtime.h>
#include <cuda_bf16.h>
#include <cuda_fp16.h>
#include <math.h>

#define Bc 4
#define Tc 1024
#define Mc 256
#define Cc 512
#define Hc 8
#define HDc 64
#define C3c 1536
#define BHc 32

// ---------------- scratch ----------------
__device__ __half g_xh[Bc * Tc * Cc];
__device__ __half g_yh[Bc * Mc * Cc];
__device__ __half g_wqxh[Cc * C3c];
__device__ __half g_wqyh[Cc * C3c];
__device__ __half g_wgsh[Cc * Cc];
__device__ __half g_wgch[Cc * Cc];
__device__ __half g_wph[Cc * Cc];
__device__ __half g_qkvxh[Bc * Tc * C3c];
__device__ __half g_qkvyh[Bc * Mc * C3c];
__device__ __half g_qsh[Bc * Tc * Cc];
__device__ float g_catt1[BHc * Tc];
__device__ float g_catt2[BHc * Mc];
__device__ float g_catt[(long)BHc * Tc * Mc];
__device__ __half g_pxy[(long)BHc * Tc * Mc];
__device__ __half g_y2xh[(long)BHc * Tc * Mc];
__device__ float g_cval[Bc * Tc * Cc];
__device__ __half g_cvalh[Bc * Tc * Cc];
__device__ __half g_svalh[Bc * Tc * Cc];
__device__ float g_gs[Bc * Tc * Cc];
__device__ __half g_zh[Bc * Tc * Cc];

// ---------------- helpers ----------------
__device__ __forceinline__ void mma16h(float* d, const unsigned* a, const unsigned* b) {
    asm volatile(
        "mma.sync.aligned.m16n8k16.row.col.f32.f16.f16.f32 "
        "{%0,%1,%2,%3},{%4,%5,%6,%7},{%8,%9},{%0,%1,%2,%3};"
        : "+f"(d[0]), "+f"(d[1]), "+f"(d[2]), "+f"(d[3])
        : "r"(a[0]), "r"(a[1]), "r"(a[2]), "r"(a[3]), "r"(b[0]), "r"(b[1]));
}
__device__ __forceinline__ void cpa16(unsigned dst, const void* src) {
    asm volatile("cp.async.cg.shared.global [%0], [%1], 16;" :: "r"(dst), "l"(src));
}
__device__ __forceinline__ void cpcommit() { asm volatile("cp.async.commit_group;"); }
__device__ __forceinline__ void ldsm4(unsigned& r0, unsigned& r1, unsigned& r2, unsigned& r3,
                                      unsigned addr) {
    asm volatile("ldmatrix.sync.aligned.m8n8.x4.shared.b16 {%0,%1,%2,%3},[%4];"
                 : "=r"(r0), "=r"(r1), "=r"(r2), "=r"(r3) : "r"(addr));
}
__device__ __forceinline__ void ldsm4t(unsigned& r0, unsigned& r1, unsigned& r2, unsigned& r3,
                                       unsigned addr) {
    asm volatile("ldmatrix.sync.aligned.m8n8.x4.trans.shared.b16 {%0,%1,%2,%3},[%4];"
                 : "=r"(r0), "=r"(r1), "=r"(r2), "=r"(r3) : "r"(addr));
}
__device__ __forceinline__ unsigned packh2(float lo, float hi) {
    __half2 h = __floats2half2_rn(lo, hi);
    return *(unsigned*)&h;
}

// pipelines (halfs)
#define NT_STG (128 * 72)
#define NT_SMEM (6 * NT_STG * 2)
#define H_ASTG (128 * 72)
#define H_BSTG (64 * 72)
#define H_SMEM ((3 * H_ASTG + 3 * H_BSTG) * 2)
#define W_ASTG (128 * 72)
#define W_BSTG (64 * 136)
#define W_SMEM ((3 * W_ASTG + 3 * W_BSTG) * 2)
#define FA_SMEM_MAX 221184

extern __shared__ unsigned smem_u[];

// ================= fused flash attention (causal, K double-buffered) =================
// Cp may be null (fp16-only output, no accumulate/addV).
__global__ void __launch_bounds__(256, 1)
fused_attn(const __half* __restrict__ Aq, long Abs, long Ahs, int ldA,
           const __half* __restrict__ Bk, long Bbs, long Bhs, int ldB,
           const __half* __restrict__ Vp, long Vbs, int ldV,
           float* __restrict__ Cp, __half* __restrict__ CpH,
           long Cbs, long Chs, int ldC,
           int Kd, float scale, int accumulate, const float* __restrict__ addV) {
    const int bh = blockIdx.y, b = bh >> 3, h = bh & 7;
    const int i0 = (gridDim.x - 1 - blockIdx.x) * 128;
    const int tid = threadIdx.x, wid = tid >> 5, lane = tid & 31;
    const int g = lane >> 2, t = lane & 3;
    const int wr = wid * 16;
    const int lrow = lane & 15, lblk = lane >> 4;
    const int trow = lane & 7, tsel = lane >> 3;
    const int tko = (tsel & 1) * 8 + trow;
    const int tnb = (tsel >> 1) * 8;

    const int st = Kd + 8;
    const int kd8 = Kd >> 3;
    const int kshift = (Kd == 64) ? 3 : 5;
    const unsigned sQ = (unsigned)__cvta_generic_to_shared(smem_u);
    const unsigned sK0 = sQ + 128 * st * 2;
    const unsigned sK1 = sK0 + 128 * st * 2;
    const unsigned sV = sK1 + 128 * st * 2;

    const __half* Ab = Aq + (long)b * Abs + (long)h * Ahs + (long)i0 * ldA;
    const __half* Bb = Bk + (long)b * Bbs + (long)h * Bhs;
    const __half* Vb = Vp + (long)b * Vbs + h * HDc;

    const int nQ = Kd * 16;
    for (int idx = tid; idx < nQ; idx += 256) {
        int r = idx >> kshift, c8 = (idx & (kd8 - 1)) * 8;
        cpa16(sQ + (r * st + c8) * 2, Ab + (long)r * ldA + c8);
        cpa16(sK0 + (r * st + c8) * 2, Bb + (long)r * ldB + c8);
    }
    for (int idx = tid; idx < 1024; idx += 256) {
        int r = idx >> 3, c8 = (idx & 7) * 8;
        cpa16(sV + (r * 72 + c8) * 2, Vb + (long)r * ldV + c8);
    }
    cpcommit();

    const int nkc = Kd >> 4;
    const int nblk = i0 / 128 + 1;
    float oAcc[8][4] = {};
    float m0 = -1e30f, m1 = -1e30f, sum0 = 0.f, sum1 = 0.f;

    for (int jb = 0; jb < nblk; jb++) {
        const int j0 = jb * 128;
        asm volatile("cp.async.wait_group 0;");
        __syncthreads();
        const unsigned sKc = (jb & 1) ? sK1 : sK0;

        float s[16][4] = {};
        for (int kc = 0; kc < nkc; kc++) {
            unsigned a[4];
            ldsm4(a[0], a[1], a[2], a[3],
                  sQ + ((wr + lrow) * st + kc * 16 + 8 * lblk) * 2);
            #pragma unroll
            for (int q = 0; q < 8; q++) {
                unsigned r0, r1, r2, r3;
                ldsm4(r0, r1, r2, r3,
                      sKc + ((q * 16 + lrow) * st + kc * 16 + 8 * lblk) * 2);
                unsigned b0[2] = {r0, r2}, b1[2] = {r1, r3};
                mma16h(s[2 * q], a, b0);
                mma16h(s[2 * q + 1], a, b1);
            }
        }
        if (jb + 1 < nblk) {
            const unsigned sKn = (jb & 1) ? sK0 : sK1;
            const __half* Bn = Bb + (long)(j0 + 128) * ldB;
            for (int idx = tid; idx < nQ; idx += 256) {
                int r = idx >> kshift, c8 = (idx & (kd8 - 1)) * 8;
                cpa16(sKn + (r * st + c8) * 2, Bn + (long)r * ldB + c8);
            }
            cpcommit();
        }

        const bool diag = (j0 == i0);
        #pragma unroll
        for (int nf = 0; nf < 16; nf++)
            #pragma unroll
            for (int e = 0; e < 4; e++) {
                float v = s[nf][e] * scale;
                if (diag) {
                    int row = wr + g + (e >> 1) * 8;
                    int col = 8 * nf + 2 * t + (e & 1);
                    if (col > row) v = -1e30f;
                }
                s[nf][e] = v;
            }
        float mx0 = -1e30f, mx1 = -1e30f;
        #pragma unroll
        for (int nf = 0; nf < 16; nf++) {
            mx0 = fmaxf(mx0, fmaxf(s[nf][0], s[nf][1]));
            mx1 = fmaxf(mx1, fmaxf(s[nf][2], s[nf][3]));
        }
        #pragma unroll
        for (int o = 1; o <= 2; o <<= 1) {
            mx0 = fmaxf(mx0, __shfl_xor_sync(0xffffffffu, mx0, o));
            mx1 = fmaxf(mx1, __shfl_xor_sync(0xffffffffu, mx1, o));
        }
        float mn0 = fmaxf(m0, mx0), mn1 = fmaxf(m1, mx1);
        float f0 = __expf(m0 - mn0), f1 = __expf(m1 - mn1);
        sum0 *= f0; sum1 *= f1;
        #pragma unroll
        for (int nf = 0; nf < 8; nf++) {
            oAcc[nf][0] *= f0; oAcc[nf][1] *= f0;
            oAcc[nf][2] *= f1; oAcc[nf][3] *= f1;
        }
        float ps0 = 0.f, ps1 = 0.f;
        #pragma unroll
        for (int nf = 0; nf < 16; nf++) {
            float e0 = __expf(s[nf][0] - mn0), e1 = __expf(s[nf][1] - mn0);
            float e2 = __expf(s[nf][2] - mn1), e3 = __expf(s[nf][3] - mn1);
            s[nf][0] = e0; s[nf][1] = e1; s[nf][2] = e2; s[nf][3] = e3;
            ps0 += e0 + e1; ps1 += e2 + e3;
        }
        #pragma unroll
        for (int o = 1; o <= 2; o <<= 1) {
            ps0 += __shfl_xor_sync(0xffffffffu, ps0, o);
            ps1 += __shfl_xor_sync(0xffffffffu, ps1, o);
        }
        sum0 += ps0; sum1 += ps1;
        m0 = mn0; m1 = mn1;

        #pragma unroll
        for (int c = 0; c < 8; c++) {
            unsigned aP[4];
            aP[0] = packh2(s[2 * c][0], s[2 * c][1]);
            aP[1] = packh2(s[2 * c][2], s[2 * c][3]);
            aP[2] = packh2(s[2 * c + 1][0], s[2 * c + 1][1]);
            aP[3] = packh2(s[2 * c + 1][2], s[2 * c + 1][3]);
            #pragma unroll
            for (int q = 0; q < 4; q++) {
                unsigned r0, r1, r2, r3;
                ldsm4t(r0, r1, r2, r3,
                       sV + ((c * 16 + tko) * 72 + q * 16 + tnb) * 2);
                unsigned b0[2] = {r0, r1}, b1[2] = {r2, r3};
                mma16h(oAcc[2 * q], aP, b0);
                mma16h(oAcc[2 * q + 1], aP, b1);
            }
        }
        __syncthreads();
        if (jb + 1 < nblk) {
            const __half* Vn = Vb + (long)(j0 + 128) * ldV;
            for (int idx = tid; idx < 1024; idx += 256) {
                int r = idx >> 3, c8 = (idx & 7) * 8;
                cpa16(sV + (r * 72 + c8) * 2, Vn + (long)r * ldV + c8);
            }
            cpcommit();
        }
    }

    const float inv0 = 1.f / sum0, inv1 = 1.f / sum1;
    const long baseoff = (long)b * Cbs + (long)h * Chs + (long)i0 * ldC;
    float* Cb = Cp ? Cp + baseoff : nullptr;
    __half* Ch = CpH ? CpH + baseoff : nullptr;
    const float* Xb = addV ? addV + baseoff : nullptr;
    #pragma unroll
    for (int nf = 0; nf < 8; nf++)
        #pragma unroll
        for (int e = 0; e < 4; e++) {
            int row = wr + g + (e >> 1) * 8;
            int cc = 8 * nf + 2 * t + (e & 1);
            float v = oAcc[nf][e] * ((e >> 1) ? inv1 : inv0);
            long off = (long)row * ldC + cc;
            if (accumulate && Cb) v += Cb[off];
            if (Xb) v += Xb[off];
            if (Cb) Cb[off] = v;
            if (Ch) Ch[off] = __float2half_rn(v);
        }
}

// ================= fp16 NT GEMM (catt) =================
__global__ void __launch_bounds__(256, 2)
mma_nt_h(const __half* __restrict__ A, long Abs, long Ahs, int ldA,
         const __half* __restrict__ Bp, long Bbs, long Bhs, int ldB,
         const float* __restrict__ rbias, const float* __restrict__ cbias,
         float* __restrict__ Cp, int I, int J, int K, float alpha, int causal) {
    const int bh = blockIdx.z, b = bh >> 3, h = bh & 7;
    const int j0 = blockIdx.x * 128;
    const int i0 = causal ? (I - 128 - blockIdx.y * 128) : blockIdx.y * 128;
    if (causal && j0 > i0) return;
    const unsigned sA0 = (unsigned)__cvta_generic_to_shared(smem_u);
    const unsigned sB0 = sA0 + 3 * NT_STG * 2;
    const __half* Ab = A + (long)b * Abs + (long)h * Ahs + (long)i0 * ldA;
    const __half* Bb = Bp + (long)b * Bbs + (long)h * Bhs + (long)j0 * ldB;

    const int tid = threadIdx.x, wid = tid >> 5, lane = tid & 31;
    const int g = lane >> 2, t = lane & 3;
    const int wm = (wid & 1) * 64, wn = (wid >> 1) * 32;
    const int lrow = lane & 15, lblk = lane >> 4;
    const int ldrow = tid >> 3, hc8 = (tid & 7) * 8;

    const int niter = K / 64;
    float acc[4][4][4] = {};

    #pragma unroll
    for (int s = 0; s < 2; s++) {
        if (s < niter) {
            const int k0 = s * 64;
            #pragma unroll
            for (int w = 0; w < 4; w++) {
                int r = ldrow + w * 32;
                cpa16(sA0 + (s * NT_STG + r * 72 + hc8) * 2, Ab + (long)r * ldA + k0 + hc8);
                cpa16(sB0 + (s * NT_STG + r * 72 + hc8) * 2, Bb + (long)r * ldB + k0 + hc8);
            }
            cpcommit();
        }
    }

    int slot = 0, pslot = 2;
    for (int it = 0; it < niter; it++) {
        if (it < niter - 1) asm volatile("cp.async.wait_group 1;");
        else                asm volatile("cp.async.wait_group 0;");
        __syncthreads();

        const unsigned aBase = sA0 + slot * NT_STG * 2;
        const unsigned bBase = sB0 + slot * NT_STG * 2;
        #pragma unroll
        for (int kk = 0; kk < 4; kk++) {
            const int kb = kk * 16 + 8 * lblk;
            unsigned a[4][4], bb[4][2];
            #pragma unroll
            for (int mf = 0; mf < 4; mf++)
                ldsm4(a[mf][0], a[mf][1], a[mf][2], a[mf][3],
                      aBase + ((wm + mf * 16 + lrow) * 72 + kb) * 2);
            #pragma unroll
            for (int p = 0; p < 2; p++) {
                unsigned r0, r1, r2, r3;
                ldsm4(r0, r1, r2, r3, bBase + ((wn + p * 16 + lrow) * 72 + kb) * 2);
                bb[2 * p][0] = r0;
                bb[2 * p][1] = r2;
                bb[2 * p + 1][0] = r1;
                bb[2 * p + 1][1] = r3;
            }
            #pragma unroll
            for (int mf = 0; mf < 4; mf++)
                #pragma unroll
                for (int nf = 0; nf < 4; nf++) mma16h(acc[mf][nf], a[mf], bb[nf]);
        }

        if (it + 2 < niter) {
            const int k0 = (it + 2) * 64;
            #pragma unroll
            for (int w = 0; w < 4; w++) {
                int r = ldrow + w * 32;
                cpa16(sA0 + (pslot * NT_STG + r * 72 + hc8) * 2,
                      Ab + (long)r * ldA + k0 + hc8);
                cpa16(sB0 + (pslot * NT_STG + r * 72 + hc8) * 2,
                      Bb + (long)r * ldB + k0 + hc8);
            }
            cpcommit();
        }
        slot = (slot == 2) ? 0 : slot + 1;
        pslot = (pslot == 2) ? 0 : pslot + 1;
    }

    float* Cb = Cp + (long)bh * I * J;
    const float* rb = rbias ? rbias + (long)bh * I : nullptr;
    const float* cb = cbias ? cbias + (long)bh * J : nullptr;
    #pragma unroll
    for (int mf = 0; mf < 4; mf++)
        #pragma unroll
        for (int nf = 0; nf < 4; nf++) {
            int r0 = i0 + wm + mf * 16 + g;
            int c0 = j0 + wn + nf * 8 + 2 * t;
            #pragma unroll
            for (int ep = 0; ep < 2; ep++) {
                int rr = r0 + ep * 8;
                float v0 = acc[mf][nf][2 * ep] * alpha;
                float v1 = acc[mf][nf][2 * ep + 1] * alpha;
                if (rb) { v0 += rb[rr]; v1 += rb[rr]; }
                if (cb) { v0 += cb[c0]; v1 += cb[c0 + 1]; }
                *(float2*)&Cb[(long)rr * J + c0] = make_float2(v0, v1);
            }
        }
}

// ================= fp16 NN GEMM (cval = x2y @ v_y) =================
__global__ void __launch_bounds__(256, 2)
mma_nn_h(const __half* __restrict__ A, long Ahs, int ldA,
         const __half* __restrict__ Bp, long Bbs, int ldB,
         float* __restrict__ Cp, __half* __restrict__ CpH,
         long Cbs, long Chs, int ldC, int K) {
    const int bh = blockIdx.z, b = bh >> 3, h = bh & 7;
    const int i0 = blockIdx.y * 128;
    const unsigned sA0 = (unsigned)__cvta_generic_to_shared(smem_u);
    const unsigned sB0 = sA0 + 3 * H_ASTG * 2;
    const __half* Ab = A + (long)bh * Ahs + (long)i0 * ldA;
    const __half* Bb = Bp + (long)b * Bbs + h * HDc;

    const int tid = threadIdx.x, wid = tid >> 5, lane = tid & 31;
    const int g = lane >> 2, t = lane & 3;
    const int wm = (wid & 1) * 64, wn = (wid >> 1) * 16;
    const int lrow = lane & 15, lblk = lane >> 4;
    const int ldrow = tid >> 3, hc8 = (tid & 7) * 8;
    const int trow = lane & 7, tsel = lane >> 3;
    const int tko = (tsel & 1) * 8 + trow;
    const int tno = wn + (tsel >> 1) * 8;

    const int niter = K / 64;
    float acc[4][2][4] = {};

    #pragma unroll
    for (int s = 0; s < 2; s++) {
        if (s < niter) {
            const int k0 = s * 64;
            #pragma unroll
            for (int w = 0; w < 4; w++) {
                int r = ldrow + w * 32;
                cpa16(sA0 + (s * H_ASTG + r * 72 + hc8) * 2, Ab + (long)r * ldA + k0 + hc8);
            }
            #pragma unroll
            for (int w = 0; w < 2; w++) {
                int li = tid + w * 256;
                int r = li >> 3, c8 = (li & 7) * 8;
                cpa16(sB0 + (s * H_BSTG + r * 72 + c8) * 2, Bb + (long)(k0 + r) * ldB + c8);
            }
            cpcommit();
        }
    }

    int slot = 0, pslot = 2;
    for (int it = 0; it < niter; it++) {
        if (it < niter - 1) asm volatile("cp.async.wait_group 1;");
        else                asm volatile("cp.async.wait_group 0;");
        __syncthreads();

        const unsigned aBase = sA0 + slot * H_ASTG * 2;
        const unsigned bBase = sB0 + slot * H_BSTG * 2;
        #pragma unroll
        for (int kk = 0; kk < 4; kk++) {
            const int kb = kk * 16;
            unsigned a[4][4], bb[2][2];
            #pragma unroll
            for (int mf = 0; mf < 4; mf++)
                ldsm4(a[mf][0], a[mf][1], a[mf][2], a[mf][3],
                      aBase + ((wm + mf * 16 + lrow) * 72 + kb + 8 * lblk) * 2);
            {
                unsigned r0, r1, r2, r3;
                ldsm4t(r0, r1, r2, r3, bBase + ((kb + tko) * 72 + tno) * 2);
                bb[0][0] = r0; bb[0][1] = r1;
                bb[1][0] = r2; bb[1][1] = r3;
            }
            #pragma unroll
            for (int mf = 0; mf < 4; mf++)
                #pragma unroll
                for (int nf = 0; nf < 2; nf++) mma16h(acc[mf][nf], a[mf], bb[nf]);
        }

        if (it + 2 < niter) {
            const int k0 = (it + 2) * 64;
            #pragma unroll
            for (int w = 0; w < 4; w++) {
                int r = ldrow + w * 32;
                cpa16(sA0 + (pslot * H_ASTG + r * 72 + hc8) * 2,
                      Ab + (long)r * ldA + k0 + hc8);
            }
            #pragma unroll
            for (int w = 0; w < 2; w++) {
                int li = tid + w * 256;
                int r = li >> 3, c8 = (li & 7) * 8;
                cpa16(sB0 + (pslot * H_BSTG + r * 72 + c8) * 2,
                      Bb + (long)(k0 + r) * ldB + c8);
            }
            cpcommit();
        }
        slot = (slot == 2) ? 0 : slot + 1;
        pslot = (pslot == 2) ? 0 : pslot + 1;
    }

    const long baseoff = (long)b * Cbs + (long)h * Chs + (long)i0 * ldC;
    float* Cb = Cp + baseoff;
    __half* Ch = CpH ? CpH + baseoff : nullptr;
    #pragma unroll
    for (int mf = 0; mf < 4; mf++)
        #pragma unroll
        for (int nf = 0; nf < 2; nf++) {
            int r0 = wm + mf * 16 + g;
            int c0 = wn + nf * 8 + 2 * t;
            #pragma unroll
            for (int e = 0; e < 4; e++) {
                int rr = r0 + (e >> 1) * 8;
                int cc = c0 + (e & 1);
                float v = acc[mf][nf][e];
                long off = (long)rr * ldC + cc;
                Cb[off] = v;
                if (Ch) Ch[off] = __float2half_rn(v);
            }
        }
}

// ================= fp16 wide NN GEMM (dense) =================
// gate: v = sig(gGs)*gA2 + sig(v)*gB2h  (gB2h fp16)
__global__ void __launch_bounds__(256, 2)
mma_nn_wide_h(const __half* __restrict__ A, int ldA,
              const __half* __restrict__ Bp, int ldB,
              const float* __restrict__ bias,
              float* __restrict__ outF, __half* __restrict__ outH, int ldC,
              int K,
              const float* __restrict__ gGs, const float* __restrict__ gA2,
              const __half* __restrict__ gB2h) {
    const int col0 = blockIdx.x * 128, i0 = blockIdx.y * 128;
    const unsigned sA0 = (unsigned)__cvta_generic_to_shared(smem_u);
    const unsigned sB0 = sA0 + 3 * W_ASTG * 2;
    const __half* Ab = A + (long)i0 * ldA;
    const __half* Bb = Bp + col0;

    const int tid = threadIdx.x, wid = tid >> 5, lane = tid & 31;
    const int g = lane >> 2, t = lane & 3;
    const int wm = (wid & 1) * 64, wn = (wid >> 1) * 32;
    const int lrow = lane & 15, lblk = lane >> 4;
    const int ldrow = tid >> 3, hc8 = (tid & 7) * 8;
    const int trow = lane & 7, tsel = lane >> 3;
    const int tko = (tsel & 1) * 8 + trow;
    const int tnb = (tsel >> 1) * 8;

    const int niter = K / 64;
    float acc[4][4][4] = {};

    #pragma unroll
    for (int s = 0; s < 2; s++) {
        if (s < niter) {
            const int k0 = s * 64;
            #pragma unroll
            for (int w = 0; w < 4; w++) {
                int r = ldrow + w * 32;
                cpa16(sA0 + (s * W_ASTG + r * 72 + hc8) * 2, Ab + (long)r * ldA + k0 + hc8);
            }
            #pragma unroll
            for (int w = 0; w < 4; w++) {
                int li = tid + w * 256;
                int r = li >> 4, c8 = (li & 15) * 8;
                cpa16(sB0 + (s * W_BSTG + r * 136 + c8) * 2, Bb + (long)(k0 + r) * ldB + c8);
            }
            cpcommit();
        }
    }

    int slot = 0, pslot = 2;
    for (int it = 0; it < niter; it++) {
        if (it < niter - 1) asm volatile("cp.async.wait_group 1;");
        else                asm volatile("cp.async.wait_group 0;");
        __syncthreads();

        const unsigned aBase = sA0 + slot * W_ASTG * 2;
        const unsigned bBase = sB0 + slot * W_BSTG * 2;
        #pragma unroll
        for (int kk = 0; kk < 4; kk++) {
            const int kb = kk * 16;
            unsigned a[4][4], bb[4][2];
            #pragma unroll
            for (int mf = 0; mf < 4; mf++)
                ldsm4(a[mf][0], a[mf][1], a[mf][2], a[mf][3],
                      aBase + ((wm + mf * 16 + lrow) * 72 + kb + 8 * lblk) * 2);
            #pragma unroll
            for (int p = 0; p < 2; p++) {
                unsigned r0, r1, r2, r3;
                ldsm4t(r0, r1, r2, r3,
                       bBase + ((kb + tko) * 136 + wn + p * 16 + tnb) * 2);
                bb[2 * p][0] = r0; bb[2 * p][1] = r1;
                bb[2 * p + 1][0] = r2; bb[2 * p + 1][1] = r3;
            }
            #pragma unroll
            for (int mf = 0; mf < 4; mf++)
                #pragma unroll
                for (int nf = 0; nf < 4; nf++) mma16h(acc[mf][nf], a[mf], bb[nf]);
        }

        if (it + 2 < niter) {
            const int k0 = (it + 2) * 64;
            #pragma unroll
            for (int w = 0; w < 4; w++) {
                int r = ldrow + w * 32;
                cpa16(sA0 + (pslot * W_ASTG + r * 72 + hc8) * 2,
                      Ab + (long)r * ldA + k0 + hc8);
            }
            #pragma unroll
            for (int w = 0; w < 4; w++) {
                int li = tid + w * 256;
                int r = li >> 4, c8 = (li & 15) * 8;
                cpa16(sB0 + (pslot * W_BSTG + r * 136 + c8) * 2,
                      Bb + (long)(k0 + r) * ldB + c8);
            }
            cpcommit();
        }
        slot = (slot == 2) ? 0 : slot + 1;
        pslot = (pslot == 2) ? 0 : pslot + 1;
    }

    #pragma unroll
    for (int mf = 0; mf < 4; mf++)
        #pragma unroll
        for (int nf = 0; nf < 4; nf++) {
            int rr0 = i0 + wm + mf * 16 + g;
            int cc0 = col0 + wn + nf * 8 + 2 * t;
            #pragma unroll
            for (int e = 0; e < 4; e++) {
                int rr = rr0 + (e >> 1) * 8;
                int cc = cc0 + (e & 1);
                float v = acc[mf][nf][e];
                if (bias) v += bias[cc];
                long off = (long)rr * ldC + cc;
                if (gGs) {
                    float sg = 1.f / (1.f + __expf(-gGs[off]));
                    float cg = 1.f / (1.f + __expf(-v));
                    v = sg * gA2[off] + cg * __half2float(gB2h[off]);
                }
                if (outF) outF[off] = v;
                if (outH) outH[off] = __float2half_rn(v);
            }
        }
}

// -------- merged f32 -> fp16 convert (7 segments) --------
__global__ void cvt_all(const float4* s0, __half* d0, int n0,
                        const float4* s1, __half* d1, int n1,
                        const float4* s2, __half* d2, int n2,
                        const float4* s3, __half* d3, int n3,
                        const float4* s4, __half* d4, int n4c,
                        const float4* s5, __half* d5, int n5,
                        const float4* s6, __half* d6, int n6) {
    int i = blockIdx.x * blockDim.x + threadIdx.x;
    const float4* src; __half* dst; int li = i;
    if (li < n0) { src = s0; dst = d0; }
    else { li -= n0;
    if (li < n1) { src = s1; dst = d1; }
    else { li -= n1;
    if (li < n2) { src = s2; dst = d2; }
    else { li -= n2;
    if (li < n3) { src = s3; dst = d3; }
    else { li -= n3;
    if (li < n4c) { src = s4; dst = d4; }
    else { li -= n4c;
    if (li < n5) { src = s5; dst = d5; }
    else { li -= n5;
    if (li < n6) { src = s6; dst = d6; }
    else return; }}}}}}
    float4 v = src[li];
    __half2 h0 = __floats2half2_rn(v.x, v.y);
    __half2 h1 = __floats2half2_rn(v.z, v.w);
    uint2 u;
    u.x = *(unsigned*)&h0;
    u.y = *(unsigned*)&h1;
    *(uint2*)&dst[li * 4] = u;
}

// -------- fused: catt1 = q_x.w4x per (bh,t)  AND  qs = q_x * w4xy (fp16) --------
__global__ void dotw_qs(const __half* __restrict__ qkv, const float* __restrict__ w4x,
                        const float* __restrict__ w4xy,
                        float* __restrict__ out, __half* __restrict__ qs) {
    int gw = (blockIdx.x * blockDim.x + threadIdx.x) >> 5;
    int lane = threadIdx.x & 31;
    if (gw >= BHc * Tc) return;
    int bh = gw / Tc, r = gw % Tc;
    int b = bh >> 3, h = bh & 7;
    const __half* p = qkv + (long)(b * Tc + r) * C3c + h * HDc;
    float q0 = __half2float(p[lane]);
    float q1 = __half2float(p[lane + 32]);
    float s = q0 * w4x[h * HDc + lane] + q1 * w4x[h * HDc + lane + 32];
    #pragma unroll
    for (int o = 16; o; o >>= 1) s += __shfl_xor_sync(0xffffffffu, s, o);
    if (lane == 0) out[gw] = s;
    __half* qrow = qs + (long)(b * Tc + r) * Cc + h * HDc;
    qrow[lane] = __float2half_rn(q0 * w4xy[h * HDc + lane]);
    qrow[lane + 32] = __float2half_rn(q1 * w4xy[h * HDc + lane + 32]);
}

// -------- catt2 dot products --------
__global__ void dotw(const __half* __restrict__ qkv, const float* __restrict__ w,
                     int rows, float* __restrict__ out) {
    int gw = (blockIdx.x * blockDim.x + threadIdx.x) >> 5;
    int lane = threadIdx.x & 31;
    if (gw >= BHc * rows) return;
    int bh = gw / rows, r = gw % rows;
    int b = bh >> 3, h = bh & 7;
    const __half* p = qkv + (long)(b * rows + r) * C3c + h * HDc;
    float s = __half2float(p[lane]) * w[h * HDc + lane]
            + __half2float(p[lane + 32]) * w[h * HDc + lane + 32];
    #pragma unroll
    for (int o = 16; o; o >>= 1) s += __shfl_xor_sync(0xffffffffu, s, o);
    if (lane == 0) out[gw] = s;
}

// -------- row softmax over M=256 -> fp16 --------
__global__ void softmax_row256(const float* __restrict__ in, __half* __restrict__ out) {
    long row = blockIdx.x;
    int tid = threadIdx.x;
    __shared__ float sh[8];
    float v = in[row * 256 + tid];
    float m = v;
    #pragma unroll
    for (int o = 16; o; o >>= 1) m = fmaxf(m, __shfl_xor_sync(0xffffffffu, m, o));
    if ((tid & 31) == 0) sh[tid >> 5] = m;
    __syncthreads();
    float bm = sh[0];
    #pragma unroll
    for (int i = 1; i < 8; i++) bm = fmaxf(bm, sh[i]);
    __syncthreads();
    float e = __expf(v - bm);
    float s = e;
    #pragma unroll
    for (int o = 16; o; o >>= 1) s += __shfl_xor_sync(0xffffffffu, s, o);
    if ((tid & 31) == 0) sh[tid >> 5] = s;
    __syncthreads();
    float bs = 0.f;
    #pragma unroll
    for (int i = 0; i < 8; i++) bs += sh[i];
    out[row * 256 + tid] = __float2half_rn(e / bs);
}

// -------- column softmax over T=1024 -> fp16 --------
__global__ void softmax_col(const float* __restrict__ in, __half* __restrict__ out) {
    int bh = blockIdx.y;
    int mx = threadIdx.x & 63;
    int ty = threadIdx.x >> 6;
    int m = blockIdx.x * 64 + mx;
    const float* base = in + (long)bh * Tc * Mc + m;
    __shared__ float red[256];
    __shared__ float cstat[64];
    float acc = -3.4e38f;
    for (int t = ty; t < Tc; t += 4) acc = fmaxf(acc, base[(long)t * Mc]);
    red[threadIdx.x] = acc;
    __syncthreads();
    if (ty == 0)
        cstat[mx] = fmaxf(fmaxf(red[mx], red[64 + mx]), fmaxf(red[128 + mx], red[192 + mx]));
    __syncthreads();
    float cm = cstat[mx];
    __syncthreads();
    float s = 0.f;
    for (int t = ty; t < Tc; t += 4) s += __expf(base[(long)t * Mc] - cm);
    red[threadIdx.x] = s;
    __syncthreads();
    if (ty == 0) cstat[mx] = red[mx] + red[64 + mx] + red[128 + mx] + red[192 + mx];
    __syncthreads();
    float inv = 1.f / cstat[mx];
    __half* ob = out + (long)bh * Tc * Mc + m;
    for (int t = ty; t < Tc; t += 4)
        ob[(long)t * Mc] = __float2half_rn(__expf(base[(long)t * Mc] - cm) * inv);
}

extern "C" void kernel_launch(void* const* d_in, const int* in_sizes, int n_in,
                              void* d_out, int out_size) {
    const float* x      = (const float*)d_in[0];
    const float* y      = (const float*)d_in[1];
    const float* Wqkv_x = (const float*)d_in[3];
    const float* bqkv_x = (const float*)d_in[4];
    const float* Wqkv_y = (const float*)d_in[5];
    const float* bqkv_y = (const float*)d_in[6];
    const float* w4x    = (const float*)d_in[7];
    const float* w4y    = (const float*)d_in[8];
    const float* w4xy   = (const float*)d_in[9];
    const float* Wgs    = (const float*)d_in[10];
    const float* bgs    = (const float*)d_in[11];
    const float* Wgc    = (const float*)d_in[12];
    const float* bgc    = (const float*)d_in[13];
    const float* Wp     = (const float*)d_in[14];
    const float* bp     = (const float*)d_in[15];
    float* out = (float*)d_out;

    cudaFuncSetAttribute(mma_nt_h, cudaFuncAttributeMaxDynamicSharedMemorySize, NT_SMEM);
    cudaFuncSetAttribute(mma_nn_h, cudaFuncAttributeMaxDynamicSharedMemorySize, H_SMEM);
    cudaFuncSetAttribute(mma_nn_wide_h, cudaFuncAttributeMaxDynamicSharedMemorySize, W_SMEM);
    cudaFuncSetAttribute(fused_attn, cudaFuncAttributeMaxDynamicSharedMemorySize, FA_SMEM_MAX);

    __half *p_xh, *p_yh, *p_wqxh, *p_wqyh, *p_wgsh, *p_wgch, *p_wph,
           *p_qkvxh, *p_qkvyh, *p_qsh, *p_pxy, *p_y2xh,
           *p_cvalh, *p_svalh, *p_zh;
    float *p_catt1, *p_catt2, *p_catt, *p_cval, *p_gs;
    cudaGetSymbolAddress((void**)&p_xh, g_xh);
    cudaGetSymbolAddress((void**)&p_yh, g_yh);
    cudaGetSymbolAddress((void**)&p_wqxh, g_wqxh);
    cudaGetSymbolAddress((void**)&p_wqyh, g_wqyh);
    cudaGetSymbolAddress((void**)&p_wgsh, g_wgsh);
    cudaGetSymbolAddress((void**)&p_wgch, g_wgch);
    cudaGetSymbolAddress((void**)&p_wph, g_wph);
    cudaGetSymbolAddress((void**)&p_qkvxh, g_qkvxh);
    cudaGetSymbolAddress((void**)&p_qkvyh, g_qkvyh);
    cudaGetSymbolAddress((void**)&p_qsh, g_qsh);
    cudaGetSymbolAddress((void**)&p_pxy, g_pxy);
    cudaGetSymbolAddress((void**)&p_y2xh, g_y2xh);
    cudaGetSymbolAddress((void**)&p_cvalh, g_cvalh);
    cudaGetSymbolAddress((void**)&p_svalh, g_svalh);
    cudaGetSymbolAddress((void**)&p_zh, g_zh);
    cudaGetSymbolAddress((void**)&p_catt1, g_catt1);
    cudaGetSymbolAddress((void**)&p_catt2, g_catt2);
    cudaGetSymbolAddress((void**)&p_catt, g_catt);
    cudaGetSymbolAddress((void**)&p_cval, g_cval);
    cudaGetSymbolAddress((void**)&p_gs, g_gs);

    const float scale = 0.125f;
    const float invSqrtM = 0.0625f;

    // 0. merged fp16 conversions
    {
        const int n0 = Bc * Tc * Cc / 4, n1 = Bc * Mc * Cc / 4;
        const int n2 = Cc * C3c / 4, n3 = Cc * C3c / 4;
        const int n4c = Cc * Cc / 4, n5 = Cc * Cc / 4, n6 = Cc * Cc / 4;
        const int ntot = n0 + n1 + n2 + n3 + n4c + n5 + n6;
        cvt_all<<<(ntot + 255) / 256, 256>>>(
            (const float4*)x, p_xh, n0,
            (const float4*)y, p_yh, n1,
            (const float4*)Wqkv_x, p_wqxh, n2,
            (const float4*)Wqkv_y, p_wqyh, n3,
            (const float4*)Wgs, p_wgsh, n4c,
            (const float4*)Wgc, p_wgch, n5,
            (const float4*)Wp, p_wph, n6);
    }

    // 1-2. QKV projections
    mma_nn_wide_h<<<dim3(C3c / 128, (Bc * Tc) / 128), 256, W_SMEM>>>(
        p_xh, Cc, p_wqxh, C3c, bqkv_x, nullptr, p_qkvxh, C3c, Cc,
        nullptr, nullptr, nullptr);
    mma_nn_wide_h<<<dim3(C3c / 128, (Bc * Mc) / 128), 256, W_SMEM>>>(
        p_yh, Cc, p_wqyh, C3c, bqkv_y, nullptr, p_qkvyh, C3c, Cc,
        nullptr, nullptr, nullptr);
    // 3. catt1+qs fused; catt2
    dotw_qs<<<(BHc * Tc) / 8, 256>>>(p_qkvxh, w4x, w4xy, p_catt1, p_qsh);
    dotw<<<(BHc * Mc) / 8, 256>>>(p_qkvyh, w4y, Mc, p_catt2);
    // 4. satt: fused flash -> svalh only
    fused_attn<<<dim3(Tc / 128, BHc), 256, 4 * 128 * 72 * 2>>>(
        p_qkvxh, (long)Tc * C3c, 64, C3c,
        p_qkvxh + Cc, (long)Tc * C3c, 64, C3c,
        p_qkvxh + 2 * Cc, (long)Tc * C3c, C3c,
        nullptr, p_svalh, (long)Tc * Cc, HDc, Cc,
        HDc, scale, 0, nullptr);
    // 5. gs = sval @ Wgs + bgs
    mma_nn_wide_h<<<dim3(Cc / 128, (Bc * Tc) / 128), 256, W_SMEM>>>(
        p_svalh, Cc, p_wgsh, Cc, bgs, p_gs, nullptr, Cc, Cc,
        nullptr, nullptr, nullptr);

    // 6. catt scores
    mma_nt_h<<<dim3(Mc / 128, Tc / 128, BHc), 256, NT_SMEM>>>(
        p_qsh, (long)Tc * Cc, 64, Cc,
        p_qkvyh + Cc, (long)Mc * C3c, 64, C3c,
        p_catt1, p_catt2,
        p_catt, Tc, Mc, HDc, scale, 0);
    // 7-8. softmaxes -> fp16
    softmax_row256<<<BHc * Tc, 256>>>(p_catt, p_pxy);
    softmax_col<<<dim3(Mc / 64, BHc), 256>>>(p_catt, p_y2xh);
    // 9. cval = x2y @ v_y
    mma_nn_h<<<dim3(1, Tc / 128, BHc), 256, H_SMEM>>>(
        p_pxy, (long)Tc * Mc, Mc,
        p_qkvyh + 2 * Cc, (long)Mc * C3c, C3c,
        p_cval, nullptr, (long)Tc * Cc, HDc, Cc, Mc);
    // 10. chain: fused flash -> cval += chain@v_x + x (+fp16)
    fused_attn<<<dim3(Tc / 128, BHc), 256, FA_SMEM_MAX>>>(
        p_pxy, 8L * Tc * Mc, (long)Tc * Mc, Mc,
        p_y2xh, 8L * Tc * Mc, (long)Tc * Mc, Mc,
        p_qkvxh + 2 * Cc, (long)Tc * C3c, C3c,
        p_cval, p_cvalh, (long)Tc * Cc, HDc, Cc,
        Mc, invSqrtM, 1, x);

    // 11. z = sig(gs)*cval + sig(cval@Wgc+bgc)*svalh
    mma_nn_wide_h<<<dim3(Cc / 128, (Bc * Tc) / 128), 256, W_SMEM>>>(
        p_cvalh, Cc, p_wgch, Cc, bgc, nullptr, p_zh, Cc, Cc,
        p_gs, p_cval, p_svalh);

    // 12. out = z @ Wp + bp
    mma_nn_wide_h<<<dim3(Cc / 128, (Bc * Tc) / 128), 256, W_SMEM>>>(
        p_zh, Cc, p_wph, Cc, bp, out, nullptr, Cc, Cc,
        nullptr, nullptr, nullptr);
}

// round 17
// speedup vs baseline: 1.8736x; 1.0647x over previous
#include <cuda_runtime.h>
#include <cuda_bf16.h>
#include <cuda_fp16.h>
#include <math.h>

#define Bc 4
#define Tc 1024
#define Mc 256
#define Cc 512
#define Hc 8
#define HDc 64
#define C3c 1536
#define BHc 32

// ---------------- scratch ----------------
__device__ __half g_xh[Bc * Tc * Cc];
__device__ __half g_yh[Bc * Mc * Cc];
__device__ __half g_wqxh[Cc * C3c];
__device__ __half g_wqyh[Cc * C3c];
__device__ __half g_wgsh[Cc * Cc];
__device__ __half g_wgch[Cc * Cc];
__device__ __half g_wph[Cc * Cc];
__device__ __half g_qkvxh[Bc * Tc * C3c];
__device__ __half g_qkvyh[Bc * Mc * C3c];
__device__ __half g_qsh[Bc * Tc * Cc];
__device__ float g_catt1[BHc * Tc];
__device__ float g_catt2[BHc * Mc];
__device__ float g_catt[(long)BHc * Tc * Mc];
__device__ __half g_pxy[(long)BHc * Tc * Mc];
__device__ __half g_y2xh[(long)BHc * Tc * Mc];
__device__ float g_cval[Bc * Tc * Cc];
__device__ __half g_cvalh[Bc * Tc * Cc];
__device__ __half g_svalh[Bc * Tc * Cc];
__device__ float g_gs[Bc * Tc * Cc];
__device__ __half g_zh[Bc * Tc * Cc];

// ---------------- helpers ----------------
__device__ __forceinline__ void mma16h(float* d, const unsigned* a, const unsigned* b) {
    asm volatile(
        "mma.sync.aligned.m16n8k16.row.col.f32.f16.f16.f32 "
        "{%0,%1,%2,%3},{%4,%5,%6,%7},{%8,%9},{%0,%1,%2,%3};"
        : "+f"(d[0]), "+f"(d[1]), "+f"(d[2]), "+f"(d[3])
        : "r"(a[0]), "r"(a[1]), "r"(a[2]), "r"(a[3]), "r"(b[0]), "r"(b[1]));
}
__device__ __forceinline__ void cpa16(unsigned dst, const void* src) {
    asm volatile("cp.async.cg.shared.global [%0], [%1], 16;" :: "r"(dst), "l"(src));
}
__device__ __forceinline__ void cpcommit() { asm volatile("cp.async.commit_group;"); }
__device__ __forceinline__ void ldsm4(unsigned& r0, unsigned& r1, unsigned& r2, unsigned& r3,
                                      unsigned addr) {
    asm volatile("ldmatrix.sync.aligned.m8n8.x4.shared.b16 {%0,%1,%2,%3},[%4];"
                 : "=r"(r0), "=r"(r1), "=r"(r2), "=r"(r3) : "r"(addr));
}
__device__ __forceinline__ void ldsm4t(unsigned& r0, unsigned& r1, unsigned& r2, unsigned& r3,
                                       unsigned addr) {
    asm volatile("ldmatrix.sync.aligned.m8n8.x4.trans.shared.b16 {%0,%1,%2,%3},[%4];"
                 : "=r"(r0), "=r"(r1), "=r"(r2), "=r"(r3) : "r"(addr));
}
__device__ __forceinline__ unsigned packh2(float lo, float hi) {
    __half2 h = __floats2half2_rn(lo, hi);
    return *(unsigned*)&h;
}

// pipelines (halfs)
#define H_ASTG (128 * 72)
#define H_BSTG (64 * 72)
#define H_SMEM ((3 * H_ASTG + 3 * H_BSTG) * 2)
#define W_ASTG (128 * 72)
#define W_BSTG (64 * 136)
#define W_SMEM ((3 * W_ASTG + 3 * W_BSTG) * 2)
#define FA_SMEM_MAX 221184
// catt_fused: Q 128x72 + K 256x72 halfs, + catt1(128 f32) + catt2(256 f32)
#define CF_SMEM ((128 * 72 + 256 * 72) * 2 + 128 * 4 + 256 * 4)

extern __shared__ unsigned smem_u[];

// ================= fused flash attention (causal, K double-buffered) =================
__global__ void __launch_bounds__(256, 1)
fused_attn(const __half* __restrict__ Aq, long Abs, long Ahs, int ldA,
           const __half* __restrict__ Bk, long Bbs, long Bhs, int ldB,
           const __half* __restrict__ Vp, long Vbs, int ldV,
           float* __restrict__ Cp, __half* __restrict__ CpH,
           long Cbs, long Chs, int ldC,
           int Kd, float scale, int accumulate, const float* __restrict__ addV) {
    const int bh = blockIdx.y, b = bh >> 3, h = bh & 7;
    const int i0 = (gridDim.x - 1 - blockIdx.x) * 128;
    const int tid = threadIdx.x, wid = tid >> 5, lane = tid & 31;
    const int g = lane >> 2, t = lane & 3;
    const int wr = wid * 16;
    const int lrow = lane & 15, lblk = lane >> 4;
    const int trow = lane & 7, tsel = lane >> 3;
    const int tko = (tsel & 1) * 8 + trow;
    const int tnb = (tsel >> 1) * 8;

    const int st = Kd + 8;
    const int kd8 = Kd >> 3;
    const int kshift = (Kd == 64) ? 3 : 5;
    const unsigned sQ = (unsigned)__cvta_generic_to_shared(smem_u);
    const unsigned sK0 = sQ + 128 * st * 2;
    const unsigned sK1 = sK0 + 128 * st * 2;
    const unsigned sV = sK1 + 128 * st * 2;

    const __half* Ab = Aq + (long)b * Abs + (long)h * Ahs + (long)i0 * ldA;
    const __half* Bb = Bk + (long)b * Bbs + (long)h * Bhs;
    const __half* Vb = Vp + (long)b * Vbs + h * HDc;

    const int nQ = Kd * 16;
    for (int idx = tid; idx < nQ; idx += 256) {
        int r = idx >> kshift, c8 = (idx & (kd8 - 1)) * 8;
        cpa16(sQ + (r * st + c8) * 2, Ab + (long)r * ldA + c8);
        cpa16(sK0 + (r * st + c8) * 2, Bb + (long)r * ldB + c8);
    }
    for (int idx = tid; idx < 1024; idx += 256) {
        int r = idx >> 3, c8 = (idx & 7) * 8;
        cpa16(sV + (r * 72 + c8) * 2, Vb + (long)r * ldV + c8);
    }
    cpcommit();

    const int nkc = Kd >> 4;
    const int nblk = i0 / 128 + 1;
    float oAcc[8][4] = {};
    float m0 = -1e30f, m1 = -1e30f, sum0 = 0.f, sum1 = 0.f;

    for (int jb = 0; jb < nblk; jb++) {
        const int j0 = jb * 128;
        asm volatile("cp.async.wait_group 0;");
        __syncthreads();
        const unsigned sKc = (jb & 1) ? sK1 : sK0;

        float s[16][4] = {};
        for (int kc = 0; kc < nkc; kc++) {
            unsigned a[4];
            ldsm4(a[0], a[1], a[2], a[3],
                  sQ + ((wr + lrow) * st + kc * 16 + 8 * lblk) * 2);
            #pragma unroll
            for (int q = 0; q < 8; q++) {
                unsigned r0, r1, r2, r3;
                ldsm4(r0, r1, r2, r3,
                      sKc + ((q * 16 + lrow) * st + kc * 16 + 8 * lblk) * 2);
                unsigned b0[2] = {r0, r2}, b1[2] = {r1, r3};
                mma16h(s[2 * q], a, b0);
                mma16h(s[2 * q + 1], a, b1);
            }
        }
        if (jb + 1 < nblk) {
            const unsigned sKn = (jb & 1) ? sK0 : sK1;
            const __half* Bn = Bb + (long)(j0 + 128) * ldB;
            for (int idx = tid; idx < nQ; idx += 256) {
                int r = idx >> kshift, c8 = (idx & (kd8 - 1)) * 8;
                cpa16(sKn + (r * st + c8) * 2, Bn + (long)r * ldB + c8);
            }
            cpcommit();
        }

        const bool diag = (j0 == i0);
        #pragma unroll
        for (int nf = 0; nf < 16; nf++)
            #pragma unroll
            for (int e = 0; e < 4; e++) {
                float v = s[nf][e] * scale;
                if (diag) {
                    int row = wr + g + (e >> 1) * 8;
                    int col = 8 * nf + 2 * t + (e & 1);
                    if (col > row) v = -1e30f;
                }
                s[nf][e] = v;
            }
        float mx0 = -1e30f, mx1 = -1e30f;
        #pragma unroll
        for (int nf = 0; nf < 16; nf++) {
            mx0 = fmaxf(mx0, fmaxf(s[nf][0], s[nf][1]));
            mx1 = fmaxf(mx1, fmaxf(s[nf][2], s[nf][3]));
        }
        #pragma unroll
        for (int o = 1; o <= 2; o <<= 1) {
            mx0 = fmaxf(mx0, __shfl_xor_sync(0xffffffffu, mx0, o));
            mx1 = fmaxf(mx1, __shfl_xor_sync(0xffffffffu, mx1, o));
        }
        float mn0 = fmaxf(m0, mx0), mn1 = fmaxf(m1, mx1);
        float f0 = __expf(m0 - mn0), f1 = __expf(m1 - mn1);
        sum0 *= f0; sum1 *= f1;
        #pragma unroll
        for (int nf = 0; nf < 8; nf++) {
            oAcc[nf][0] *= f0; oAcc[nf][1] *= f0;
            oAcc[nf][2] *= f1; oAcc[nf][3] *= f1;
        }
        float ps0 = 0.f, ps1 = 0.f;
        #pragma unroll
        for (int nf = 0; nf < 16; nf++) {
            float e0 = __expf(s[nf][0] - mn0), e1 = __expf(s[nf][1] - mn0);
            float e2 = __expf(s[nf][2] - mn1), e3 = __expf(s[nf][3] - mn1);
            s[nf][0] = e0; s[nf][1] = e1; s[nf][2] = e2; s[nf][3] = e3;
            ps0 += e0 + e1; ps1 += e2 + e3;
        }
        #pragma unroll
        for (int o = 1; o <= 2; o <<= 1) {
            ps0 += __shfl_xor_sync(0xffffffffu, ps0, o);
            ps1 += __shfl_xor_sync(0xffffffffu, ps1, o);
        }
        sum0 += ps0; sum1 += ps1;
        m0 = mn0; m1 = mn1;

        #pragma unroll
        for (int c = 0; c < 8; c++) {
            unsigned aP[4];
            aP[0] = packh2(s[2 * c][0], s[2 * c][1]);
            aP[1] = packh2(s[2 * c][2], s[2 * c][3]);
            aP[2] = packh2(s[2 * c + 1][0], s[2 * c + 1][1]);
            aP[3] = packh2(s[2 * c + 1][2], s[2 * c + 1][3]);
            #pragma unroll
            for (int q = 0; q < 4; q++) {
                unsigned r0, r1, r2, r3;
                ldsm4t(r0, r1, r2, r3,
                       sV + ((c * 16 + tko) * 72 + q * 16 + tnb) * 2);
                unsigned b0[2] = {r0, r1}, b1[2] = {r2, r3};
                mma16h(oAcc[2 * q], aP, b0);
                mma16h(oAcc[2 * q + 1], aP, b1);
            }
        }
        __syncthreads();
        if (jb + 1 < nblk) {
            const __half* Vn = Vb + (long)(j0 + 128) * ldV;
            for (int idx = tid; idx < 1024; idx += 256) {
                int r = idx >> 3, c8 = (idx & 7) * 8;
                cpa16(sV + (r * 72 + c8) * 2, Vn + (long)r * ldV + c8);
            }
            cpcommit();
        }
    }

    const float inv0 = 1.f / sum0, inv1 = 1.f / sum1;
    const long baseoff = (long)b * Cbs + (long)h * Chs + (long)i0 * ldC;
    float* Cb = Cp ? Cp + baseoff : nullptr;
    __half* Ch = CpH ? CpH + baseoff : nullptr;
    const float* Xb = addV ? addV + baseoff : nullptr;
    #pragma unroll
    for (int nf = 0; nf < 8; nf++)
        #pragma unroll
        for (int e = 0; e < 4; e++) {
            int row = wr + g + (e >> 1) * 8;
            int cc = 8 * nf + 2 * t + (e & 1);
            float v = oAcc[nf][e] * ((e >> 1) ? inv1 : inv0);
            long off = (long)row * ldC + cc;
            if (accumulate && Cb) v += Cb[off];
            if (Xb) v += Xb[off];
            if (Cb) Cb[off] = v;
            if (Ch) Ch[off] = __float2half_rn(v);
        }
}

// ================= fused catt scores + row softmax =================
// S[128 x 256] = scale * qs @ k_y^T + catt1[row] + catt2[col]
// writes f32 scores (for softmax_col) and fp16 row-softmax probs.
// grid (Tc/128, BHc), 256 thr, 8 warps x 16 rows.
__global__ void __launch_bounds__(256, 1)
catt_fused(const __half* __restrict__ Qs, const __half* __restrict__ Ky,
           const float* __restrict__ catt1, const float* __restrict__ catt2,
           float* __restrict__ scoreOut, __half* __restrict__ probOut,
           float scale) {
    const int bh = blockIdx.y, b = bh >> 3, h = bh & 7;
    const int i0 = blockIdx.x * 128;
    const int tid = threadIdx.x, wid = tid >> 5, lane = tid & 31;
    const int g = lane >> 2, t = lane & 3;
    const int wr = wid * 16;
    const int lrow = lane & 15, lblk = lane >> 4;

    const unsigned sQ = (unsigned)__cvta_generic_to_shared(smem_u);
    const unsigned sK = sQ + 128 * 72 * 2;
    float* c1s = (float*)(smem_u + (128 * 72 + 256 * 72) / 2);
    float* c2s = c1s + 128;

    const __half* Qb = Qs + (long)(b * Tc + i0) * Cc + h * HDc;
    const __half* Kb = Ky + (long)(b * Mc) * C3c + Cc + h * HDc;

    for (int idx = tid; idx < 1024; idx += 256) {      // Q: 128 rows x 8 seg
        int r = idx >> 3, c8 = (idx & 7) * 8;
        cpa16(sQ + (r * 72 + c8) * 2, Qb + (long)r * Cc + c8);
    }
    for (int idx = tid; idx < 2048; idx += 256) {      // K: 256 rows x 8 seg
        int r = idx >> 3, c8 = (idx & 7) * 8;
        cpa16(sK + (r * 72 + c8) * 2, Kb + (long)r * C3c + c8);
    }
    if (tid < 128) c1s[tid] = catt1[(long)bh * Tc + i0 + tid];
    c2s[tid] = catt2[(long)bh * Mc + tid];
    cpcommit();
    asm volatile("cp.async.wait_group 0;");
    __syncthreads();

    float s[32][4] = {};
    #pragma unroll
    for (int kc = 0; kc < 4; kc++) {
        unsigned a[4];
        ldsm4(a[0], a[1], a[2], a[3],
              sQ + ((wr + lrow) * 72 + kc * 16 + 8 * lblk) * 2);
        #pragma unroll
        for (int q = 0; q < 16; q++) {
            unsigned r0, r1, r2, r3;
            ldsm4(r0, r1, r2, r3,
                  sK + ((q * 16 + lrow) * 72 + kc * 16 + 8 * lblk) * 2);
            unsigned b0[2] = {r0, r2}, b1[2] = {r1, r3};
            mma16h(s[2 * q], a, b0);
            mma16h(s[2 * q + 1], a, b1);
        }
    }

    const float c1lo = c1s[wr + g], c1hi = c1s[wr + g + 8];
    float mx0 = -1e30f, mx1 = -1e30f;
    #pragma unroll
    for (int nf = 0; nf < 32; nf++) {
        int col = 8 * nf + 2 * t;
        float b0 = c2s[col], b1 = c2s[col + 1];
        s[nf][0] = s[nf][0] * scale + c1lo + b0;
        s[nf][1] = s[nf][1] * scale + c1lo + b1;
        s[nf][2] = s[nf][2] * scale + c1hi + b0;
        s[nf][3] = s[nf][3] * scale + c1hi + b1;
        mx0 = fmaxf(mx0, fmaxf(s[nf][0], s[nf][1]));
        mx1 = fmaxf(mx1, fmaxf(s[nf][2], s[nf][3]));
    }
    #pragma unroll
    for (int o = 1; o <= 2; o <<= 1) {
        mx0 = fmaxf(mx0, __shfl_xor_sync(0xffffffffu, mx0, o));
        mx1 = fmaxf(mx1, __shfl_xor_sync(0xffffffffu, mx1, o));
    }

    // write f32 scores + compute exp sums
    const long rb0 = (long)bh * Tc * Mc + (long)(i0 + wr + g) * Mc;
    const long rb1 = rb0 + 8L * Mc;
    float sum0 = 0.f, sum1 = 0.f;
    #pragma unroll
    for (int nf = 0; nf < 32; nf++) {
        int col = 8 * nf + 2 * t;
        *(float2*)&scoreOut[rb0 + col] = make_float2(s[nf][0], s[nf][1]);
        *(float2*)&scoreOut[rb1 + col] = make_float2(s[nf][2], s[nf][3]);
        float e0 = __expf(s[nf][0] - mx0), e1 = __expf(s[nf][1] - mx0);
        float e2 = __expf(s[nf][2] - mx1), e3 = __expf(s[nf][3] - mx1);
        s[nf][0] = e0; s[nf][1] = e1; s[nf][2] = e2; s[nf][3] = e3;
        sum0 += e0 + e1; sum1 += e2 + e3;
    }
    #pragma unroll
    for (int o = 1; o <= 2; o <<= 1) {
        sum0 += __shfl_xor_sync(0xffffffffu, sum0, o);
        sum1 += __shfl_xor_sync(0xffffffffu, sum1, o);
    }
    const float inv0 = 1.f / sum0, inv1 = 1.f / sum1;
    #pragma unroll
    for (int nf = 0; nf < 32; nf++) {
        int col = 8 * nf + 2 * t;
        __half2 p0 = __floats2half2_rn(s[nf][0] * inv0, s[nf][1] * inv0);
        __half2 p1 = __floats2half2_rn(s[nf][2] * inv1, s[nf][3] * inv1);
        *(__half2*)&probOut[rb0 + col] = p0;
        *(__half2*)&probOut[rb1 + col] = p1;
    }
}

// ================= fp16 NN GEMM (cval = x2y @ v_y) =================
__global__ void __launch_bounds__(256, 2)
mma_nn_h(const __half* __restrict__ A, long Ahs, int ldA,
         const __half* __restrict__ Bp, long Bbs, int ldB,
         float* __restrict__ Cp, __half* __restrict__ CpH,
         long Cbs, long Chs, int ldC, int K) {
    const int bh = blockIdx.z, b = bh >> 3, h = bh & 7;
    const int i0 = blockIdx.y * 128;
    const unsigned sA0 = (unsigned)__cvta_generic_to_shared(smem_u);
    const unsigned sB0 = sA0 + 3 * H_ASTG * 2;
    const __half* Ab = A + (long)bh * Ahs + (long)i0 * ldA;
    const __half* Bb = Bp + (long)b * Bbs + h * HDc;

    const int tid = threadIdx.x, wid = tid >> 5, lane = tid & 31;
    const int g = lane >> 2, t = lane & 3;
    const int wm = (wid & 1) * 64, wn = (wid >> 1) * 16;
    const int lrow = lane & 15, lblk = lane >> 4;
    const int ldrow = tid >> 3, hc8 = (tid & 7) * 8;
    const int trow = lane & 7, tsel = lane >> 3;
    const int tko = (tsel & 1) * 8 + trow;
    const int tno = wn + (tsel >> 1) * 8;

    const int niter = K / 64;
    float acc[4][2][4] = {};

    #pragma unroll
    for (int s = 0; s < 2; s++) {
        if (s < niter) {
            const int k0 = s * 64;
            #pragma unroll
            for (int w = 0; w < 4; w++) {
                int r = ldrow + w * 32;
                cpa16(sA0 + (s * H_ASTG + r * 72 + hc8) * 2, Ab + (long)r * ldA + k0 + hc8);
            }
            #pragma unroll
            for (int w = 0; w < 2; w++) {
                int li = tid + w * 256;
                int r = li >> 3, c8 = (li & 7) * 8;
                cpa16(sB0 + (s * H_BSTG + r * 72 + c8) * 2, Bb + (long)(k0 + r) * ldB + c8);
            }
            cpcommit();
        }
    }

    int slot = 0, pslot = 2;
    for (int it = 0; it < niter; it++) {
        if (it < niter - 1) asm volatile("cp.async.wait_group 1;");
        else                asm volatile("cp.async.wait_group 0;");
        __syncthreads();

        const unsigned aBase = sA0 + slot * H_ASTG * 2;
        const unsigned bBase = sB0 + slot * H_BSTG * 2;
        #pragma unroll
        for (int kk = 0; kk < 4; kk++) {
            const int kb = kk * 16;
            unsigned a[4][4], bb[2][2];
            #pragma unroll
            for (int mf = 0; mf < 4; mf++)
                ldsm4(a[mf][0], a[mf][1], a[mf][2], a[mf][3],
                      aBase + ((wm + mf * 16 + lrow) * 72 + kb + 8 * lblk) * 2);
            {
                unsigned r0, r1, r2, r3;
                ldsm4t(r0, r1, r2, r3, bBase + ((kb + tko) * 72 + tno) * 2);
                bb[0][0] = r0; bb[0][1] = r1;
                bb[1][0] = r2; bb[1][1] = r3;
            }
            #pragma unroll
            for (int mf = 0; mf < 4; mf++)
                #pragma unroll
                for (int nf = 0; nf < 2; nf++) mma16h(acc[mf][nf], a[mf], bb[nf]);
        }

        if (it + 2 < niter) {
            const int k0 = (it + 2) * 64;
            #pragma unroll
            for (int w = 0; w < 4; w++) {
                int r = ldrow + w * 32;
                cpa16(sA0 + (pslot * H_ASTG + r * 72 + hc8) * 2,
                      Ab + (long)r * ldA + k0 + hc8);
            }
            #pragma unroll
            for (int w = 0; w < 2; w++) {
                int li = tid + w * 256;
                int r = li >> 3, c8 = (li & 7) * 8;
                cpa16(sB0 + (pslot * H_BSTG + r * 72 + c8) * 2,
                      Bb + (long)(k0 + r) * ldB + c8);
            }
            cpcommit();
        }
        slot = (slot == 2) ? 0 : slot + 1;
        pslot = (pslot == 2) ? 0 : pslot + 1;
    }

    const long baseoff = (long)b * Cbs + (long)h * Chs + (long)i0 * ldC;
    float* Cb = Cp + baseoff;
    __half* Ch = CpH ? CpH + baseoff : nullptr;
    #pragma unroll
    for (int mf = 0; mf < 4; mf++)
        #pragma unroll
        for (int nf = 0; nf < 2; nf++) {
            int r0 = wm + mf * 16 + g;
            int c0 = wn + nf * 8 + 2 * t;
            #pragma unroll
            for (int e = 0; e < 4; e++) {
                int rr = r0 + (e >> 1) * 8;
                int cc = c0 + (e & 1);
                float v = acc[mf][nf][e];
                long off = (long)rr * ldC + cc;
                Cb[off] = v;
                if (Ch) Ch[off] = __float2half_rn(v);
            }
        }
}

// ================= fp16 wide NN GEMM (dense) =================
__global__ void __launch_bounds__(256, 2)
mma_nn_wide_h(const __half* __restrict__ A, int ldA,
              const __half* __restrict__ Bp, int ldB,
              const float* __restrict__ bias,
              float* __restrict__ outF, __half* __restrict__ outH, int ldC,
              int K,
              const float* __restrict__ gGs, const float* __restrict__ gA2,
              const __half* __restrict__ gB2h) {
    const int col0 = blockIdx.x * 128, i0 = blockIdx.y * 128;
    const unsigned sA0 = (unsigned)__cvta_generic_to_shared(smem_u);
    const unsigned sB0 = sA0 + 3 * W_ASTG * 2;
    const __half* Ab = A + (long)i0 * ldA;
    const __half* Bb = Bp + col0;

    const int tid = threadIdx.x, wid = tid >> 5, lane = tid & 31;
    const int g = lane >> 2, t = lane & 3;
    const int wm = (wid & 1) * 64, wn = (wid >> 1) * 32;
    const int lrow = lane & 15, lblk = lane >> 4;
    const int ldrow = tid >> 3, hc8 = (tid & 7) * 8;
    const int trow = lane & 7, tsel = lane >> 3;
    const int tko = (tsel & 1) * 8 + trow;
    const int tnb = (tsel >> 1) * 8;

    const int niter = K / 64;
    float acc[4][4][4] = {};

    #pragma unroll
    for (int s = 0; s < 2; s++) {
        if (s < niter) {
            const int k0 = s * 64;
            #pragma unroll
            for (int w = 0; w < 4; w++) {
                int r = ldrow + w * 32;
                cpa16(sA0 + (s * W_ASTG + r * 72 + hc8) * 2, Ab + (long)r * ldA + k0 + hc8);
            }
            #pragma unroll
            for (int w = 0; w < 4; w++) {
                int li = tid + w * 256;
                int r = li >> 4, c8 = (li & 15) * 8;
                cpa16(sB0 + (s * W_BSTG + r * 136 + c8) * 2, Bb + (long)(k0 + r) * ldB + c8);
            }
            cpcommit();
        }
    }

    int slot = 0, pslot = 2;
    for (int it = 0; it < niter; it++) {
        if (it < niter - 1) asm volatile("cp.async.wait_group 1;");
        else                asm volatile("cp.async.wait_group 0;");
        __syncthreads();

        const unsigned aBase = sA0 + slot * W_ASTG * 2;
        const unsigned bBase = sB0 + slot * W_BSTG * 2;
        #pragma unroll
        for (int kk = 0; kk < 4; kk++) {
            const int kb = kk * 16;
            unsigned a[4][4], bb[4][2];
            #pragma unroll
            for (int mf = 0; mf < 4; mf++)
                ldsm4(a[mf][0], a[mf][1], a[mf][2], a[mf][3],
                      aBase + ((wm + mf * 16 + lrow) * 72 + kb + 8 * lblk) * 2);
            #pragma unroll
            for (int p = 0; p < 2; p++) {
                unsigned r0, r1, r2, r3;
                ldsm4t(r0, r1, r2, r3,
                       bBase + ((kb + tko) * 136 + wn + p * 16 + tnb) * 2);
                bb[2 * p][0] = r0; bb[2 * p][1] = r1;
                bb[2 * p + 1][0] = r2; bb[2 * p + 1][1] = r3;
            }
            #pragma unroll
            for (int mf = 0; mf < 4; mf++)
                #pragma unroll
                for (int nf = 0; nf < 4; nf++) mma16h(acc[mf][nf], a[mf], bb[nf]);
        }

        if (it + 2 < niter) {
            const int k0 = (it + 2) * 64;
            #pragma unroll
            for (int w = 0; w < 4; w++) {
                int r = ldrow + w * 32;
                cpa16(sA0 + (pslot * W_ASTG + r * 72 + hc8) * 2,
                      Ab + (long)r * ldA + k0 + hc8);
            }
            #pragma unroll
            for (int w = 0; w < 4; w++) {
                int li = tid + w * 256;
                int r = li >> 4, c8 = (li & 15) * 8;
                cpa16(sB0 + (pslot * W_BSTG + r * 136 + c8) * 2,
                      Bb + (long)(k0 + r) * ldB + c8);
            }
            cpcommit();
        }
        slot = (slot == 2) ? 0 : slot + 1;
        pslot = (pslot == 2) ? 0 : pslot + 1;
    }

    #pragma unroll
    for (int mf = 0; mf < 4; mf++)
        #pragma unroll
        for (int nf = 0; nf < 4; nf++) {
            int rr0 = i0 + wm + mf * 16 + g;
            int cc0 = col0 + wn + nf * 8 + 2 * t;
            #pragma unroll
            for (int e = 0; e < 4; e++) {
                int rr = rr0 + (e >> 1) * 8;
                int cc = cc0 + (e & 1);
                float v = acc[mf][nf][e];
                if (bias) v += bias[cc];
                long off = (long)rr * ldC + cc;
                if (gGs) {
                    float sg = 1.f / (1.f + __expf(-gGs[off]));
                    float cg = 1.f / (1.f + __expf(-v));
                    v = sg * gA2[off] + cg * __half2float(gB2h[off]);
                }
                if (outF) outF[off] = v;
                if (outH) outH[off] = __float2half_rn(v);
            }
        }
}

// -------- merged f32 -> fp16 convert (7 segments) --------
__global__ void cvt_all(const float4* s0, __half* d0, int n0,
                        const float4* s1, __half* d1, int n1,
                        const float4* s2, __half* d2, int n2,
                        const float4* s3, __half* d3, int n3,
                        const float4* s4, __half* d4, int n4c,
                        const float4* s5, __half* d5, int n5,
                        const float4* s6, __half* d6, int n6) {
    int i = blockIdx.x * blockDim.x + threadIdx.x;
    const float4* src; __half* dst; int li = i;
    if (li < n0) { src = s0; dst = d0; }
    else { li -= n0;
    if (li < n1) { src = s1; dst = d1; }
    else { li -= n1;
    if (li < n2) { src = s2; dst = d2; }
    else { li -= n2;
    if (li < n3) { src = s3; dst = d3; }
    else { li -= n3;
    if (li < n4c) { src = s4; dst = d4; }
    else { li -= n4c;
    if (li < n5) { src = s5; dst = d5; }
    else { li -= n5;
    if (li < n6) { src = s6; dst = d6; }
    else return; }}}}}}
    float4 v = src[li];
    __half2 h0 = __floats2half2_rn(v.x, v.y);
    __half2 h1 = __floats2half2_rn(v.z, v.w);
    uint2 u;
    u.x = *(unsigned*)&h0;
    u.y = *(unsigned*)&h1;
    *(uint2*)&dst[li * 4] = u;
}

// -------- fused: catt1 + qs --------
__global__ void dotw_qs(const __half* __restrict__ qkv, const float* __restrict__ w4x,
                        const float* __restrict__ w4xy,
                        float* __restrict__ out, __half* __restrict__ qs) {
    int gw = (blockIdx.x * blockDim.x + threadIdx.x) >> 5;
    int lane = threadIdx.x & 31;
    if (gw >= BHc * Tc) return;
    int bh = gw / Tc, r = gw % Tc;
    int b = bh >> 3, h = bh & 7;
    const __half* p = qkv + (long)(b * Tc + r) * C3c + h * HDc;
    float q0 = __half2float(p[lane]);
    float q1 = __half2float(p[lane + 32]);
    float s = q0 * w4x[h * HDc + lane] + q1 * w4x[h * HDc + lane + 32];
    #pragma unroll
    for (int o = 16; o; o >>= 1) s += __shfl_xor_sync(0xffffffffu, s, o);
    if (lane == 0) out[gw] = s;
    __half* qrow = qs + (long)(b * Tc + r) * Cc + h * HDc;
    qrow[lane] = __float2half_rn(q0 * w4xy[h * HDc + lane]);
    qrow[lane + 32] = __float2half_rn(q1 * w4xy[h * HDc + lane + 32]);
}

// -------- catt2 dot products --------
__global__ void dotw(const __half* __restrict__ qkv, const float* __restrict__ w,
                     int rows, float* __restrict__ out) {
    int gw = (blockIdx.x * blockDim.x + threadIdx.x) >> 5;
    int lane = threadIdx.x & 31;
    if (gw >= BHc * rows) return;
    int bh = gw / rows, r = gw % rows;
    int b = bh >> 3, h = bh & 7;
    const __half* p = qkv + (long)(b * rows + r) * C3c + h * HDc;
    float s = __half2float(p[lane]) * w[h * HDc + lane]
            + __half2float(p[lane + 32]) * w[h * HDc + lane + 32];
    #pragma unroll
    for (int o = 16; o; o >>= 1) s += __shfl_xor_sync(0xffffffffu, s, o);
    if (lane == 0) out[gw] = s;
}

// -------- column softmax over T=1024 -> fp16 --------
__global__ void softmax_col(const float* __restrict__ in, __half* __restrict__ out) {
    int bh = blockIdx.y;
    int mx = threadIdx.x & 63;
    int ty = threadIdx.x >> 6;
    int m = blockIdx.x * 64 + mx;
    const float* base = in + (long)bh * Tc * Mc + m;
    __shared__ float red[256];
    __shared__ float cstat[64];
    float acc = -3.4e38f;
    for (int t = ty; t < Tc; t += 4) acc = fmaxf(acc, base[(long)t * Mc]);
    red[threadIdx.x] = acc;
    __syncthreads();
    if (ty == 0)
        cstat[mx] = fmaxf(fmaxf(red[mx], red[64 + mx]), fmaxf(red[128 + mx], red[192 + mx]));
    __syncthreads();
    float cm = cstat[mx];
    __syncthreads();
    float s = 0.f;
    for (int t = ty; t < Tc; t += 4) s += __expf(base[(long)t * Mc] - cm);
    red[threadIdx.x] = s;
    __syncthreads();
    if (ty == 0) cstat[mx] = red[mx] + red[64 + mx] + red[128 + mx] + red[192 + mx];
    __syncthreads();
    float inv = 1.f / cstat[mx];
    __half* ob = out + (long)bh * Tc * Mc + m;
    for (int t = ty; t < Tc; t += 4)
        ob[(long)t * Mc] = __float2half_rn(__expf(base[(long)t * Mc] - cm) * inv);
}

extern "C" void kernel_launch(void* const* d_in, const int* in_sizes, int n_in,
                              void* d_out, int out_size) {
    const float* x      = (const float*)d_in[0];
    const float* y      = (const float*)d_in[1];
    const float* Wqkv_x = (const float*)d_in[3];
    const float* bqkv_x = (const float*)d_in[4];
    const float* Wqkv_y = (const float*)d_in[5];
    const float* bqkv_y = (const float*)d_in[6];
    const float* w4x    = (const float*)d_in[7];
    const float* w4y    = (const float*)d_in[8];
    const float* w4xy   = (const float*)d_in[9];
    const float* Wgs    = (const float*)d_in[10];
    const float* bgs    = (const float*)d_in[11];
    const float* Wgc    = (const float*)d_in[12];
    const float* bgc    = (const float*)d_in[13];
    const float* Wp     = (const float*)d_in[14];
    const float* bp     = (const float*)d_in[15];
    float* out = (float*)d_out;

    cudaFuncSetAttribute(mma_nn_h, cudaFuncAttributeMaxDynamicSharedMemorySize, H_SMEM);
    cudaFuncSetAttribute(mma_nn_wide_h, cudaFuncAttributeMaxDynamicSharedMemorySize, W_SMEM);
    cudaFuncSetAttribute(fused_attn, cudaFuncAttributeMaxDynamicSharedMemorySize, FA_SMEM_MAX);
    cudaFuncSetAttribute(catt_fused, cudaFuncAttributeMaxDynamicSharedMemorySize, CF_SMEM);

    __half *p_xh, *p_yh, *p_wqxh, *p_wqyh, *p_wgsh, *p_wgch, *p_wph,
           *p_qkvxh, *p_qkvyh, *p_qsh, *p_pxy, *p_y2xh,
           *p_cvalh, *p_svalh, *p_zh;
    float *p_catt1, *p_catt2, *p_catt, *p_cval, *p_gs;
    cudaGetSymbolAddress((void**)&p_xh, g_xh);
    cudaGetSymbolAddress((void**)&p_yh, g_yh);
    cudaGetSymbolAddress((void**)&p_wqxh, g_wqxh);
    cudaGetSymbolAddress((void**)&p_wqyh, g_wqyh);
    cudaGetSymbolAddress((void**)&p_wgsh, g_wgsh);
    cudaGetSymbolAddress((void**)&p_wgch, g_wgch);
    cudaGetSymbolAddress((void**)&p_wph, g_wph);
    cudaGetSymbolAddress((void**)&p_qkvxh, g_qkvxh);
    cudaGetSymbolAddress((void**)&p_qkvyh, g_qkvyh);
    cudaGetSymbolAddress((void**)&p_qsh, g_qsh);
    cudaGetSymbolAddress((void**)&p_pxy, g_pxy);
    cudaGetSymbolAddress((void**)&p_y2xh, g_y2xh);
    cudaGetSymbolAddress((void**)&p_cvalh, g_cvalh);
    cudaGetSymbolAddress((void**)&p_svalh, g_svalh);
    cudaGetSymbolAddress((void**)&p_zh, g_zh);
    cudaGetSymbolAddress((void**)&p_catt1, g_catt1);
    cudaGetSymbolAddress((void**)&p_catt2, g_catt2);
    cudaGetSymbolAddress((void**)&p_catt, g_catt);
    cudaGetSymbolAddress((void**)&p_cval, g_cval);
    cudaGetSymbolAddress((void**)&p_gs, g_gs);

    const float scale = 0.125f;
    const float invSqrtM = 0.0625f;

    // 0. merged fp16 conversions
    {
        const int n0 = Bc * Tc * Cc / 4, n1 = Bc * Mc * Cc / 4;
        const int n2 = Cc * C3c / 4, n3 = Cc * C3c / 4;
        const int n4c = Cc * Cc / 4, n5 = Cc * Cc / 4, n6 = Cc * Cc / 4;
        const int ntot = n0 + n1 + n2 + n3 + n4c + n5 + n6;
        cvt_all<<<(ntot + 255) / 256, 256>>>(
            (const float4*)x, p_xh, n0,
            (const float4*)y, p_yh, n1,
            (const float4*)Wqkv_x, p_wqxh, n2,
            (const float4*)Wqkv_y, p_wqyh, n3,
            (const float4*)Wgs, p_wgsh, n4c,
            (const float4*)Wgc, p_wgch, n5,
            (const float4*)Wp, p_wph, n6);
    }

    // 1-2. QKV projections
    mma_nn_wide_h<<<dim3(C3c / 128, (Bc * Tc) / 128), 256, W_SMEM>>>(
        p_xh, Cc, p_wqxh, C3c, bqkv_x, nullptr, p_qkvxh, C3c, Cc,
        nullptr, nullptr, nullptr);
    mma_nn_wide_h<<<dim3(C3c / 128, (Bc * Mc) / 128), 256, W_SMEM>>>(
        p_yh, Cc, p_wqyh, C3c, bqkv_y, nullptr, p_qkvyh, C3c, Cc,
        nullptr, nullptr, nullptr);
    // 3. catt1+qs fused; catt2
    dotw_qs<<<(BHc * Tc) / 8, 256>>>(p_qkvxh, w4x, w4xy, p_catt1, p_qsh);
    dotw<<<(BHc * Mc) / 8, 256>>>(p_qkvyh, w4y, Mc, p_catt2);
    // 4. satt: fused flash -> svalh
    fused_attn<<<dim3(Tc / 128, BHc), 256, 4 * 128 * 72 * 2>>>(
        p_qkvxh, (long)Tc * C3c, 64, C3c,
        p_qkvxh + Cc, (long)Tc * C3c, 64, C3c,
        p_qkvxh + 2 * Cc, (long)Tc * C3c, C3c,
        nullptr, p_svalh, (long)Tc * Cc, HDc, Cc,
        HDc, scale, 0, nullptr);
    // 5. gs = sval @ Wgs + bgs
    mma_nn_wide_h<<<dim3(Cc / 128, (Bc * Tc) / 128), 256, W_SMEM>>>(
        p_svalh, Cc, p_wgsh, Cc, bgs, p_gs, nullptr, Cc, Cc,
        nullptr, nullptr, nullptr);

    // 6. catt scores + row softmax (fused)
    catt_fused<<<dim3(Tc / 128, BHc), 256, CF_SMEM>>>(
        p_qsh, p_qkvyh, p_catt1, p_catt2, p_catt, p_pxy, scale);
    // 7. column softmax -> y2x fp16
    softmax_col<<<dim3(Mc / 64, BHc), 256>>>(p_catt, p_y2xh);
    // 8. cval = x2y @ v_y
    mma_nn_h<<<dim3(1, Tc / 128, BHc), 256, H_SMEM>>>(
        p_pxy, (long)Tc * Mc, Mc,
        p_qkvyh + 2 * Cc, (long)Mc * C3c, C3c,
        p_cval, nullptr, (long)Tc * Cc, HDc, Cc, Mc);
    // 9. chain: fused flash -> cval += chain@v_x + x (+fp16)
    fused_attn<<<dim3(Tc / 128, BHc), 256, FA_SMEM_MAX>>>(
        p_pxy, 8L * Tc * Mc, (long)Tc * Mc, Mc,
        p_y2xh, 8L * Tc * Mc, (long)Tc * Mc, Mc,
        p_qkvxh + 2 * Cc, (long)Tc * C3c, C3c,
        p_cval, p_cvalh, (long)Tc * Cc, HDc, Cc,
        Mc, invSqrtM, 1, x);

    // 10. z = sig(gs)*cval + sig(cval@Wgc+bgc)*svalh
    mma_nn_wide_h<<<dim3(Cc / 128, (Bc * Tc) / 128), 256, W_SMEM>>>(
        p_cvalh, Cc, p_wgch, Cc, bgc, nullptr, p_zh, Cc, Cc,
        p_gs, p_cval, p_svalh);

    // 11. out = z @ Wp + bp
    mma_nn_wide_h<<<dim3(Cc / 128, (Bc * Tc) / 128), 256, W_SMEM>>>(
        p_zh, Cc, p_wph, Cc, bp, out, nullptr, Cc, Cc,
        nullptr, nullptr, nullptr);
}